// round 2
// baseline (speedup 1.0000x reference)
#include <cuda_runtime.h>

// ---------------------------------------------------------------------------
// Problem constants (fixed by setup_inputs):
//   B=2, T=2048, C=4096, H=32, Dh=128, n_kv=8, G=4
// Inputs (metadata order): x, wq, wk, wv, wo, cos, sin, is_causal
// Output: [B*T, C] float32
// ---------------------------------------------------------------------------
#define BATCH   2
#define SEQ     2048
#define CMODEL  4096
#define NHEAD   32
#define DHEAD   128
#define NKV     8
#define GQA     4
#define MROWS   (BATCH * SEQ)                 // 4096
#define NQKV    (CMODEL + 2 * NKV * DHEAD)    // 6144

// Scratch (static device arrays: allocation-free per harness rules)
__device__ float g_q [BATCH * NHEAD * SEQ * DHEAD];  // [B,H,T,Dh]   64 MB
__device__ float g_k [BATCH * NKV   * SEQ * DHEAD];  // [B,kv,T,Dh]  16 MB
__device__ float g_v [BATCH * NKV   * SEQ * DHEAD];  // [B,kv,T,Dh]  16 MB
__device__ float g_ao[MROWS * CMODEL];               // [B*T, C]     64 MB

// ===========================================================================
// Kernel 1: fused QKV projection GEMM + RoPE epilogue
//   C_virtual[M=4096, N=6144] = x[4096,4096] @ [wq | wk | wv]
//   128x128 tile, BK=16, 256 threads, 8x8 per thread.
// ===========================================================================
#define BM 128
#define BN 128
#define BKG 16
#define APAD 4

__global__ __launch_bounds__(256, 2)
void qkv_rope_kernel(const float* __restrict__ x,
                     const float* __restrict__ wq,
                     const float* __restrict__ wk,
                     const float* __restrict__ wv,
                     const float* __restrict__ cosp,
                     const float* __restrict__ sinp)
{
    __shared__ float As[BKG][BM + APAD];
    __shared__ float Bs[BKG][BN];

    const int tid = threadIdx.x;
    const int tr  = tid >> 4;    // 0..15  (row group)
    const int tc  = tid & 15;    // 0..15  (col group)
    const int m0  = blockIdx.y * BM;
    const int nv0 = blockIdx.x * BN;

    const float* w; int ldw, ncol0, region;
    if (nv0 < CMODEL)              { w = wq; ldw = CMODEL;      ncol0 = nv0;                 region = 0; }
    else if (nv0 < CMODEL + 1024)  { w = wk; ldw = NKV * DHEAD; ncol0 = nv0 - CMODEL;        region = 1; }
    else                           { w = wv; ldw = NKV * DHEAD; ncol0 = nv0 - CMODEL - 1024; region = 2; }

    // A-tile loader: 128x16, two float4 per thread (rows r and r+64)
    const int arow = tid >> 2;          // 0..63
    const int ak   = (tid & 3) << 2;    // 0,4,8,12
    // B-tile loader: 16x128, two float4 per thread (rows k and k+8)
    const int bk0 = tid >> 5;           // 0..7
    const int bc0 = (tid & 31) << 2;    // 0..124

    float acc[8][8];
    #pragma unroll
    for (int i = 0; i < 8; i++)
        #pragma unroll
        for (int j = 0; j < 8; j++) acc[i][j] = 0.f;

    for (int k0 = 0; k0 < CMODEL; k0 += BKG) {
        const float4 a0 = *(const float4*)(x + (size_t)(m0 + arow)      * CMODEL + k0 + ak);
        const float4 a1 = *(const float4*)(x + (size_t)(m0 + arow + 64) * CMODEL + k0 + ak);
        const float4 b0 = *(const float4*)(w + (size_t)(k0 + bk0)     * ldw + ncol0 + bc0);
        const float4 b1 = *(const float4*)(w + (size_t)(k0 + bk0 + 8) * ldw + ncol0 + bc0);

        __syncthreads();   // previous tile's compute done before smem overwrite
        As[ak + 0][arow] = a0.x; As[ak + 1][arow] = a0.y;
        As[ak + 2][arow] = a0.z; As[ak + 3][arow] = a0.w;
        As[ak + 0][arow + 64] = a1.x; As[ak + 1][arow + 64] = a1.y;
        As[ak + 2][arow + 64] = a1.z; As[ak + 3][arow + 64] = a1.w;
        *(float4*)&Bs[bk0][bc0]     = b0;
        *(float4*)&Bs[bk0 + 8][bc0] = b1;
        __syncthreads();

        #pragma unroll
        for (int kk = 0; kk < BKG; kk++) {
            float a[8], b[8];
            *(float4*)&a[0] = *(const float4*)&As[kk][tr * 8];
            *(float4*)&a[4] = *(const float4*)&As[kk][tr * 8 + 4];
            *(float4*)&b[0] = *(const float4*)&Bs[kk][tc * 8];
            *(float4*)&b[4] = *(const float4*)&Bs[kk][tc * 8 + 4];
            #pragma unroll
            for (int i = 0; i < 8; i++)
                #pragma unroll
                for (int j = 0; j < 8; j++)
                    acc[i][j] = fmaf(a[i], b[j], acc[i][j]);
        }
    }

    // Epilogue: RoPE (q/k) and scatter into attention-friendly layouts.
    const int nbase = ncol0 + tc * 8;        // column within this weight matrix
    const int head  = nbase >> 7;            // head index within region
    const int dbase = nbase & (DHEAD - 1);   // multiple of 8 (even)

    #pragma unroll
    for (int i = 0; i < 8; i++) {
        const int m  = m0 + tr * 8 + i;
        const int bb = m >> 11;              // / SEQ
        const int tt = m & (SEQ - 1);
        float outv[8];
        if (region < 2) {
            #pragma unroll
            for (int j = 0; j < 8; j += 2) {
                const int d  = dbase + j;    // even
                const float ct = cosp[tt * DHEAD + d];
                const float st = sinp[tt * DHEAD + d];
                const float e = acc[i][j], o = acc[i][j + 1];
                outv[j]     = e * ct - o * st;
                outv[j + 1] = e * st + o * ct;
            }
        } else {
            #pragma unroll
            for (int j = 0; j < 8; j++) outv[j] = acc[i][j];
        }
        float* dst;
        if (region == 0)      dst = g_q + ((size_t)((bb * NHEAD + head) * SEQ + tt)) * DHEAD + dbase;
        else if (region == 1) dst = g_k + ((size_t)((bb * NKV  + head) * SEQ + tt)) * DHEAD + dbase;
        else                  dst = g_v + ((size_t)((bb * NKV  + head) * SEQ + tt)) * DHEAD + dbase;
        *(float4*)(dst)     = make_float4(outv[0], outv[1], outv[2], outv[3]);
        *(float4*)(dst + 4) = make_float4(outv[4], outv[5], outv[6], outv[7]);
    }
}

// ===========================================================================
// Kernel 2: fp32 flash attention (causal, GQA), BQ=BK=64, Dh=128, 256 threads
//   S cols mapped c = tx + 16*j  -> conflict-light Ks float4 reads
//   O cols mapped c = tx*8 + 0..7
// ===========================================================================
#define BQ 64
#define BKV 64
#define QPAD 132     // row stride for Qs/Ks/Vs (floats); 132*4B = 528B, 16B-aligned
#define PPAD 68      // row stride for Ps
#define ATTN_SMEM_FLOATS (3 * BQ * QPAD + BQ * PPAD)
#define ATTN_SMEM_BYTES  (ATTN_SMEM_FLOATS * 4)

__global__ __launch_bounds__(256, 1)
void flash_attn_kernel(const int* __restrict__ is_causal_p)
{
    extern __shared__ float smem[];
    float* Qs = smem;
    float* Ks = Qs + BQ * QPAD;
    float* Vs = Ks + BQ * QPAD;
    float* Ps = Vs + BQ * QPAD;

    const int tid = threadIdx.x;
    const int ty  = tid >> 4;   // 0..15
    const int tx  = tid & 15;   // 0..15
    const int qi  = gridDim.x - 1 - blockIdx.x;   // big causal tiles first
    const int h   = blockIdx.y;
    const int b   = blockIdx.z;
    const int kh  = h / GQA;

    const float scale = 0.08838834764831845f;     // 1/sqrt(128)

    const float* qg = g_q + ((size_t)(b * NHEAD + h) * SEQ + qi * BQ) * DHEAD;
    const float* kg = g_k + (size_t)(b * NKV + kh) * SEQ * DHEAD;
    const float* vg = g_v + (size_t)(b * NKV + kh) * SEQ * DHEAD;

    // Load Q tile (64 x 128) into padded smem
    for (int f = tid; f < BQ * (DHEAD / 4); f += 256) {
        const int r = f >> 5, c4 = (f & 31) << 2;
        *(float4*)&Qs[r * QPAD + c4] = *(const float4*)&qg[r * DHEAD + c4];
    }

    const int causal = is_causal_p[0];
    const int nkt = causal ? (qi + 1) : (SEQ / BKV);

    float m_i[4], l_i[4];
    float4 o0[4], o1[4];
    #pragma unroll
    for (int i = 0; i < 4; i++) {
        m_i[i] = -1e30f; l_i[i] = 0.f;
        o0[i] = make_float4(0.f, 0.f, 0.f, 0.f);
        o1[i] = make_float4(0.f, 0.f, 0.f, 0.f);
    }

    for (int kt = 0; kt < nkt; kt++) {
        __syncthreads();  // prior iteration done reading Ks/Vs/Ps
        for (int f = tid; f < BKV * (DHEAD / 4); f += 256) {
            const int r = f >> 5, c4 = (f & 31) << 2;
            *(float4*)&Ks[r * QPAD + c4] = *(const float4*)&kg[(size_t)(kt * BKV + r) * DHEAD + c4];
            *(float4*)&Vs[r * QPAD + c4] = *(const float4*)&vg[(size_t)(kt * BKV + r) * DHEAD + c4];
        }
        __syncthreads();

        // S = Q K^T : rows r = ty*4+i, cols c = tx + 16*j
        float s[4][4];
        #pragma unroll
        for (int i = 0; i < 4; i++)
            #pragma unroll
            for (int j = 0; j < 4; j++) s[i][j] = 0.f;

        #pragma unroll 4
        for (int d4 = 0; d4 < DHEAD / 4; d4++) {
            float4 qv[4], kv[4];
            #pragma unroll
            for (int i = 0; i < 4; i++)
                qv[i] = *(const float4*)&Qs[(ty * 4 + i) * QPAD + d4 * 4];
            #pragma unroll
            for (int j = 0; j < 4; j++)
                kv[j] = *(const float4*)&Ks[(tx + 16 * j) * QPAD + d4 * 4];
            #pragma unroll
            for (int i = 0; i < 4; i++)
                #pragma unroll
                for (int j = 0; j < 4; j++)
                    s[i][j] = fmaf(qv[i].x, kv[j].x,
                              fmaf(qv[i].y, kv[j].y,
                              fmaf(qv[i].z, kv[j].z,
                              fmaf(qv[i].w, kv[j].w, s[i][j]))));
        }

        const bool diag = causal && (kt == qi);
        #pragma unroll
        for (int i = 0; i < 4; i++) {
            const int r = ty * 4 + i;
            #pragma unroll
            for (int j = 0; j < 4; j++) {
                const int c = tx + 16 * j;
                float v = s[i][j] * scale;
                if (diag && c > r) v = -1e30f;
                s[i][j] = v;
            }
        }

        // Online softmax (row reductions across the 16 tx lanes of each half-warp)
        #pragma unroll
        for (int i = 0; i < 4; i++) {
            float mx = fmaxf(fmaxf(s[i][0], s[i][1]), fmaxf(s[i][2], s[i][3]));
            mx = fmaxf(mx, __shfl_xor_sync(0xffffffffu, mx, 1));
            mx = fmaxf(mx, __shfl_xor_sync(0xffffffffu, mx, 2));
            mx = fmaxf(mx, __shfl_xor_sync(0xffffffffu, mx, 4));
            mx = fmaxf(mx, __shfl_xor_sync(0xffffffffu, mx, 8));
            const float mnew  = fmaxf(m_i[i], mx);
            const float alpha = __expf(m_i[i] - mnew);
            float psum = 0.f;
            #pragma unroll
            for (int j = 0; j < 4; j++) {
                const float p = __expf(s[i][j] - mnew);
                s[i][j] = p;
                psum += p;
            }
            psum += __shfl_xor_sync(0xffffffffu, psum, 1);
            psum += __shfl_xor_sync(0xffffffffu, psum, 2);
            psum += __shfl_xor_sync(0xffffffffu, psum, 4);
            psum += __shfl_xor_sync(0xffffffffu, psum, 8);
            l_i[i] = l_i[i] * alpha + psum;
            m_i[i] = mnew;
            o0[i].x *= alpha; o0[i].y *= alpha; o0[i].z *= alpha; o0[i].w *= alpha;
            o1[i].x *= alpha; o1[i].y *= alpha; o1[i].z *= alpha; o1[i].w *= alpha;
        }

        // Publish P tile
        #pragma unroll
        for (int i = 0; i < 4; i++)
            #pragma unroll
            for (int j = 0; j < 4; j++)
                Ps[(ty * 4 + i) * PPAD + tx + 16 * j] = s[i][j];
        __syncthreads();

        // O += P @ V : rows r = ty*4+i, cols c = tx*8 + 0..7
        #pragma unroll 4
        for (int jj = 0; jj < BKV; jj += 4) {
            float pr[4][4];
            #pragma unroll
            for (int i = 0; i < 4; i++) {
                const float4 p4 = *(const float4*)&Ps[(ty * 4 + i) * PPAD + jj];
                pr[i][0] = p4.x; pr[i][1] = p4.y; pr[i][2] = p4.z; pr[i][3] = p4.w;
            }
            #pragma unroll
            for (int u = 0; u < 4; u++) {
                const float4 v0 = *(const float4*)&Vs[(jj + u) * QPAD + tx * 8];
                const float4 v1 = *(const float4*)&Vs[(jj + u) * QPAD + tx * 8 + 4];
                #pragma unroll
                for (int i = 0; i < 4; i++) {
                    const float p = pr[i][u];
                    o0[i].x = fmaf(p, v0.x, o0[i].x);
                    o0[i].y = fmaf(p, v0.y, o0[i].y);
                    o0[i].z = fmaf(p, v0.z, o0[i].z);
                    o0[i].w = fmaf(p, v0.w, o0[i].w);
                    o1[i].x = fmaf(p, v1.x, o1[i].x);
                    o1[i].y = fmaf(p, v1.y, o1[i].y);
                    o1[i].z = fmaf(p, v1.z, o1[i].z);
                    o1[i].w = fmaf(p, v1.w, o1[i].w);
                }
            }
        }
    }

    // Normalize and write to g_ao[B*T, C] (row = b*T + t, col = h*128 + c)
    #pragma unroll
    for (int i = 0; i < 4; i++) {
        const float inv = 1.0f / l_i[i];
        o0[i].x *= inv; o0[i].y *= inv; o0[i].z *= inv; o0[i].w *= inv;
        o1[i].x *= inv; o1[i].y *= inv; o1[i].z *= inv; o1[i].w *= inv;
        const int r   = ty * 4 + i;
        const int row = b * SEQ + qi * BQ + r;
        float* dst = g_ao + (size_t)row * CMODEL + h * DHEAD + tx * 8;
        *(float4*)(dst)     = o0[i];
        *(float4*)(dst + 4) = o1[i];
    }
}

// ===========================================================================
// Kernel 3: output projection  d_out[4096,4096] = g_ao @ wo
// ===========================================================================
__global__ __launch_bounds__(256, 2)
void out_proj_kernel(const float* __restrict__ wo, float* __restrict__ out)
{
    __shared__ float As[BKG][BM + APAD];
    __shared__ float Bs[BKG][BN];

    const int tid = threadIdx.x;
    const int tr  = tid >> 4;
    const int tc  = tid & 15;
    const int m0  = blockIdx.y * BM;
    const int n0  = blockIdx.x * BN;

    const int arow = tid >> 2;
    const int ak   = (tid & 3) << 2;
    const int bk0  = tid >> 5;
    const int bc0  = (tid & 31) << 2;

    float acc[8][8];
    #pragma unroll
    for (int i = 0; i < 8; i++)
        #pragma unroll
        for (int j = 0; j < 8; j++) acc[i][j] = 0.f;

    for (int k0 = 0; k0 < CMODEL; k0 += BKG) {
        const float4 a0 = *(const float4*)(g_ao + (size_t)(m0 + arow)      * CMODEL + k0 + ak);
        const float4 a1 = *(const float4*)(g_ao + (size_t)(m0 + arow + 64) * CMODEL + k0 + ak);
        const float4 b0 = *(const float4*)(wo   + (size_t)(k0 + bk0)     * CMODEL + n0 + bc0);
        const float4 b1 = *(const float4*)(wo   + (size_t)(k0 + bk0 + 8) * CMODEL + n0 + bc0);

        __syncthreads();
        As[ak + 0][arow] = a0.x; As[ak + 1][arow] = a0.y;
        As[ak + 2][arow] = a0.z; As[ak + 3][arow] = a0.w;
        As[ak + 0][arow + 64] = a1.x; As[ak + 1][arow + 64] = a1.y;
        As[ak + 2][arow + 64] = a1.z; As[ak + 3][arow + 64] = a1.w;
        *(float4*)&Bs[bk0][bc0]     = b0;
        *(float4*)&Bs[bk0 + 8][bc0] = b1;
        __syncthreads();

        #pragma unroll
        for (int kk = 0; kk < BKG; kk++) {
            float a[8], b[8];
            *(float4*)&a[0] = *(const float4*)&As[kk][tr * 8];
            *(float4*)&a[4] = *(const float4*)&As[kk][tr * 8 + 4];
            *(float4*)&b[0] = *(const float4*)&Bs[kk][tc * 8];
            *(float4*)&b[4] = *(const float4*)&Bs[kk][tc * 8 + 4];
            #pragma unroll
            for (int i = 0; i < 8; i++)
                #pragma unroll
                for (int j = 0; j < 8; j++)
                    acc[i][j] = fmaf(a[i], b[j], acc[i][j]);
        }
    }

    #pragma unroll
    for (int i = 0; i < 8; i++) {
        float* dst = out + (size_t)(m0 + tr * 8 + i) * CMODEL + n0 + tc * 8;
        *(float4*)(dst)     = make_float4(acc[i][0], acc[i][1], acc[i][2], acc[i][3]);
        *(float4*)(dst + 4) = make_float4(acc[i][4], acc[i][5], acc[i][6], acc[i][7]);
    }
}

// ===========================================================================
// Launch
// ===========================================================================
extern "C" void kernel_launch(void* const* d_in, const int* in_sizes, int n_in,
                              void* d_out, int out_size)
{
    const float* x    = (const float*)d_in[0];
    const float* wq   = (const float*)d_in[1];
    const float* wk   = (const float*)d_in[2];
    const float* wv   = (const float*)d_in[3];
    const float* wo   = (const float*)d_in[4];
    const float* cosp = (const float*)d_in[5];
    const float* sinp = (const float*)d_in[6];
    const int*   isc  = (const int*)d_in[7];

    // QKV projection + RoPE
    dim3 g1(NQKV / BN, MROWS / BM);        // (48, 32)
    qkv_rope_kernel<<<g1, 256>>>(x, wq, wk, wv, cosp, sinp);

    // Flash attention (118 KB dynamic smem). Attribute set is idempotent; the
    // first (uncaptured) correctness call establishes it before graph capture.
    cudaFuncSetAttribute(flash_attn_kernel,
                         cudaFuncAttributeMaxDynamicSharedMemorySize,
                         ATTN_SMEM_BYTES);
    dim3 g2(SEQ / BQ, NHEAD, BATCH);       // (32, 32, 2)
    flash_attn_kernel<<<g2, 256, ATTN_SMEM_BYTES>>>(isc);

    // Output projection
    dim3 g3(CMODEL / BN, MROWS / BM);      // (32, 32)
    out_proj_kernel<<<g3, 256>>>(wo, (float*)d_out);
}

// round 4
// speedup vs baseline: 1.9557x; 1.9557x over previous
#include <cuda_runtime.h>
#include <cuda_bf16.h>
#include <cstdint>

// ---------------------------------------------------------------------------
// B=2, T=2048, C=4096, H=32, Dh=128, n_kv=8, G=4
// Inputs: x, wq, wk, wv, wo, cos, sin, is_causal ; Output: [B*T, C] fp32
// ---------------------------------------------------------------------------
#define BATCH   2
#define SEQ     2048
#define CMODEL  4096
#define NHEAD   32
#define DHEAD   128
#define NKV     8
#define GQA     4
#define MROWS   (BATCH * SEQ)                 // 4096
#define NQKV    (CMODEL + 2 * NKV * DHEAD)    // 6144

// ------------------------- device scratch (no allocs) ----------------------
__device__ float g_q [BATCH * NHEAD * SEQ * DHEAD];
__device__ float g_k [BATCH * NKV   * SEQ * DHEAD];
__device__ float g_v [BATCH * NKV   * SEQ * DHEAD];
__device__ float g_ao[MROWS * CMODEL];

__device__ __nv_bfloat16 g_xh [MROWS * CMODEL];
__device__ __nv_bfloat16 g_xl [MROWS * CMODEL];
__device__ __nv_bfloat16 g_wth[NQKV * CMODEL];    // [feature][K] transposed
__device__ __nv_bfloat16 g_wtl[NQKV * CMODEL];
__device__ __nv_bfloat16 g_woth[CMODEL * CMODEL];
__device__ __nv_bfloat16 g_wotl[CMODEL * CMODEL];
__device__ __nv_bfloat16 g_aoh[MROWS * CMODEL];
__device__ __nv_bfloat16 g_aol[MROWS * CMODEL];

// ------------------------- PTX helpers (sm_80-level, legal on compute_103) --
__device__ __forceinline__ uint32_t s2u(const void* p) {
    uint32_t a;
    asm("{ .reg .u64 t; cvta.to.shared.u64 t, %1; cvt.u32.u64 %0, t; }" : "=r"(a) : "l"(p));
    return a;
}
__device__ __forceinline__ void ldsm4(uint32_t& r0, uint32_t& r1, uint32_t& r2, uint32_t& r3,
                                      uint32_t addr) {
    asm volatile("ldmatrix.sync.aligned.m8n8.x4.shared.b16 {%0,%1,%2,%3}, [%4];"
                 : "=r"(r0), "=r"(r1), "=r"(r2), "=r"(r3) : "r"(addr));
}
__device__ __forceinline__ void ldsm2(uint32_t& r0, uint32_t& r1, uint32_t addr) {
    asm volatile("ldmatrix.sync.aligned.m8n8.x2.shared.b16 {%0,%1}, [%2];"
                 : "=r"(r0), "=r"(r1) : "r"(addr));
}
__device__ __forceinline__ void mma16816(float* c, uint32_t a0, uint32_t a1, uint32_t a2,
                                         uint32_t a3, uint32_t b0, uint32_t b1) {
    asm volatile("mma.sync.aligned.m16n8k16.row.col.f32.bf16.bf16.f32 "
                 "{%0,%1,%2,%3}, {%4,%5,%6,%7}, {%8,%9}, {%0,%1,%2,%3};"
                 : "+f"(c[0]), "+f"(c[1]), "+f"(c[2]), "+f"(c[3])
                 : "r"(a0), "r"(a1), "r"(a2), "r"(a3), "r"(b0), "r"(b1));
}

// ------------------------- conversion kernels -------------------------------
__global__ __launch_bounds__(256)
void fsplit_kernel(const float* __restrict__ s, __nv_bfloat16* __restrict__ dh,
                   __nv_bfloat16* __restrict__ dl, int n4) {
    int i = blockIdx.x * 256 + threadIdx.x;
    if (i >= n4) return;
    float4 v = ((const float4*)s)[i];
    __nv_bfloat16 h0 = __float2bfloat16(v.x), h1 = __float2bfloat16(v.y);
    __nv_bfloat16 h2 = __float2bfloat16(v.z), h3 = __float2bfloat16(v.w);
    __nv_bfloat16 l0 = __float2bfloat16(v.x - __bfloat162float(h0));
    __nv_bfloat16 l1 = __float2bfloat16(v.y - __bfloat162float(h1));
    __nv_bfloat16 l2 = __float2bfloat16(v.z - __bfloat162float(h2));
    __nv_bfloat16 l3 = __float2bfloat16(v.w - __bfloat162float(h3));
    ((__nv_bfloat162*)dh)[i * 2]     = __nv_bfloat162(h0, h1);
    ((__nv_bfloat162*)dh)[i * 2 + 1] = __nv_bfloat162(h2, h3);
    ((__nv_bfloat162*)dl)[i * 2]     = __nv_bfloat162(l0, l1);
    ((__nv_bfloat162*)dl)[i * 2 + 1] = __nv_bfloat162(l2, l3);
}

__global__ __launch_bounds__(256)
void tsplit_kernel(const float* __restrict__ src, int N,
                   __nv_bfloat16* __restrict__ dh, __nv_bfloat16* __restrict__ dl,
                   int row_off) {
    __shared__ float t[32][33];
    const int k0 = blockIdx.y * 32, n0 = blockIdx.x * 32;
    const int tx = threadIdx.x, ty = threadIdx.y;    // (32, 8)
    #pragma unroll
    for (int i = 0; i < 32; i += 8)
        t[ty + i][tx] = src[(size_t)(k0 + ty + i) * N + n0 + tx];
    __syncthreads();
    #pragma unroll
    for (int i = 0; i < 32; i += 8) {
        const int n = n0 + ty + i, k = k0 + tx;
        const float v = t[tx][ty + i];
        const __nv_bfloat16 h = __float2bfloat16(v);
        const __nv_bfloat16 l = __float2bfloat16(v - __bfloat162float(h));
        dh[(size_t)(row_off + n) * CMODEL + k] = h;
        dl[(size_t)(row_off + n) * CMODEL + k] = l;
    }
}

// ------------------------- split-bf16 HMMA GEMM -----------------------------
// C[128,128] = A[m0:,K] * B(features)[n0:,K]^T  (TN), 3 passes:
// Ahi*Bhi + Ahi*Blo + Alo*Bhi, fp32 accumulators in registers.
#define BKH 64                   // bf16 K per iter
#define LDA 72                   // padded smem row stride (bf16): 144B, ldmatrix conflict-free
#define TILE_SM (128 * LDA)      // bf16 elems per tile
#define GEMM_SMEM (4 * TILE_SM * 2)   // 73728 B

__device__ __forceinline__ void load_tile(const __nv_bfloat16* __restrict__ g,
                                          int row0, int col0, __nv_bfloat16* s, int tid) {
    const char* gp = (const char*)(g + (size_t)row0 * CMODEL + col0);
    #pragma unroll
    for (int i = 0; i < 4; i++) {
        const int idx = i * 256 + tid;     // 0..1023 ; 128 rows * 8 x 16B
        const int r = idx >> 3, cb = (idx & 7) << 4;
        const uint4 v = *(const uint4*)(gp + (size_t)r * (CMODEL * 2) + cb);
        *(uint4*)((char*)s + r * (LDA * 2) + cb) = v;
    }
}

template<int MODE>   // 0 = QKV (+RoPE scatter), 1 = out proj -> outp
__global__ __launch_bounds__(256)
void gemm_mma(const __nv_bfloat16* __restrict__ Ah, const __nv_bfloat16* __restrict__ Al,
              const __nv_bfloat16* __restrict__ Bh, const __nv_bfloat16* __restrict__ Bl,
              const float* __restrict__ cosp, const float* __restrict__ sinp,
              float* __restrict__ outp)
{
    extern __shared__ __nv_bfloat16 sm[];
    __nv_bfloat16* sAh = sm;
    __nv_bfloat16* sAl = sm + TILE_SM;
    __nv_bfloat16* sBh = sm + 2 * TILE_SM;
    __nv_bfloat16* sBl = sm + 3 * TILE_SM;

    const int tid  = threadIdx.x;
    const int wid  = tid >> 5, lane = tid & 31;
    const int wm   = wid >> 2;          // 0..1 : 64 rows each
    const int wn   = wid & 3;           // 0..3 : 32 cols each
    const int n0   = blockIdx.x * 128, m0 = blockIdx.y * 128;

    float acc[4][4][4];
    #pragma unroll
    for (int i = 0; i < 4; i++)
        #pragma unroll
        for (int j = 0; j < 4; j++)
            #pragma unroll
            for (int c = 0; c < 4; c++) acc[i][j][c] = 0.f;

    const uint32_t uAh = s2u(sAh), uAl = s2u(sAl), uBh = s2u(sBh), uBl = s2u(sBl);
    // A frag addr: row = lane%16 (+16*mf), k-half byte = (lane/16)*16
    const uint32_t aOff = (uint32_t)((wm * 64 + (lane & 15)) * (LDA * 2) + (lane >> 4) * 16);
    // B frag addr: row = lane%8 (+8*nf), k-half byte = ((lane&15)>>3)*16
    const uint32_t bOff = (uint32_t)((wn * 32 + (lane & 7)) * (LDA * 2) + ((lane & 15) >> 3) * 16);

    for (int kc = 0; kc < CMODEL; kc += BKH) {
        load_tile(Ah, m0, kc, sAh, tid);
        load_tile(Al, m0, kc, sAl, tid);
        load_tile(Bh, n0, kc, sBh, tid);
        load_tile(Bl, n0, kc, sBl, tid);
        __syncthreads();

        #pragma unroll
        for (int ks = 0; ks < 4; ks++) {
            const uint32_t kb = ks * 32;     // 16 bf16 = 32B per k-step
            uint32_t ah[4][4], al[4][4], bh[4][2], bl[4][2];
            #pragma unroll
            for (int mf = 0; mf < 4; mf++) {
                ldsm4(ah[mf][0], ah[mf][1], ah[mf][2], ah[mf][3],
                      uAh + aOff + mf * (16 * LDA * 2) + kb);
                ldsm4(al[mf][0], al[mf][1], al[mf][2], al[mf][3],
                      uAl + aOff + mf * (16 * LDA * 2) + kb);
            }
            #pragma unroll
            for (int nf = 0; nf < 4; nf++) {
                ldsm2(bh[nf][0], bh[nf][1], uBh + bOff + nf * (8 * LDA * 2) + kb);
                ldsm2(bl[nf][0], bl[nf][1], uBl + bOff + nf * (8 * LDA * 2) + kb);
            }
            #pragma unroll
            for (int mf = 0; mf < 4; mf++)
                #pragma unroll
                for (int nf = 0; nf < 4; nf++) {
                    mma16816(acc[mf][nf], ah[mf][0], ah[mf][1], ah[mf][2], ah[mf][3],
                             bh[nf][0], bh[nf][1]);
                    mma16816(acc[mf][nf], ah[mf][0], ah[mf][1], ah[mf][2], ah[mf][3],
                             bl[nf][0], bl[nf][1]);
                    mma16816(acc[mf][nf], al[mf][0], al[mf][1], al[mf][2], al[mf][3],
                             bh[nf][0], bh[nf][1]);
                }
        }
        __syncthreads();
    }

    // -------- epilogue ------------------------------------------------------
    // C frag: (c0,c1) at row g=lane>>2, cols 2*(lane&3),+1 ; (c2,c3) at row g+8.
    const int group = lane >> 2, tig = lane & 3;

    if (MODE == 0) {
        float* basep; int head, roped;
        if (n0 < CMODEL)             { basep = g_q; head = n0 >> 7;                  roped = 1; }
        else if (n0 < CMODEL + 1024) { basep = g_k; head = (n0 - CMODEL) >> 7;       roped = 1; }
        else                         { basep = g_v; head = (n0 - CMODEL - 1024) >> 7; roped = 0; }
        const int nh = (n0 < CMODEL) ? NHEAD : NKV;
        #pragma unroll
        for (int mf = 0; mf < 4; mf++) {
            #pragma unroll
            for (int nf = 0; nf < 4; nf++) {
                const int d = wn * 32 + nf * 8 + tig * 2;
                #pragma unroll
                for (int half = 0; half < 2; half++) {
                    const int row = m0 + wm * 64 + mf * 16 + group + half * 8;
                    const int bb = row >> 11, tt = row & (SEQ - 1);
                    float e = acc[mf][nf][half * 2], o = acc[mf][nf][half * 2 + 1];
                    if (roped) {
                        const float ct = cosp[tt * DHEAD + d];
                        const float st = sinp[tt * DHEAD + d];
                        const float ne = e * ct - o * st;
                        o = e * st + o * ct;
                        e = ne;
                    }
                    float* dst = basep + ((size_t)(bb * nh + head) * SEQ + tt) * DHEAD + d;
                    *(float2*)dst = make_float2(e, o);
                }
            }
        }
    } else {
        #pragma unroll
        for (int mf = 0; mf < 4; mf++) {
            #pragma unroll
            for (int nf = 0; nf < 4; nf++) {
                const int d = wn * 32 + nf * 8 + tig * 2;
                #pragma unroll
                for (int half = 0; half < 2; half++) {
                    const int row = m0 + wm * 64 + mf * 16 + group + half * 8;
                    float* dst = outp + (size_t)row * CMODEL + n0 + d;
                    *(float2*)dst = make_float2(acc[mf][nf][half * 2], acc[mf][nf][half * 2 + 1]);
                }
            }
        }
    }
}

// ===========================================================================
// Flash attention (unchanged from passing round-2 kernel)
// ===========================================================================
#define BQ 64
#define BKV 64
#define QPAD 132
#define PPAD 68
#define ATTN_SMEM_FLOATS (3 * BQ * QPAD + BQ * PPAD)
#define ATTN_SMEM_BYTES  (ATTN_SMEM_FLOATS * 4)

__global__ __launch_bounds__(256, 1)
void flash_attn_kernel(const int* __restrict__ is_causal_p)
{
    extern __shared__ float smem[];
    float* Qs = smem;
    float* Ks = Qs + BQ * QPAD;
    float* Vs = Ks + BQ * QPAD;
    float* Ps = Vs + BQ * QPAD;

    const int tid = threadIdx.x;
    const int ty  = tid >> 4;
    const int tx  = tid & 15;
    const int qi  = gridDim.x - 1 - blockIdx.x;
    const int h   = blockIdx.y;
    const int b   = blockIdx.z;
    const int kh  = h / GQA;

    const float scale = 0.08838834764831845f;

    const float* qg = g_q + ((size_t)(b * NHEAD + h) * SEQ + qi * BQ) * DHEAD;
    const float* kg = g_k + (size_t)(b * NKV + kh) * SEQ * DHEAD;
    const float* vg = g_v + (size_t)(b * NKV + kh) * SEQ * DHEAD;

    for (int f = tid; f < BQ * (DHEAD / 4); f += 256) {
        const int r = f >> 5, c4 = (f & 31) << 2;
        *(float4*)&Qs[r * QPAD + c4] = *(const float4*)&qg[r * DHEAD + c4];
    }

    const int causal = is_causal_p[0];
    const int nkt = causal ? (qi + 1) : (SEQ / BKV);

    float m_i[4], l_i[4];
    float4 o0[4], o1[4];
    #pragma unroll
    for (int i = 0; i < 4; i++) {
        m_i[i] = -1e30f; l_i[i] = 0.f;
        o0[i] = make_float4(0.f, 0.f, 0.f, 0.f);
        o1[i] = make_float4(0.f, 0.f, 0.f, 0.f);
    }

    for (int kt = 0; kt < nkt; kt++) {
        __syncthreads();
        for (int f = tid; f < BKV * (DHEAD / 4); f += 256) {
            const int r = f >> 5, c4 = (f & 31) << 2;
            *(float4*)&Ks[r * QPAD + c4] = *(const float4*)&kg[(size_t)(kt * BKV + r) * DHEAD + c4];
            *(float4*)&Vs[r * QPAD + c4] = *(const float4*)&vg[(size_t)(kt * BKV + r) * DHEAD + c4];
        }
        __syncthreads();

        float s[4][4];
        #pragma unroll
        for (int i = 0; i < 4; i++)
            #pragma unroll
            for (int j = 0; j < 4; j++) s[i][j] = 0.f;

        #pragma unroll 4
        for (int d4 = 0; d4 < DHEAD / 4; d4++) {
            float4 qv[4], kv[4];
            #pragma unroll
            for (int i = 0; i < 4; i++)
                qv[i] = *(const float4*)&Qs[(ty * 4 + i) * QPAD + d4 * 4];
            #pragma unroll
            for (int j = 0; j < 4; j++)
                kv[j] = *(const float4*)&Ks[(tx + 16 * j) * QPAD + d4 * 4];
            #pragma unroll
            for (int i = 0; i < 4; i++)
                #pragma unroll
                for (int j = 0; j < 4; j++)
                    s[i][j] = fmaf(qv[i].x, kv[j].x,
                              fmaf(qv[i].y, kv[j].y,
                              fmaf(qv[i].z, kv[j].z,
                              fmaf(qv[i].w, kv[j].w, s[i][j]))));
        }

        const bool diag = causal && (kt == qi);
        #pragma unroll
        for (int i = 0; i < 4; i++) {
            const int r = ty * 4 + i;
            #pragma unroll
            for (int j = 0; j < 4; j++) {
                const int c = tx + 16 * j;
                float v = s[i][j] * scale;
                if (diag && c > r) v = -1e30f;
                s[i][j] = v;
            }
        }

        #pragma unroll
        for (int i = 0; i < 4; i++) {
            float mx = fmaxf(fmaxf(s[i][0], s[i][1]), fmaxf(s[i][2], s[i][3]));
            mx = fmaxf(mx, __shfl_xor_sync(0xffffffffu, mx, 1));
            mx = fmaxf(mx, __shfl_xor_sync(0xffffffffu, mx, 2));
            mx = fmaxf(mx, __shfl_xor_sync(0xffffffffu, mx, 4));
            mx = fmaxf(mx, __shfl_xor_sync(0xffffffffu, mx, 8));
            const float mnew  = fmaxf(m_i[i], mx);
            const float alpha = __expf(m_i[i] - mnew);
            float psum = 0.f;
            #pragma unroll
            for (int j = 0; j < 4; j++) {
                const float p = __expf(s[i][j] - mnew);
                s[i][j] = p;
                psum += p;
            }
            psum += __shfl_xor_sync(0xffffffffu, psum, 1);
            psum += __shfl_xor_sync(0xffffffffu, psum, 2);
            psum += __shfl_xor_sync(0xffffffffu, psum, 4);
            psum += __shfl_xor_sync(0xffffffffu, psum, 8);
            l_i[i] = l_i[i] * alpha + psum;
            m_i[i] = mnew;
            o0[i].x *= alpha; o0[i].y *= alpha; o0[i].z *= alpha; o0[i].w *= alpha;
            o1[i].x *= alpha; o1[i].y *= alpha; o1[i].z *= alpha; o1[i].w *= alpha;
        }

        #pragma unroll
        for (int i = 0; i < 4; i++)
            #pragma unroll
            for (int j = 0; j < 4; j++)
                Ps[(ty * 4 + i) * PPAD + tx + 16 * j] = s[i][j];
        __syncthreads();

        #pragma unroll 4
        for (int jj = 0; jj < BKV; jj += 4) {
            float pr[4][4];
            #pragma unroll
            for (int i = 0; i < 4; i++) {
                const float4 p4 = *(const float4*)&Ps[(ty * 4 + i) * PPAD + jj];
                pr[i][0] = p4.x; pr[i][1] = p4.y; pr[i][2] = p4.z; pr[i][3] = p4.w;
            }
            #pragma unroll
            for (int u = 0; u < 4; u++) {
                const float4 v0 = *(const float4*)&Vs[(jj + u) * QPAD + tx * 8];
                const float4 v1 = *(const float4*)&Vs[(jj + u) * QPAD + tx * 8 + 4];
                #pragma unroll
                for (int i = 0; i < 4; i++) {
                    const float p = pr[i][u];
                    o0[i].x = fmaf(p, v0.x, o0[i].x);
                    o0[i].y = fmaf(p, v0.y, o0[i].y);
                    o0[i].z = fmaf(p, v0.z, o0[i].z);
                    o0[i].w = fmaf(p, v0.w, o0[i].w);
                    o1[i].x = fmaf(p, v1.x, o1[i].x);
                    o1[i].y = fmaf(p, v1.y, o1[i].y);
                    o1[i].z = fmaf(p, v1.z, o1[i].z);
                    o1[i].w = fmaf(p, v1.w, o1[i].w);
                }
            }
        }
    }

    #pragma unroll
    for (int i = 0; i < 4; i++) {
        const float inv = 1.0f / l_i[i];
        o0[i].x *= inv; o0[i].y *= inv; o0[i].z *= inv; o0[i].w *= inv;
        o1[i].x *= inv; o1[i].y *= inv; o1[i].z *= inv; o1[i].w *= inv;
        const int r   = ty * 4 + i;
        const int row = b * SEQ + qi * BQ + r;
        float* dst = g_ao + (size_t)row * CMODEL + h * DHEAD + tx * 8;
        *(float4*)(dst)     = o0[i];
        *(float4*)(dst + 4) = o1[i];
    }
}

// ===========================================================================
// Launch
// ===========================================================================
extern "C" void kernel_launch(void* const* d_in, const int* in_sizes, int n_in,
                              void* d_out, int out_size)
{
    const float* x    = (const float*)d_in[0];
    const float* wq   = (const float*)d_in[1];
    const float* wk   = (const float*)d_in[2];
    const float* wv   = (const float*)d_in[3];
    const float* wo   = (const float*)d_in[4];
    const float* cosp = (const float*)d_in[5];
    const float* sinp = (const float*)d_in[6];
    const int*   isc  = (const int*)d_in[7];

    __nv_bfloat16 *xh, *xl, *wth, *wtl, *woth, *wotl, *aoh, *aol;
    float *ao;
    cudaGetSymbolAddress((void**)&xh,  g_xh);   cudaGetSymbolAddress((void**)&xl,  g_xl);
    cudaGetSymbolAddress((void**)&wth, g_wth);  cudaGetSymbolAddress((void**)&wtl, g_wtl);
    cudaGetSymbolAddress((void**)&woth,g_woth); cudaGetSymbolAddress((void**)&wotl,g_wotl);
    cudaGetSymbolAddress((void**)&aoh, g_aoh);  cudaGetSymbolAddress((void**)&aol, g_aol);
    cudaGetSymbolAddress((void**)&ao,  g_ao);

    // 1) split x into bf16 hi/lo
    fsplit_kernel<<<(MROWS * CMODEL / 4 + 255) / 256, 256>>>(x, xh, xl, MROWS * CMODEL / 4);

    // 2) transpose+split weights into concatenated [feature][K]
    dim3 tb(32, 8);
    tsplit_kernel<<<dim3(CMODEL / 32, CMODEL / 32), tb>>>(wq, CMODEL, wth, wtl, 0);
    tsplit_kernel<<<dim3(1024 / 32,   CMODEL / 32), tb>>>(wk, 1024,   wth, wtl, CMODEL);
    tsplit_kernel<<<dim3(1024 / 32,   CMODEL / 32), tb>>>(wv, 1024,   wth, wtl, CMODEL + 1024);
    tsplit_kernel<<<dim3(CMODEL / 32, CMODEL / 32), tb>>>(wo, CMODEL, woth, wotl, 0);

    // 3) QKV projection on HMMA tensor cores + RoPE epilogue
    cudaFuncSetAttribute(gemm_mma<0>, cudaFuncAttributeMaxDynamicSharedMemorySize, GEMM_SMEM);
    gemm_mma<0><<<dim3(NQKV / 128, MROWS / 128), 256, GEMM_SMEM>>>(
        xh, xl, wth, wtl, cosp, sinp, nullptr);

    // 4) flash attention
    cudaFuncSetAttribute(flash_attn_kernel, cudaFuncAttributeMaxDynamicSharedMemorySize,
                         ATTN_SMEM_BYTES);
    dim3 g2(SEQ / BQ, NHEAD, BATCH);
    flash_attn_kernel<<<g2, 256, ATTN_SMEM_BYTES>>>(isc);

    // 5) split attention output
    fsplit_kernel<<<(MROWS * CMODEL / 4 + 255) / 256, 256>>>(ao, aoh, aol, MROWS * CMODEL / 4);

    // 6) output projection on HMMA tensor cores
    cudaFuncSetAttribute(gemm_mma<1>, cudaFuncAttributeMaxDynamicSharedMemorySize, GEMM_SMEM);
    gemm_mma<1><<<dim3(CMODEL / 128, MROWS / 128), 256, GEMM_SMEM>>>(
        aoh, aol, woth, wotl, nullptr, nullptr, (float*)d_out);
}

// round 5
// speedup vs baseline: 2.9158x; 1.4909x over previous
#include <cuda_runtime.h>
#include <cuda_bf16.h>
#include <cstdint>

#define BATCH   2
#define SEQ     2048
#define CMODEL  4096
#define NHEAD   32
#define DHEAD   128
#define NKV     8
#define GQA     4
#define MROWS   (BATCH * SEQ)
#define NQKV    (CMODEL + 2 * NKV * DHEAD)    // 6144

// ------------------------- device scratch (no allocs) ----------------------
__device__ __nv_bfloat16 g_qh[BATCH * NHEAD * SEQ * DHEAD];
__device__ __nv_bfloat16 g_ql[BATCH * NHEAD * SEQ * DHEAD];
__device__ __nv_bfloat16 g_kh[BATCH * NKV * SEQ * DHEAD];
__device__ __nv_bfloat16 g_kl[BATCH * NKV * SEQ * DHEAD];
__device__ __nv_bfloat16 g_vh[BATCH * NKV * SEQ * DHEAD];
__device__ __nv_bfloat16 g_vl[BATCH * NKV * SEQ * DHEAD];

__device__ __nv_bfloat16 g_xh [MROWS * CMODEL];
__device__ __nv_bfloat16 g_xl [MROWS * CMODEL];
__device__ __nv_bfloat16 g_wth[NQKV * CMODEL];
__device__ __nv_bfloat16 g_wtl[NQKV * CMODEL];
__device__ __nv_bfloat16 g_woth[CMODEL * CMODEL];
__device__ __nv_bfloat16 g_wotl[CMODEL * CMODEL];
__device__ __nv_bfloat16 g_aoh[MROWS * CMODEL];
__device__ __nv_bfloat16 g_aol[MROWS * CMODEL];

// ------------------------- PTX helpers --------------------------------------
__device__ __forceinline__ uint32_t s2u(const void* p) {
    uint32_t a;
    asm("{ .reg .u64 t; cvta.to.shared.u64 t, %1; cvt.u32.u64 %0, t; }" : "=r"(a) : "l"(p));
    return a;
}
__device__ __forceinline__ void ldsm4(uint32_t& r0, uint32_t& r1, uint32_t& r2, uint32_t& r3,
                                      uint32_t addr) {
    asm volatile("ldmatrix.sync.aligned.m8n8.x4.shared.b16 {%0,%1,%2,%3}, [%4];"
                 : "=r"(r0), "=r"(r1), "=r"(r2), "=r"(r3) : "r"(addr));
}
__device__ __forceinline__ void ldsm4t(uint32_t& r0, uint32_t& r1, uint32_t& r2, uint32_t& r3,
                                       uint32_t addr) {
    asm volatile("ldmatrix.sync.aligned.m8n8.x4.trans.shared.b16 {%0,%1,%2,%3}, [%4];"
                 : "=r"(r0), "=r"(r1), "=r"(r2), "=r"(r3) : "r"(addr));
}
__device__ __forceinline__ void ldsm2(uint32_t& r0, uint32_t& r1, uint32_t addr) {
    asm volatile("ldmatrix.sync.aligned.m8n8.x2.shared.b16 {%0,%1}, [%2];"
                 : "=r"(r0), "=r"(r1) : "r"(addr));
}
__device__ __forceinline__ void mma16816(float* c, uint32_t a0, uint32_t a1, uint32_t a2,
                                         uint32_t a3, uint32_t b0, uint32_t b1) {
    asm volatile("mma.sync.aligned.m16n8k16.row.col.f32.bf16.bf16.f32 "
                 "{%0,%1,%2,%3}, {%4,%5,%6,%7}, {%8,%9}, {%0,%1,%2,%3};"
                 : "+f"(c[0]), "+f"(c[1]), "+f"(c[2]), "+f"(c[3])
                 : "r"(a0), "r"(a1), "r"(a2), "r"(a3), "r"(b0), "r"(b1));
}
__device__ __forceinline__ void split_pair(float a, float b,
                                           __nv_bfloat162& hi, __nv_bfloat162& lo) {
    __nv_bfloat16 ha = __float2bfloat16(a), hb = __float2bfloat16(b);
    hi = __nv_bfloat162(ha, hb);
    lo = __nv_bfloat162(__float2bfloat16(a - __bfloat162float(ha)),
                        __float2bfloat16(b - __bfloat162float(hb)));
}

// ------------------------- conversion kernels -------------------------------
__global__ __launch_bounds__(256)
void fsplit_kernel(const float* __restrict__ s, __nv_bfloat16* __restrict__ dh,
                   __nv_bfloat16* __restrict__ dl, int n4) {
    int i = blockIdx.x * 256 + threadIdx.x;
    if (i >= n4) return;
    float4 v = ((const float4*)s)[i];
    __nv_bfloat162 h0, l0, h1, l1;
    split_pair(v.x, v.y, h0, l0);
    split_pair(v.z, v.w, h1, l1);
    ((__nv_bfloat162*)dh)[i * 2]     = h0;
    ((__nv_bfloat162*)dh)[i * 2 + 1] = h1;
    ((__nv_bfloat162*)dl)[i * 2]     = l0;
    ((__nv_bfloat162*)dl)[i * 2 + 1] = l1;
}

__global__ __launch_bounds__(256)
void tsplit_kernel(const float* __restrict__ src, int N,
                   __nv_bfloat16* __restrict__ dh, __nv_bfloat16* __restrict__ dl,
                   int row_off) {
    __shared__ float t[32][33];
    const int k0 = blockIdx.y * 32, n0 = blockIdx.x * 32;
    const int tx = threadIdx.x, ty = threadIdx.y;
    #pragma unroll
    for (int i = 0; i < 32; i += 8)
        t[ty + i][tx] = src[(size_t)(k0 + ty + i) * N + n0 + tx];
    __syncthreads();
    #pragma unroll
    for (int i = 0; i < 32; i += 8) {
        const int n = n0 + ty + i, k = k0 + tx;
        const float v = t[tx][ty + i];
        const __nv_bfloat16 h = __float2bfloat16(v);
        dh[(size_t)(row_off + n) * CMODEL + k] = h;
        dl[(size_t)(row_off + n) * CMODEL + k] = __float2bfloat16(v - __bfloat162float(h));
    }
}

// ------------------------- split-bf16 HMMA GEMM (round-4, epilogue changed) -
#define BKH 64
#define LDA 72
#define TILE_SM (128 * LDA)
#define GEMM_SMEM (4 * TILE_SM * 2)

__device__ __forceinline__ void load_tile(const __nv_bfloat16* __restrict__ g,
                                          int row0, int col0, __nv_bfloat16* s, int tid) {
    const char* gp = (const char*)(g + (size_t)row0 * CMODEL + col0);
    #pragma unroll
    for (int i = 0; i < 4; i++) {
        const int idx = i * 256 + tid;
        const int r = idx >> 3, cb = (idx & 7) << 4;
        const uint4 v = *(const uint4*)(gp + (size_t)r * (CMODEL * 2) + cb);
        *(uint4*)((char*)s + r * (LDA * 2) + cb) = v;
    }
}

template<int MODE>
__global__ __launch_bounds__(256)
void gemm_mma(const __nv_bfloat16* __restrict__ Ah, const __nv_bfloat16* __restrict__ Al,
              const __nv_bfloat16* __restrict__ Bh, const __nv_bfloat16* __restrict__ Bl,
              const float* __restrict__ cosp, const float* __restrict__ sinp,
              float* __restrict__ outp)
{
    extern __shared__ __nv_bfloat16 sm[];
    __nv_bfloat16* sAh = sm;
    __nv_bfloat16* sAl = sm + TILE_SM;
    __nv_bfloat16* sBh = sm + 2 * TILE_SM;
    __nv_bfloat16* sBl = sm + 3 * TILE_SM;

    const int tid  = threadIdx.x;
    const int wid  = tid >> 5, lane = tid & 31;
    const int wm   = wid >> 2;
    const int wn   = wid & 3;
    const int n0   = blockIdx.x * 128, m0 = blockIdx.y * 128;

    float acc[4][4][4];
    #pragma unroll
    for (int i = 0; i < 4; i++)
        #pragma unroll
        for (int j = 0; j < 4; j++)
            #pragma unroll
            for (int c = 0; c < 4; c++) acc[i][j][c] = 0.f;

    const uint32_t uAh = s2u(sAh), uAl = s2u(sAl), uBh = s2u(sBh), uBl = s2u(sBl);
    const uint32_t aOff = (uint32_t)((wm * 64 + (lane & 15)) * (LDA * 2) + (lane >> 4) * 16);
    const uint32_t bOff = (uint32_t)((wn * 32 + (lane & 7)) * (LDA * 2) + ((lane & 15) >> 3) * 16);

    for (int kc = 0; kc < CMODEL; kc += BKH) {
        load_tile(Ah, m0, kc, sAh, tid);
        load_tile(Al, m0, kc, sAl, tid);
        load_tile(Bh, n0, kc, sBh, tid);
        load_tile(Bl, n0, kc, sBl, tid);
        __syncthreads();

        #pragma unroll
        for (int ks = 0; ks < 4; ks++) {
            const uint32_t kb = ks * 32;
            uint32_t ah[4][4], al[4][4], bh[4][2], bl[4][2];
            #pragma unroll
            for (int mf = 0; mf < 4; mf++) {
                ldsm4(ah[mf][0], ah[mf][1], ah[mf][2], ah[mf][3],
                      uAh + aOff + mf * (16 * LDA * 2) + kb);
                ldsm4(al[mf][0], al[mf][1], al[mf][2], al[mf][3],
                      uAl + aOff + mf * (16 * LDA * 2) + kb);
            }
            #pragma unroll
            for (int nf = 0; nf < 4; nf++) {
                ldsm2(bh[nf][0], bh[nf][1], uBh + bOff + nf * (8 * LDA * 2) + kb);
                ldsm2(bl[nf][0], bl[nf][1], uBl + bOff + nf * (8 * LDA * 2) + kb);
            }
            #pragma unroll
            for (int mf = 0; mf < 4; mf++)
                #pragma unroll
                for (int nf = 0; nf < 4; nf++) {
                    mma16816(acc[mf][nf], ah[mf][0], ah[mf][1], ah[mf][2], ah[mf][3],
                             bh[nf][0], bh[nf][1]);
                    mma16816(acc[mf][nf], ah[mf][0], ah[mf][1], ah[mf][2], ah[mf][3],
                             bl[nf][0], bl[nf][1]);
                    mma16816(acc[mf][nf], al[mf][0], al[mf][1], al[mf][2], al[mf][3],
                             bh[nf][0], bh[nf][1]);
                }
        }
        __syncthreads();
    }

    const int group = lane >> 2, tig = lane & 3;

    if (MODE == 0) {
        // QKV: RoPE (q,k) then split to bf16 hi/lo scatter
        __nv_bfloat16 *bph, *bpl; int head, roped, nh;
        if (n0 < CMODEL) {
            bph = g_qh; bpl = g_ql; head = n0 >> 7; roped = 1; nh = NHEAD;
        } else if (n0 < CMODEL + 1024) {
            bph = g_kh; bpl = g_kl; head = (n0 - CMODEL) >> 7; roped = 1; nh = NKV;
        } else {
            bph = g_vh; bpl = g_vl; head = (n0 - CMODEL - 1024) >> 7; roped = 0; nh = NKV;
        }
        #pragma unroll
        for (int mf = 0; mf < 4; mf++) {
            #pragma unroll
            for (int nf = 0; nf < 4; nf++) {
                const int d = wn * 32 + nf * 8 + tig * 2;
                #pragma unroll
                for (int half = 0; half < 2; half++) {
                    const int row = m0 + wm * 64 + mf * 16 + group + half * 8;
                    const int bb = row >> 11, tt = row & (SEQ - 1);
                    float e = acc[mf][nf][half * 2], o = acc[mf][nf][half * 2 + 1];
                    if (roped) {
                        const float ct = cosp[tt * DHEAD + d];
                        const float st = sinp[tt * DHEAD + d];
                        const float ne = e * ct - o * st;
                        o = e * st + o * ct;
                        e = ne;
                    }
                    __nv_bfloat162 hi, lo;
                    split_pair(e, o, hi, lo);
                    const size_t off = ((size_t)(bb * nh + head) * SEQ + tt) * DHEAD + d;
                    *(__nv_bfloat162*)(bph + off) = hi;
                    *(__nv_bfloat162*)(bpl + off) = lo;
                }
            }
        }
    } else {
        #pragma unroll
        for (int mf = 0; mf < 4; mf++) {
            #pragma unroll
            for (int nf = 0; nf < 4; nf++) {
                const int d = wn * 32 + nf * 8 + tig * 2;
                #pragma unroll
                for (int half = 0; half < 2; half++) {
                    const int row = m0 + wm * 64 + mf * 16 + group + half * 8;
                    float* dst = outp + (size_t)row * CMODEL + n0 + d;
                    *(float2*)dst = make_float2(acc[mf][nf][half * 2], acc[mf][nf][half * 2 + 1]);
                }
            }
        }
    }
}

// ===========================================================================
// HMMA flash attention: BQ=128, BKV=64, 8 warps, split-bf16 3-pass QK and PV
// ===========================================================================
#define FBQ 128
#define FBK 64
#define SQK 136                  // Q/K/V smem row stride (bf16): 272B ≡ 4 banks
#define SP  72                   // P smem row stride: 144B ≡ 4 banks
#define FLASH_SMEM ((2 * FBQ * SQK + 4 * FBK * SQK + 2 * FBQ * SP) * 2)

__global__ __launch_bounds__(256, 1)
void flash_mma_kernel(const int* __restrict__ is_causal_p)
{
    extern __shared__ __nv_bfloat16 fsm[];
    __nv_bfloat16* Qh = fsm;
    __nv_bfloat16* Ql = Qh + FBQ * SQK;
    __nv_bfloat16* Kh = Ql + FBQ * SQK;
    __nv_bfloat16* Kl = Kh + FBK * SQK;
    __nv_bfloat16* Vh = Kl + FBK * SQK;
    __nv_bfloat16* Vl = Vh + FBK * SQK;
    __nv_bfloat16* Ph = Vl + FBK * SQK;
    __nv_bfloat16* Pl = Ph + FBQ * SP;

    const int tid  = threadIdx.x;
    const int wid  = tid >> 5, lane = tid & 31;
    const int g    = lane >> 2, tig = lane & 3;
    const int qi   = (gridDim.x - 1) - blockIdx.x;
    const int h    = blockIdx.y, b = blockIdx.z;
    const int kh   = h >> 2;                        // GQA group
    const float scale = 0.08838834764831845f;

    const __nv_bfloat16* qgh = g_qh + ((size_t)(b * NHEAD + h) * SEQ + qi * FBQ) * DHEAD;
    const __nv_bfloat16* qgl = g_ql + ((size_t)(b * NHEAD + h) * SEQ + qi * FBQ) * DHEAD;
    const __nv_bfloat16* kgh = g_kh + (size_t)(b * NKV + kh) * SEQ * DHEAD;
    const __nv_bfloat16* kgl = g_kl + (size_t)(b * NKV + kh) * SEQ * DHEAD;
    const __nv_bfloat16* vgh = g_vh + (size_t)(b * NKV + kh) * SEQ * DHEAD;
    const __nv_bfloat16* vgl = g_vl + (size_t)(b * NKV + kh) * SEQ * DHEAD;

    // Load Q tiles (128x128 bf16 hi/lo)
    #pragma unroll
    for (int i = 0; i < 8; i++) {
        const int idx = i * 256 + tid;
        const int r = idx >> 4, c = (idx & 15) << 3;
        *(uint4*)&Qh[r * SQK + c] = *(const uint4*)&qgh[r * DHEAD + c];
        *(uint4*)&Ql[r * SQK + c] = *(const uint4*)&qgl[r * DHEAD + c];
    }

    const int causal = is_causal_p[0];
    const int nkt = causal ? (2 * qi + 2) : (SEQ / FBK);

    float oc[16][4];
    #pragma unroll
    for (int i = 0; i < 16; i++)
        #pragma unroll
        for (int c = 0; c < 4; c++) oc[i][c] = 0.f;
    float mrow[2] = {-1e30f, -1e30f}, lrow[2] = {0.f, 0.f};

    const uint32_t uQh = s2u(Qh), uQl = s2u(Ql), uKh = s2u(Kh), uKl = s2u(Kl);
    const uint32_t uVh = s2u(Vh), uVl = s2u(Vl), uPh = s2u(Ph), uPl = s2u(Pl);
    // A-operand base (Q): row wid*16 + lane%16, k-half chunk lane/16
    const uint32_t aQ = (uint32_t)((wid * 16 + (lane & 15)) * (SQK * 2) + ((lane >> 4) << 4));
    const uint32_t aP = (uint32_t)((wid * 16 + (lane & 15)) * (SP * 2) + ((lane >> 4) << 4));
    // B-operand (K, non-trans x4 covering n16): n-row, k-half
    const int brow = (lane & 7) + ((lane >> 4) << 3);
    const uint32_t bcol = ((lane >> 3) & 1) << 4;
    // B-operand (V, trans x4 covering k16 x n16): k-row, d-col
    const int vkrow = (lane & 7) + (((lane >> 3) & 1) << 3);
    const int vdcol = (lane >> 4) << 3;

    for (int kt = 0; kt < nkt; kt++) {
        __syncthreads();   // prior PV done reading K/V
        #pragma unroll
        for (int i = 0; i < 4; i++) {
            const int idx = i * 256 + tid;
            const int r = idx >> 4, c = (idx & 15) << 3;
            const size_t go = ((size_t)kt * FBK + r) * DHEAD + c;
            *(uint4*)&Kh[r * SQK + c] = *(const uint4*)&kgh[go];
            *(uint4*)&Kl[r * SQK + c] = *(const uint4*)&kgl[go];
            *(uint4*)&Vh[r * SQK + c] = *(const uint4*)&vgh[go];
            *(uint4*)&Vl[r * SQK + c] = *(const uint4*)&vgl[go];
        }
        __syncthreads();

        // ---- S = Q K^T (16x64 per warp), 3 passes --------------------------
        float sc[8][4];
        #pragma unroll
        for (int i = 0; i < 8; i++)
            #pragma unroll
            for (int c = 0; c < 4; c++) sc[i][c] = 0.f;

        #pragma unroll
        for (int ks = 0; ks < 8; ks++) {
            const uint32_t kb = ks * 32;
            uint32_t ah0, ah1, ah2, ah3, al0, al1, al2, al3;
            ldsm4(ah0, ah1, ah2, ah3, uQh + aQ + kb);
            ldsm4(al0, al1, al2, al3, uQl + aQ + kb);
            #pragma unroll
            for (int j = 0; j < 4; j++) {
                const uint32_t ro = (uint32_t)((j * 16 + brow) * (SQK * 2)) + bcol + kb;
                uint32_t bh0, bh1, bh2, bh3, bl0, bl1, bl2, bl3;
                ldsm4(bh0, bh1, bh2, bh3, uKh + ro);
                ldsm4(bl0, bl1, bl2, bl3, uKl + ro);
                mma16816(sc[2 * j],     ah0, ah1, ah2, ah3, bh0, bh1);
                mma16816(sc[2 * j],     ah0, ah1, ah2, ah3, bl0, bl1);
                mma16816(sc[2 * j],     al0, al1, al2, al3, bh0, bh1);
                mma16816(sc[2 * j + 1], ah0, ah1, ah2, ah3, bh2, bh3);
                mma16816(sc[2 * j + 1], ah0, ah1, ah2, ah3, bl2, bl3);
                mma16816(sc[2 * j + 1], al0, al1, al2, al3, bh2, bh3);
            }
        }

        // ---- scale + causal mask ------------------------------------------
        const int rowA = qi * FBQ + wid * 16 + g;
        const bool mb = causal && (kt >= 2 * qi);
        #pragma unroll
        for (int nf = 0; nf < 8; nf++)
            #pragma unroll
            for (int c = 0; c < 4; c++) {
                float v = sc[nf][c] * scale;
                if (mb) {
                    const int col = kt * FBK + nf * 8 + 2 * tig + (c & 1);
                    const int row = rowA + ((c >> 1) << 3);
                    if (col > row) v = -1e30f;
                }
                sc[nf][c] = v;
            }

        // ---- online softmax (2 rows per thread) ---------------------------
        #pragma unroll
        for (int half = 0; half < 2; half++) {
            float mx = -1e30f;
            #pragma unroll
            for (int nf = 0; nf < 8; nf++)
                mx = fmaxf(mx, fmaxf(sc[nf][half * 2], sc[nf][half * 2 + 1]));
            mx = fmaxf(mx, __shfl_xor_sync(0xffffffffu, mx, 1));
            mx = fmaxf(mx, __shfl_xor_sync(0xffffffffu, mx, 2));
            const float mnew  = fmaxf(mrow[half], mx);
            const float alpha = __expf(mrow[half] - mnew);
            float ps = 0.f;
            #pragma unroll
            for (int nf = 0; nf < 8; nf++) {
                const float p0 = __expf(sc[nf][half * 2]     - mnew);
                const float p1 = __expf(sc[nf][half * 2 + 1] - mnew);
                sc[nf][half * 2] = p0; sc[nf][half * 2 + 1] = p1;
                ps += p0 + p1;
            }
            ps += __shfl_xor_sync(0xffffffffu, ps, 1);
            ps += __shfl_xor_sync(0xffffffffu, ps, 2);
            lrow[half] = lrow[half] * alpha + ps;
            mrow[half] = mnew;
            #pragma unroll
            for (int i = 0; i < 16; i++) {
                oc[i][half * 2]     *= alpha;
                oc[i][half * 2 + 1] *= alpha;
            }
        }

        // ---- publish P as bf16 hi/lo (warp-local rows) --------------------
        #pragma unroll
        for (int nf = 0; nf < 8; nf++)
            #pragma unroll
            for (int half = 0; half < 2; half++) {
                __nv_bfloat162 hi, lo;
                split_pair(sc[nf][half * 2], sc[nf][half * 2 + 1], hi, lo);
                const int r = wid * 16 + g + half * 8;
                const int cc = nf * 8 + 2 * tig;
                *(__nv_bfloat162*)&Ph[r * SP + cc] = hi;
                *(__nv_bfloat162*)&Pl[r * SP + cc] = lo;
            }
        __syncwarp();

        // ---- O += P V (16x128 per warp), 3 passes -------------------------
        #pragma unroll
        for (int ks = 0; ks < 4; ks++) {
            const uint32_t kb = ks * 32;
            uint32_t ph0, ph1, ph2, ph3, pl0, pl1, pl2, pl3;
            ldsm4(ph0, ph1, ph2, ph3, uPh + aP + kb);
            ldsm4(pl0, pl1, pl2, pl3, uPl + aP + kb);
            #pragma unroll
            for (int j = 0; j < 8; j++) {
                const uint32_t vo = (uint32_t)((ks * 16 + vkrow) * (SQK * 2) + (j * 16 + vdcol) * 2);
                uint32_t vh0, vh1, vh2, vh3, vl0, vl1, vl2, vl3;
                ldsm4t(vh0, vh1, vh2, vh3, uVh + vo);
                ldsm4t(vl0, vl1, vl2, vl3, uVl + vo);
                mma16816(oc[2 * j],     ph0, ph1, ph2, ph3, vh0, vh1);
                mma16816(oc[2 * j],     ph0, ph1, ph2, ph3, vl0, vl1);
                mma16816(oc[2 * j],     pl0, pl1, pl2, pl3, vh0, vh1);
                mma16816(oc[2 * j + 1], ph0, ph1, ph2, ph3, vh2, vh3);
                mma16816(oc[2 * j + 1], ph0, ph1, ph2, ph3, vl2, vl3);
                mma16816(oc[2 * j + 1], pl0, pl1, pl2, pl3, vh2, vh3);
            }
        }
    }

    // ---- epilogue: normalize, split to bf16 hi/lo, store to g_aoh/g_aol ----
    const float inv0 = 1.0f / lrow[0], inv1 = 1.0f / lrow[1];
    const int row0 = b * SEQ + qi * FBQ + wid * 16 + g;
    const int cb   = h * DHEAD + 2 * tig;
    #pragma unroll
    for (int nfo = 0; nfo < 16; nfo++) {
        const int col = cb + nfo * 8;
        __nv_bfloat162 hi, lo;
        split_pair(oc[nfo][0] * inv0, oc[nfo][1] * inv0, hi, lo);
        *(__nv_bfloat162*)(g_aoh + (size_t)row0 * CMODEL + col) = hi;
        *(__nv_bfloat162*)(g_aol + (size_t)row0 * CMODEL + col) = lo;
        split_pair(oc[nfo][2] * inv1, oc[nfo][3] * inv1, hi, lo);
        *(__nv_bfloat162*)(g_aoh + (size_t)(row0 + 8) * CMODEL + col) = hi;
        *(__nv_bfloat162*)(g_aol + (size_t)(row0 + 8) * CMODEL + col) = lo;
    }
}

// ===========================================================================
// Launch
// ===========================================================================
extern "C" void kernel_launch(void* const* d_in, const int* in_sizes, int n_in,
                              void* d_out, int out_size)
{
    const float* x    = (const float*)d_in[0];
    const float* wq   = (const float*)d_in[1];
    const float* wk   = (const float*)d_in[2];
    const float* wv   = (const float*)d_in[3];
    const float* wo   = (const float*)d_in[4];
    const float* cosp = (const float*)d_in[5];
    const float* sinp = (const float*)d_in[6];
    const int*   isc  = (const int*)d_in[7];

    __nv_bfloat16 *xh, *xl, *wth, *wtl, *woth, *wotl, *aoh, *aol;
    cudaGetSymbolAddress((void**)&xh,  g_xh);   cudaGetSymbolAddress((void**)&xl,  g_xl);
    cudaGetSymbolAddress((void**)&wth, g_wth);  cudaGetSymbolAddress((void**)&wtl, g_wtl);
    cudaGetSymbolAddress((void**)&woth,g_woth); cudaGetSymbolAddress((void**)&wotl,g_wotl);
    cudaGetSymbolAddress((void**)&aoh, g_aoh);  cudaGetSymbolAddress((void**)&aol, g_aol);

    // 1) split x into bf16 hi/lo
    fsplit_kernel<<<(MROWS * CMODEL / 4 + 255) / 256, 256>>>(x, xh, xl, MROWS * CMODEL / 4);

    // 2) transpose+split weights
    dim3 tb(32, 8);
    tsplit_kernel<<<dim3(CMODEL / 32, CMODEL / 32), tb>>>(wq, CMODEL, wth, wtl, 0);
    tsplit_kernel<<<dim3(1024 / 32,   CMODEL / 32), tb>>>(wk, 1024,   wth, wtl, CMODEL);
    tsplit_kernel<<<dim3(1024 / 32,   CMODEL / 32), tb>>>(wv, 1024,   wth, wtl, CMODEL + 1024);
    tsplit_kernel<<<dim3(CMODEL / 32, CMODEL / 32), tb>>>(wo, CMODEL, woth, wotl, 0);

    // 3) QKV projection (HMMA) + RoPE + bf16 hi/lo q/k/v emit
    cudaFuncSetAttribute(gemm_mma<0>, cudaFuncAttributeMaxDynamicSharedMemorySize, GEMM_SMEM);
    gemm_mma<0><<<dim3(NQKV / 128, MROWS / 128), 256, GEMM_SMEM>>>(
        xh, xl, wth, wtl, cosp, sinp, nullptr);

    // 4) HMMA flash attention -> g_aoh/g_aol
    cudaFuncSetAttribute(flash_mma_kernel, cudaFuncAttributeMaxDynamicSharedMemorySize,
                         FLASH_SMEM);
    dim3 g2(SEQ / FBQ, NHEAD, BATCH);   // (16, 32, 2)
    flash_mma_kernel<<<g2, 256, FLASH_SMEM>>>(isc);

    // 5) output projection (HMMA)
    cudaFuncSetAttribute(gemm_mma<1>, cudaFuncAttributeMaxDynamicSharedMemorySize, GEMM_SMEM);
    gemm_mma<1><<<dim3(CMODEL / 128, MROWS / 128), 256, GEMM_SMEM>>>(
        aoh, aol, woth, wotl, nullptr, nullptr, (float*)d_out);
}

// round 6
// speedup vs baseline: 3.0382x; 1.0420x over previous
#include <cuda_runtime.h>
#include <cuda_bf16.h>
#include <cstdint>

#define BATCH   2
#define SEQ     2048
#define CMODEL  4096
#define NHEAD   32
#define DHEAD   128
#define NKV     8
#define GQA     4
#define MROWS   (BATCH * SEQ)
#define NQKV    (CMODEL + 2 * NKV * DHEAD)    // 6144

// ------------------------- device scratch (no allocs) ----------------------
__device__ __nv_bfloat16 g_qh[BATCH * NHEAD * SEQ * DHEAD];
__device__ __nv_bfloat16 g_ql[BATCH * NHEAD * SEQ * DHEAD];
__device__ __nv_bfloat16 g_kh[BATCH * NKV * SEQ * DHEAD];
__device__ __nv_bfloat16 g_kl[BATCH * NKV * SEQ * DHEAD];
__device__ __nv_bfloat16 g_vh[BATCH * NKV * SEQ * DHEAD];
__device__ __nv_bfloat16 g_vl[BATCH * NKV * SEQ * DHEAD];

__device__ __nv_bfloat16 g_xh [MROWS * CMODEL];
__device__ __nv_bfloat16 g_xl [MROWS * CMODEL];
__device__ __nv_bfloat16 g_wth[NQKV * CMODEL];
__device__ __nv_bfloat16 g_wtl[NQKV * CMODEL];
__device__ __nv_bfloat16 g_woth[CMODEL * CMODEL];
__device__ __nv_bfloat16 g_wotl[CMODEL * CMODEL];
__device__ __nv_bfloat16 g_aoh[MROWS * CMODEL];
__device__ __nv_bfloat16 g_aol[MROWS * CMODEL];

// ------------------------- PTX helpers --------------------------------------
__device__ __forceinline__ uint32_t s2u(const void* p) {
    uint32_t a;
    asm("{ .reg .u64 t; cvta.to.shared.u64 t, %1; cvt.u32.u64 %0, t; }" : "=r"(a) : "l"(p));
    return a;
}
__device__ __forceinline__ void cpa16(uint32_t dst, const void* src) {
    asm volatile("cp.async.ca.shared.global [%0], [%1], 16;" :: "r"(dst), "l"(src));
}
__device__ __forceinline__ void cpa_commit() {
    asm volatile("cp.async.commit_group;" ::: "memory");
}
__device__ __forceinline__ void cpa_wait1() {
    asm volatile("cp.async.wait_group 1;" ::: "memory");
}
__device__ __forceinline__ void cpa_wait0() {
    asm volatile("cp.async.wait_group 0;" ::: "memory");
}
__device__ __forceinline__ void ldsm4(uint32_t& r0, uint32_t& r1, uint32_t& r2, uint32_t& r3,
                                      uint32_t addr) {
    asm volatile("ldmatrix.sync.aligned.m8n8.x4.shared.b16 {%0,%1,%2,%3}, [%4];"
                 : "=r"(r0), "=r"(r1), "=r"(r2), "=r"(r3) : "r"(addr));
}
__device__ __forceinline__ void ldsm4t(uint32_t& r0, uint32_t& r1, uint32_t& r2, uint32_t& r3,
                                       uint32_t addr) {
    asm volatile("ldmatrix.sync.aligned.m8n8.x4.trans.shared.b16 {%0,%1,%2,%3}, [%4];"
                 : "=r"(r0), "=r"(r1), "=r"(r2), "=r"(r3) : "r"(addr));
}
__device__ __forceinline__ void ldsm2(uint32_t& r0, uint32_t& r1, uint32_t addr) {
    asm volatile("ldmatrix.sync.aligned.m8n8.x2.shared.b16 {%0,%1}, [%2];"
                 : "=r"(r0), "=r"(r1) : "r"(addr));
}
__device__ __forceinline__ void mma16816(float* c, uint32_t a0, uint32_t a1, uint32_t a2,
                                         uint32_t a3, uint32_t b0, uint32_t b1) {
    asm volatile("mma.sync.aligned.m16n8k16.row.col.f32.bf16.bf16.f32 "
                 "{%0,%1,%2,%3}, {%4,%5,%6,%7}, {%8,%9}, {%0,%1,%2,%3};"
                 : "+f"(c[0]), "+f"(c[1]), "+f"(c[2]), "+f"(c[3])
                 : "r"(a0), "r"(a1), "r"(a2), "r"(a3), "r"(b0), "r"(b1));
}
__device__ __forceinline__ void split_pair(float a, float b,
                                           __nv_bfloat162& hi, __nv_bfloat162& lo) {
    __nv_bfloat16 ha = __float2bfloat16(a), hb = __float2bfloat16(b);
    hi = __nv_bfloat162(ha, hb);
    lo = __nv_bfloat162(__float2bfloat16(a - __bfloat162float(ha)),
                        __float2bfloat16(b - __bfloat162float(hb)));
}

// ------------------------- conversion kernels -------------------------------
__global__ __launch_bounds__(256)
void fsplit_kernel(const float* __restrict__ s, __nv_bfloat16* __restrict__ dh,
                   __nv_bfloat16* __restrict__ dl, int n4) {
    int i = blockIdx.x * 256 + threadIdx.x;
    if (i >= n4) return;
    float4 v = ((const float4*)s)[i];
    __nv_bfloat162 h0, l0, h1, l1;
    split_pair(v.x, v.y, h0, l0);
    split_pair(v.z, v.w, h1, l1);
    ((__nv_bfloat162*)dh)[i * 2]     = h0;
    ((__nv_bfloat162*)dh)[i * 2 + 1] = h1;
    ((__nv_bfloat162*)dl)[i * 2]     = l0;
    ((__nv_bfloat162*)dl)[i * 2 + 1] = l1;
}

__global__ __launch_bounds__(256)
void tsplit_kernel(const float* __restrict__ src, int N,
                   __nv_bfloat16* __restrict__ dh, __nv_bfloat16* __restrict__ dl,
                   int row_off) {
    __shared__ float t[32][33];
    const int k0 = blockIdx.y * 32, n0 = blockIdx.x * 32;
    const int tx = threadIdx.x, ty = threadIdx.y;
    #pragma unroll
    for (int i = 0; i < 32; i += 8)
        t[ty + i][tx] = src[(size_t)(k0 + ty + i) * N + n0 + tx];
    __syncthreads();
    #pragma unroll
    for (int i = 0; i < 32; i += 8) {
        const int n = n0 + ty + i, k = k0 + tx;
        const float v = t[tx][ty + i];
        const __nv_bfloat16 h = __float2bfloat16(v);
        dh[(size_t)(row_off + n) * CMODEL + k] = h;
        dl[(size_t)(row_off + n) * CMODEL + k] = __float2bfloat16(v - __bfloat162float(h));
    }
}

// ------------------------- split-bf16 HMMA GEMM, 2-stage cp.async pipeline --
#define BKH 64
#define LDA 72
#define TILE_SM (128 * LDA)                 // bf16 per tile
#define STAGE_SM (4 * TILE_SM)              // 4 tiles (Ah, Al, Bh, Bl)
#define GEMM_SMEM (2 * STAGE_SM * 2)        // 147456 B

__device__ __forceinline__ void load_tile_async(const __nv_bfloat16* __restrict__ g,
                                                int row0, int col0, uint32_t sdst, int tid) {
    const char* gp = (const char*)(g + (size_t)row0 * CMODEL + col0);
    #pragma unroll
    for (int i = 0; i < 4; i++) {
        const int idx = i * 256 + tid;
        const int r = idx >> 3, cb = (idx & 7) << 4;
        cpa16(sdst + (uint32_t)(r * (LDA * 2) + cb), gp + (size_t)r * (CMODEL * 2) + cb);
    }
}

template<int MODE>
__global__ __launch_bounds__(256)
void gemm_mma(const __nv_bfloat16* __restrict__ Ah, const __nv_bfloat16* __restrict__ Al,
              const __nv_bfloat16* __restrict__ Bh, const __nv_bfloat16* __restrict__ Bl,
              const float* __restrict__ cosp, const float* __restrict__ sinp,
              float* __restrict__ outp)
{
    extern __shared__ __nv_bfloat16 sm[];
    const uint32_t base = s2u(sm);

    const int tid  = threadIdx.x;
    const int wid  = tid >> 5, lane = tid & 31;
    const int wm   = wid >> 2;
    const int wn   = wid & 3;
    const int n0   = blockIdx.x * 128, m0 = blockIdx.y * 128;

    float acc[4][4][4];
    #pragma unroll
    for (int i = 0; i < 4; i++)
        #pragma unroll
        for (int j = 0; j < 4; j++)
            #pragma unroll
            for (int c = 0; c < 4; c++) acc[i][j][c] = 0.f;

    const uint32_t aOff = (uint32_t)((wm * 64 + (lane & 15)) * (LDA * 2) + (lane >> 4) * 16);
    const uint32_t bOff = (uint32_t)((wn * 32 + (lane & 7)) * (LDA * 2) + ((lane & 15) >> 3) * 16);

    // prologue: stage 0
    {
        const uint32_t s0 = base;
        load_tile_async(Ah, m0, 0, s0 + 0 * TILE_SM * 2, tid);
        load_tile_async(Al, m0, 0, s0 + 1 * TILE_SM * 2, tid);
        load_tile_async(Bh, n0, 0, s0 + 2 * TILE_SM * 2, tid);
        load_tile_async(Bl, n0, 0, s0 + 3 * TILE_SM * 2, tid);
        cpa_commit();
    }

    const int NIT = CMODEL / BKH;   // 64
    for (int it = 0; it < NIT; it++) {
        // issue next chunk into the other stage (empty commit keeps group count)
        if (it + 1 < NIT) {
            const uint32_t sn = base + ((it + 1) & 1) * STAGE_SM * 2;
            const int kc = (it + 1) * BKH;
            load_tile_async(Ah, m0, kc, sn + 0 * TILE_SM * 2, tid);
            load_tile_async(Al, m0, kc, sn + 1 * TILE_SM * 2, tid);
            load_tile_async(Bh, n0, kc, sn + 2 * TILE_SM * 2, tid);
            load_tile_async(Bl, n0, kc, sn + 3 * TILE_SM * 2, tid);
        }
        cpa_commit();
        cpa_wait1();          // oldest group (current stage) complete
        __syncthreads();

        const uint32_t sc = base + (it & 1) * STAGE_SM * 2;
        const uint32_t uAh = sc, uAl = sc + TILE_SM * 2;
        const uint32_t uBh = sc + 2 * TILE_SM * 2, uBl = sc + 3 * TILE_SM * 2;

        #pragma unroll
        for (int ks = 0; ks < 4; ks++) {
            const uint32_t kb = ks * 32;
            uint32_t ah[4][4], al[4][4], bh[4][2], bl[4][2];
            #pragma unroll
            for (int mf = 0; mf < 4; mf++) {
                ldsm4(ah[mf][0], ah[mf][1], ah[mf][2], ah[mf][3],
                      uAh + aOff + mf * (16 * LDA * 2) + kb);
                ldsm4(al[mf][0], al[mf][1], al[mf][2], al[mf][3],
                      uAl + aOff + mf * (16 * LDA * 2) + kb);
            }
            #pragma unroll
            for (int nf = 0; nf < 4; nf++) {
                ldsm2(bh[nf][0], bh[nf][1], uBh + bOff + nf * (8 * LDA * 2) + kb);
                ldsm2(bl[nf][0], bl[nf][1], uBl + bOff + nf * (8 * LDA * 2) + kb);
            }
            #pragma unroll
            for (int mf = 0; mf < 4; mf++)
                #pragma unroll
                for (int nf = 0; nf < 4; nf++) {
                    mma16816(acc[mf][nf], ah[mf][0], ah[mf][1], ah[mf][2], ah[mf][3],
                             bh[nf][0], bh[nf][1]);
                    mma16816(acc[mf][nf], ah[mf][0], ah[mf][1], ah[mf][2], ah[mf][3],
                             bl[nf][0], bl[nf][1]);
                    mma16816(acc[mf][nf], al[mf][0], al[mf][1], al[mf][2], al[mf][3],
                             bh[nf][0], bh[nf][1]);
                }
        }
        __syncthreads();     // all warps done with this stage before it is refilled
    }

    const int group = lane >> 2, tig = lane & 3;

    if (MODE == 0) {
        __nv_bfloat16 *bph, *bpl; int head, roped, nh;
        if (n0 < CMODEL) {
            bph = g_qh; bpl = g_ql; head = n0 >> 7; roped = 1; nh = NHEAD;
        } else if (n0 < CMODEL + 1024) {
            bph = g_kh; bpl = g_kl; head = (n0 - CMODEL) >> 7; roped = 1; nh = NKV;
        } else {
            bph = g_vh; bpl = g_vl; head = (n0 - CMODEL - 1024) >> 7; roped = 0; nh = NKV;
        }
        #pragma unroll
        for (int mf = 0; mf < 4; mf++) {
            #pragma unroll
            for (int nf = 0; nf < 4; nf++) {
                const int d = wn * 32 + nf * 8 + tig * 2;
                #pragma unroll
                for (int half = 0; half < 2; half++) {
                    const int row = m0 + wm * 64 + mf * 16 + group + half * 8;
                    const int bb = row >> 11, tt = row & (SEQ - 1);
                    float e = acc[mf][nf][half * 2], o = acc[mf][nf][half * 2 + 1];
                    if (roped) {
                        const float ct = cosp[tt * DHEAD + d];
                        const float st = sinp[tt * DHEAD + d];
                        const float ne = e * ct - o * st;
                        o = e * st + o * ct;
                        e = ne;
                    }
                    __nv_bfloat162 hi, lo;
                    split_pair(e, o, hi, lo);
                    const size_t off = ((size_t)(bb * nh + head) * SEQ + tt) * DHEAD + d;
                    *(__nv_bfloat162*)(bph + off) = hi;
                    *(__nv_bfloat162*)(bpl + off) = lo;
                }
            }
        }
    } else {
        #pragma unroll
        for (int mf = 0; mf < 4; mf++) {
            #pragma unroll
            for (int nf = 0; nf < 4; nf++) {
                const int d = wn * 32 + nf * 8 + tig * 2;
                #pragma unroll
                for (int half = 0; half < 2; half++) {
                    const int row = m0 + wm * 64 + mf * 16 + group + half * 8;
                    float* dst = outp + (size_t)row * CMODEL + n0 + d;
                    *(float2*)dst = make_float2(acc[mf][nf][half * 2], acc[mf][nf][half * 2 + 1]);
                }
            }
        }
    }
}

// ===========================================================================
// HMMA flash attention: BQ=128, BKV=64, 8 warps, split-bf16 3-pass QK and PV
// ===========================================================================
#define FBQ 128
#define FBK 64
#define SQK 136
#define SP  72
#define FLASH_SMEM ((2 * FBQ * SQK + 4 * FBK * SQK + 2 * FBQ * SP) * 2)

__global__ __launch_bounds__(256, 1)
void flash_mma_kernel(const int* __restrict__ is_causal_p)
{
    extern __shared__ __nv_bfloat16 fsm[];
    __nv_bfloat16* Qh = fsm;
    __nv_bfloat16* Ql = Qh + FBQ * SQK;
    __nv_bfloat16* Kh = Ql + FBQ * SQK;
    __nv_bfloat16* Kl = Kh + FBK * SQK;
    __nv_bfloat16* Vh = Kl + FBK * SQK;
    __nv_bfloat16* Vl = Vh + FBK * SQK;
    __nv_bfloat16* Ph = Vl + FBK * SQK;
    __nv_bfloat16* Pl = Ph + FBQ * SP;

    const int tid  = threadIdx.x;
    const int wid  = tid >> 5, lane = tid & 31;
    const int g    = lane >> 2, tig = lane & 3;
    const int qi   = (gridDim.x - 1) - blockIdx.x;
    const int h    = blockIdx.y, b = blockIdx.z;
    const int kh   = h >> 2;
    const float scale = 0.08838834764831845f;

    const __nv_bfloat16* qgh = g_qh + ((size_t)(b * NHEAD + h) * SEQ + qi * FBQ) * DHEAD;
    const __nv_bfloat16* qgl = g_ql + ((size_t)(b * NHEAD + h) * SEQ + qi * FBQ) * DHEAD;
    const __nv_bfloat16* kgh = g_kh + (size_t)(b * NKV + kh) * SEQ * DHEAD;
    const __nv_bfloat16* kgl = g_kl + (size_t)(b * NKV + kh) * SEQ * DHEAD;
    const __nv_bfloat16* vgh = g_vh + (size_t)(b * NKV + kh) * SEQ * DHEAD;
    const __nv_bfloat16* vgl = g_vl + (size_t)(b * NKV + kh) * SEQ * DHEAD;

    const uint32_t uQh = s2u(Qh), uQl = s2u(Ql), uKh = s2u(Kh), uKl = s2u(Kl);
    const uint32_t uVh = s2u(Vh), uVl = s2u(Vl), uPh = s2u(Ph), uPl = s2u(Pl);

    // Load Q tiles via cp.async
    #pragma unroll
    for (int i = 0; i < 8; i++) {
        const int idx = i * 256 + tid;
        const int r = idx >> 4, c = (idx & 15) << 3;
        cpa16(uQh + (uint32_t)(r * SQK + c) * 2, qgh + (size_t)r * DHEAD + c);
        cpa16(uQl + (uint32_t)(r * SQK + c) * 2, qgl + (size_t)r * DHEAD + c);
    }
    cpa_commit();

    const int causal = is_causal_p[0];
    const int nkt = causal ? (2 * qi + 2) : (SEQ / FBK);

    float oc[16][4];
    #pragma unroll
    for (int i = 0; i < 16; i++)
        #pragma unroll
        for (int c = 0; c < 4; c++) oc[i][c] = 0.f;
    float mrow[2] = {-1e30f, -1e30f}, lrow[2] = {0.f, 0.f};

    const uint32_t aQ = (uint32_t)((wid * 16 + (lane & 15)) * (SQK * 2) + ((lane >> 4) << 4));
    const uint32_t aP = (uint32_t)((wid * 16 + (lane & 15)) * (SP * 2) + ((lane >> 4) << 4));
    const int brow = (lane & 7) + ((lane >> 4) << 3);
    const uint32_t bcol = ((lane >> 3) & 1) << 4;
    const int vkrow = (lane & 7) + (((lane >> 3) & 1) << 3);
    const int vdcol = (lane >> 4) << 3;

    for (int kt = 0; kt < nkt; kt++) {
        __syncthreads();   // prior iteration done reading K/V
        #pragma unroll
        for (int i = 0; i < 4; i++) {
            const int idx = i * 256 + tid;
            const int r = idx >> 4, c = (idx & 15) << 3;
            const size_t go = ((size_t)kt * FBK + r) * DHEAD + c;
            const uint32_t so = (uint32_t)(r * SQK + c) * 2;
            cpa16(uKh + so, kgh + go);
            cpa16(uKl + so, kgl + go);
            cpa16(uVh + so, vgh + go);
            cpa16(uVl + so, vgl + go);
        }
        cpa_commit();
        cpa_wait0();
        __syncthreads();

        // ---- S = Q K^T ----------------------------------------------------
        float sc[8][4];
        #pragma unroll
        for (int i = 0; i < 8; i++)
            #pragma unroll
            for (int c = 0; c < 4; c++) sc[i][c] = 0.f;

        #pragma unroll
        for (int ks = 0; ks < 8; ks++) {
            const uint32_t kb = ks * 32;
            uint32_t ah0, ah1, ah2, ah3, al0, al1, al2, al3;
            ldsm4(ah0, ah1, ah2, ah3, uQh + aQ + kb);
            ldsm4(al0, al1, al2, al3, uQl + aQ + kb);
            #pragma unroll
            for (int j = 0; j < 4; j++) {
                const uint32_t ro = (uint32_t)((j * 16 + brow) * (SQK * 2)) + bcol + kb;
                uint32_t bh0, bh1, bh2, bh3, bl0, bl1, bl2, bl3;
                ldsm4(bh0, bh1, bh2, bh3, uKh + ro);
                ldsm4(bl0, bl1, bl2, bl3, uKl + ro);
                mma16816(sc[2 * j],     ah0, ah1, ah2, ah3, bh0, bh1);
                mma16816(sc[2 * j],     ah0, ah1, ah2, ah3, bl0, bl1);
                mma16816(sc[2 * j],     al0, al1, al2, al3, bh0, bh1);
                mma16816(sc[2 * j + 1], ah0, ah1, ah2, ah3, bh2, bh3);
                mma16816(sc[2 * j + 1], ah0, ah1, ah2, ah3, bl2, bl3);
                mma16816(sc[2 * j + 1], al0, al1, al2, al3, bh2, bh3);
            }
        }

        // ---- scale + causal mask ------------------------------------------
        const int rowA = qi * FBQ + wid * 16 + g;
        const bool mb = causal && (kt >= 2 * qi);
        #pragma unroll
        for (int nf = 0; nf < 8; nf++)
            #pragma unroll
            for (int c = 0; c < 4; c++) {
                float v = sc[nf][c] * scale;
                if (mb) {
                    const int col = kt * FBK + nf * 8 + 2 * tig + (c & 1);
                    const int row = rowA + ((c >> 1) << 3);
                    if (col > row) v = -1e30f;
                }
                sc[nf][c] = v;
            }

        // ---- online softmax -----------------------------------------------
        #pragma unroll
        for (int half = 0; half < 2; half++) {
            float mx = -1e30f;
            #pragma unroll
            for (int nf = 0; nf < 8; nf++)
                mx = fmaxf(mx, fmaxf(sc[nf][half * 2], sc[nf][half * 2 + 1]));
            mx = fmaxf(mx, __shfl_xor_sync(0xffffffffu, mx, 1));
            mx = fmaxf(mx, __shfl_xor_sync(0xffffffffu, mx, 2));
            const float mnew  = fmaxf(mrow[half], mx);
            const float alpha = __expf(mrow[half] - mnew);
            float ps = 0.f;
            #pragma unroll
            for (int nf = 0; nf < 8; nf++) {
                const float p0 = __expf(sc[nf][half * 2]     - mnew);
                const float p1 = __expf(sc[nf][half * 2 + 1] - mnew);
                sc[nf][half * 2] = p0; sc[nf][half * 2 + 1] = p1;
                ps += p0 + p1;
            }
            ps += __shfl_xor_sync(0xffffffffu, ps, 1);
            ps += __shfl_xor_sync(0xffffffffu, ps, 2);
            lrow[half] = lrow[half] * alpha + ps;
            mrow[half] = mnew;
            #pragma unroll
            for (int i = 0; i < 16; i++) {
                oc[i][half * 2]     *= alpha;
                oc[i][half * 2 + 1] *= alpha;
            }
        }

        // ---- publish P ----------------------------------------------------
        #pragma unroll
        for (int nf = 0; nf < 8; nf++)
            #pragma unroll
            for (int half = 0; half < 2; half++) {
                __nv_bfloat162 hi, lo;
                split_pair(sc[nf][half * 2], sc[nf][half * 2 + 1], hi, lo);
                const int r = wid * 16 + g + half * 8;
                const int cc = nf * 8 + 2 * tig;
                *(__nv_bfloat162*)&Ph[r * SP + cc] = hi;
                *(__nv_bfloat162*)&Pl[r * SP + cc] = lo;
            }
        __syncwarp();

        // ---- O += P V -----------------------------------------------------
        #pragma unroll
        for (int ks = 0; ks < 4; ks++) {
            const uint32_t kb = ks * 32;
            uint32_t ph0, ph1, ph2, ph3, pl0, pl1, pl2, pl3;
            ldsm4(ph0, ph1, ph2, ph3, uPh + aP + kb);
            ldsm4(pl0, pl1, pl2, pl3, uPl + aP + kb);
            #pragma unroll
            for (int j = 0; j < 8; j++) {
                const uint32_t vo = (uint32_t)((ks * 16 + vkrow) * (SQK * 2) + (j * 16 + vdcol) * 2);
                uint32_t vh0, vh1, vh2, vh3, vl0, vl1, vl2, vl3;
                ldsm4t(vh0, vh1, vh2, vh3, uVh + vo);
                ldsm4t(vl0, vl1, vl2, vl3, uVl + vo);
                mma16816(oc[2 * j],     ph0, ph1, ph2, ph3, vh0, vh1);
                mma16816(oc[2 * j],     ph0, ph1, ph2, ph3, vl0, vl1);
                mma16816(oc[2 * j],     pl0, pl1, pl2, pl3, vh0, vh1);
                mma16816(oc[2 * j + 1], ph0, ph1, ph2, ph3, vh2, vh3);
                mma16816(oc[2 * j + 1], ph0, ph1, ph2, ph3, vl2, vl3);
                mma16816(oc[2 * j + 1], pl0, pl1, pl2, pl3, vh2, vh3);
            }
        }
    }

    // ---- epilogue ----------------------------------------------------------
    const float inv0 = 1.0f / lrow[0], inv1 = 1.0f / lrow[1];
    const int row0 = b * SEQ + qi * FBQ + wid * 16 + g;
    const int cb   = h * DHEAD + 2 * tig;
    #pragma unroll
    for (int nfo = 0; nfo < 16; nfo++) {
        const int col = cb + nfo * 8;
        __nv_bfloat162 hi, lo;
        split_pair(oc[nfo][0] * inv0, oc[nfo][1] * inv0, hi, lo);
        *(__nv_bfloat162*)(g_aoh + (size_t)row0 * CMODEL + col) = hi;
        *(__nv_bfloat162*)(g_aol + (size_t)row0 * CMODEL + col) = lo;
        split_pair(oc[nfo][2] * inv1, oc[nfo][3] * inv1, hi, lo);
        *(__nv_bfloat162*)(g_aoh + (size_t)(row0 + 8) * CMODEL + col) = hi;
        *(__nv_bfloat162*)(g_aol + (size_t)(row0 + 8) * CMODEL + col) = lo;
    }
}

// ===========================================================================
// Launch
// ===========================================================================
extern "C" void kernel_launch(void* const* d_in, const int* in_sizes, int n_in,
                              void* d_out, int out_size)
{
    const float* x    = (const float*)d_in[0];
    const float* wq   = (const float*)d_in[1];
    const float* wk   = (const float*)d_in[2];
    const float* wv   = (const float*)d_in[3];
    const float* wo   = (const float*)d_in[4];
    const float* cosp = (const float*)d_in[5];
    const float* sinp = (const float*)d_in[6];
    const int*   isc  = (const int*)d_in[7];

    __nv_bfloat16 *xh, *xl, *wth, *wtl, *woth, *wotl, *aoh, *aol;
    cudaGetSymbolAddress((void**)&xh,  g_xh);   cudaGetSymbolAddress((void**)&xl,  g_xl);
    cudaGetSymbolAddress((void**)&wth, g_wth);  cudaGetSymbolAddress((void**)&wtl, g_wtl);
    cudaGetSymbolAddress((void**)&woth,g_woth); cudaGetSymbolAddress((void**)&wotl,g_wotl);
    cudaGetSymbolAddress((void**)&aoh, g_aoh);  cudaGetSymbolAddress((void**)&aol, g_aol);

    // 1) split x into bf16 hi/lo
    fsplit_kernel<<<(MROWS * CMODEL / 4 + 255) / 256, 256>>>(x, xh, xl, MROWS * CMODEL / 4);

    // 2) transpose+split weights
    dim3 tb(32, 8);
    tsplit_kernel<<<dim3(CMODEL / 32, CMODEL / 32), tb>>>(wq, CMODEL, wth, wtl, 0);
    tsplit_kernel<<<dim3(1024 / 32,   CMODEL / 32), tb>>>(wk, 1024,   wth, wtl, CMODEL);
    tsplit_kernel<<<dim3(1024 / 32,   CMODEL / 32), tb>>>(wv, 1024,   wth, wtl, CMODEL + 1024);
    tsplit_kernel<<<dim3(CMODEL / 32, CMODEL / 32), tb>>>(wo, CMODEL, woth, wotl, 0);

    // 3) QKV projection (HMMA, cp.async pipelined) + RoPE + bf16 hi/lo emit
    cudaFuncSetAttribute(gemm_mma<0>, cudaFuncAttributeMaxDynamicSharedMemorySize, GEMM_SMEM);
    gemm_mma<0><<<dim3(NQKV / 128, MROWS / 128), 256, GEMM_SMEM>>>(
        xh, xl, wth, wtl, cosp, sinp, nullptr);

    // 4) HMMA flash attention -> g_aoh/g_aol
    cudaFuncSetAttribute(flash_mma_kernel, cudaFuncAttributeMaxDynamicSharedMemorySize,
                         FLASH_SMEM);
    dim3 g2(SEQ / FBQ, NHEAD, BATCH);
    flash_mma_kernel<<<g2, 256, FLASH_SMEM>>>(isc);

    // 5) output projection (HMMA, cp.async pipelined)
    cudaFuncSetAttribute(gemm_mma<1>, cudaFuncAttributeMaxDynamicSharedMemorySize, GEMM_SMEM);
    gemm_mma<1><<<dim3(CMODEL / 128, MROWS / 128), 256, GEMM_SMEM>>>(
        aoh, aol, woth, wotl, nullptr, nullptr, (float*)d_out);
}

// round 7
// speedup vs baseline: 3.7423x; 1.2317x over previous
#include <cuda_runtime.h>
#include <cuda_bf16.h>
#include <cuda_fp16.h>
#include <cstdint>

#define BATCH   2
#define SEQ     2048
#define CMODEL  4096
#define NHEAD   32
#define DHEAD   128
#define NKV     8
#define GQA     4
#define MROWS   (BATCH * SEQ)
#define NQKV    (CMODEL + 2 * NKV * DHEAD)    // 6144

// ------------------------- device scratch (no allocs) ----------------------
__device__ __nv_bfloat16 g_qh[BATCH * NHEAD * SEQ * DHEAD];
__device__ __nv_bfloat16 g_ql[BATCH * NHEAD * SEQ * DHEAD];
__device__ __nv_bfloat16 g_kh[BATCH * NKV * SEQ * DHEAD];
__device__ __nv_bfloat16 g_kl[BATCH * NKV * SEQ * DHEAD];
__device__ __nv_bfloat16 g_vh[BATCH * NKV * SEQ * DHEAD];
__device__ __nv_bfloat16 g_vl[BATCH * NKV * SEQ * DHEAD];

__device__ __nv_bfloat16 g_xh [MROWS * CMODEL];
__device__ __nv_bfloat16 g_xl [MROWS * CMODEL];
__device__ __nv_bfloat16 g_wth[NQKV * CMODEL];
__device__ __nv_bfloat16 g_wtl[NQKV * CMODEL];

__device__ __half g_wotH[CMODEL * CMODEL];   // wo transposed, fp16
__device__ __half g_aoF [MROWS * CMODEL];    // attention output, fp16

// ------------------------- PTX helpers --------------------------------------
__device__ __forceinline__ uint32_t s2u(const void* p) {
    uint32_t a;
    asm("{ .reg .u64 t; cvta.to.shared.u64 t, %1; cvt.u32.u64 %0, t; }" : "=r"(a) : "l"(p));
    return a;
}
__device__ __forceinline__ void cpa16(uint32_t dst, const void* src) {
    asm volatile("cp.async.ca.shared.global [%0], [%1], 16;" :: "r"(dst), "l"(src));
}
__device__ __forceinline__ void cpa_commit() {
    asm volatile("cp.async.commit_group;" ::: "memory");
}
__device__ __forceinline__ void cpa_wait1() {
    asm volatile("cp.async.wait_group 1;" ::: "memory");
}
__device__ __forceinline__ void cpa_wait0() {
    asm volatile("cp.async.wait_group 0;" ::: "memory");
}
__device__ __forceinline__ void ldsm4(uint32_t& r0, uint32_t& r1, uint32_t& r2, uint32_t& r3,
                                      uint32_t addr) {
    asm volatile("ldmatrix.sync.aligned.m8n8.x4.shared.b16 {%0,%1,%2,%3}, [%4];"
                 : "=r"(r0), "=r"(r1), "=r"(r2), "=r"(r3) : "r"(addr));
}
__device__ __forceinline__ void ldsm4t(uint32_t& r0, uint32_t& r1, uint32_t& r2, uint32_t& r3,
                                       uint32_t addr) {
    asm volatile("ldmatrix.sync.aligned.m8n8.x4.trans.shared.b16 {%0,%1,%2,%3}, [%4];"
                 : "=r"(r0), "=r"(r1), "=r"(r2), "=r"(r3) : "r"(addr));
}
__device__ __forceinline__ void ldsm2(uint32_t& r0, uint32_t& r1, uint32_t addr) {
    asm volatile("ldmatrix.sync.aligned.m8n8.x2.shared.b16 {%0,%1}, [%2];"
                 : "=r"(r0), "=r"(r1) : "r"(addr));
}
__device__ __forceinline__ void mma16816(float* c, uint32_t a0, uint32_t a1, uint32_t a2,
                                         uint32_t a3, uint32_t b0, uint32_t b1) {
    asm volatile("mma.sync.aligned.m16n8k16.row.col.f32.bf16.bf16.f32 "
                 "{%0,%1,%2,%3}, {%4,%5,%6,%7}, {%8,%9}, {%0,%1,%2,%3};"
                 : "+f"(c[0]), "+f"(c[1]), "+f"(c[2]), "+f"(c[3])
                 : "r"(a0), "r"(a1), "r"(a2), "r"(a3), "r"(b0), "r"(b1));
}
__device__ __forceinline__ void mma16816h(float* c, uint32_t a0, uint32_t a1, uint32_t a2,
                                          uint32_t a3, uint32_t b0, uint32_t b1) {
    asm volatile("mma.sync.aligned.m16n8k16.row.col.f32.f16.f16.f32 "
                 "{%0,%1,%2,%3}, {%4,%5,%6,%7}, {%8,%9}, {%0,%1,%2,%3};"
                 : "+f"(c[0]), "+f"(c[1]), "+f"(c[2]), "+f"(c[3])
                 : "r"(a0), "r"(a1), "r"(a2), "r"(a3), "r"(b0), "r"(b1));
}
__device__ __forceinline__ void split_pair(float a, float b,
                                           __nv_bfloat162& hi, __nv_bfloat162& lo) {
    __nv_bfloat16 ha = __float2bfloat16(a), hb = __float2bfloat16(b);
    hi = __nv_bfloat162(ha, hb);
    lo = __nv_bfloat162(__float2bfloat16(a - __bfloat162float(ha)),
                        __float2bfloat16(b - __bfloat162float(hb)));
}

// ------------------------- conversion kernels -------------------------------
__global__ __launch_bounds__(256)
void fsplit_kernel(const float* __restrict__ s, __nv_bfloat16* __restrict__ dh,
                   __nv_bfloat16* __restrict__ dl, int n4) {
    int i = blockIdx.x * 256 + threadIdx.x;
    if (i >= n4) return;
    float4 v = ((const float4*)s)[i];
    __nv_bfloat162 h0, l0, h1, l1;
    split_pair(v.x, v.y, h0, l0);
    split_pair(v.z, v.w, h1, l1);
    ((__nv_bfloat162*)dh)[i * 2]     = h0;
    ((__nv_bfloat162*)dh)[i * 2 + 1] = h1;
    ((__nv_bfloat162*)dl)[i * 2]     = l0;
    ((__nv_bfloat162*)dl)[i * 2 + 1] = l1;
}

__global__ __launch_bounds__(256)
void tsplit_kernel(const float* __restrict__ src, int N,
                   __nv_bfloat16* __restrict__ dh, __nv_bfloat16* __restrict__ dl,
                   int row_off) {
    __shared__ float t[32][33];
    const int k0 = blockIdx.y * 32, n0 = blockIdx.x * 32;
    const int tx = threadIdx.x, ty = threadIdx.y;
    #pragma unroll
    for (int i = 0; i < 32; i += 8)
        t[ty + i][tx] = src[(size_t)(k0 + ty + i) * N + n0 + tx];
    __syncthreads();
    #pragma unroll
    for (int i = 0; i < 32; i += 8) {
        const int n = n0 + ty + i, k = k0 + tx;
        const float v = t[tx][ty + i];
        const __nv_bfloat16 h = __float2bfloat16(v);
        dh[(size_t)(row_off + n) * CMODEL + k] = h;
        dl[(size_t)(row_off + n) * CMODEL + k] = __float2bfloat16(v - __bfloat162float(h));
    }
}

// transpose wo [K][N] fp32 -> [N][K] fp16
__global__ __launch_bounds__(256)
void thalf_kernel(const float* __restrict__ src, __half* __restrict__ dst) {
    __shared__ float t[32][33];
    const int k0 = blockIdx.y * 32, n0 = blockIdx.x * 32;
    const int tx = threadIdx.x, ty = threadIdx.y;
    #pragma unroll
    for (int i = 0; i < 32; i += 8)
        t[ty + i][tx] = src[(size_t)(k0 + ty + i) * CMODEL + n0 + tx];
    __syncthreads();
    #pragma unroll
    for (int i = 0; i < 32; i += 8)
        dst[(size_t)(n0 + ty + i) * CMODEL + k0 + tx] = __float2half(t[tx][ty + i]);
}

// ------------------------- split-bf16 HMMA GEMM (QKV, round-6 proven) -------
#define BKH 64
#define LDA 72
#define TILE_SM (128 * LDA)
#define STAGE_SM (4 * TILE_SM)
#define GEMM_SMEM (2 * STAGE_SM * 2)        // 147456 B

__device__ __forceinline__ void load_tile_async(const __nv_bfloat16* __restrict__ g,
                                                int row0, int col0, uint32_t sdst, int tid) {
    const char* gp = (const char*)(g + (size_t)row0 * CMODEL + col0);
    #pragma unroll
    for (int i = 0; i < 4; i++) {
        const int idx = i * 256 + tid;
        const int r = idx >> 3, cb = (idx & 7) << 4;
        cpa16(sdst + (uint32_t)(r * (LDA * 2) + cb), gp + (size_t)r * (CMODEL * 2) + cb);
    }
}

__global__ __launch_bounds__(256)
void gemm_qkv(const __nv_bfloat16* __restrict__ Ah, const __nv_bfloat16* __restrict__ Al,
              const __nv_bfloat16* __restrict__ Bh, const __nv_bfloat16* __restrict__ Bl,
              const float* __restrict__ cosp, const float* __restrict__ sinp)
{
    extern __shared__ __nv_bfloat16 sm[];
    const uint32_t base = s2u(sm);

    const int tid  = threadIdx.x;
    const int wid  = tid >> 5, lane = tid & 31;
    const int wm   = wid >> 2;
    const int wn   = wid & 3;
    const int n0   = blockIdx.x * 128, m0 = blockIdx.y * 128;

    float acc[4][4][4];
    #pragma unroll
    for (int i = 0; i < 4; i++)
        #pragma unroll
        for (int j = 0; j < 4; j++)
            #pragma unroll
            for (int c = 0; c < 4; c++) acc[i][j][c] = 0.f;

    const uint32_t aOff = (uint32_t)((wm * 64 + (lane & 15)) * (LDA * 2) + (lane >> 4) * 16);
    const uint32_t bOff = (uint32_t)((wn * 32 + (lane & 7)) * (LDA * 2) + ((lane & 15) >> 3) * 16);

    {
        const uint32_t s0 = base;
        load_tile_async(Ah, m0, 0, s0 + 0 * TILE_SM * 2, tid);
        load_tile_async(Al, m0, 0, s0 + 1 * TILE_SM * 2, tid);
        load_tile_async(Bh, n0, 0, s0 + 2 * TILE_SM * 2, tid);
        load_tile_async(Bl, n0, 0, s0 + 3 * TILE_SM * 2, tid);
        cpa_commit();
    }

    const int NIT = CMODEL / BKH;
    for (int it = 0; it < NIT; it++) {
        if (it + 1 < NIT) {
            const uint32_t sn = base + ((it + 1) & 1) * STAGE_SM * 2;
            const int kc = (it + 1) * BKH;
            load_tile_async(Ah, m0, kc, sn + 0 * TILE_SM * 2, tid);
            load_tile_async(Al, m0, kc, sn + 1 * TILE_SM * 2, tid);
            load_tile_async(Bh, n0, kc, sn + 2 * TILE_SM * 2, tid);
            load_tile_async(Bl, n0, kc, sn + 3 * TILE_SM * 2, tid);
        }
        cpa_commit();
        cpa_wait1();
        __syncthreads();

        const uint32_t sc = base + (it & 1) * STAGE_SM * 2;
        const uint32_t uAh = sc, uAl = sc + TILE_SM * 2;
        const uint32_t uBh = sc + 2 * TILE_SM * 2, uBl = sc + 3 * TILE_SM * 2;

        #pragma unroll
        for (int ks = 0; ks < 4; ks++) {
            const uint32_t kb = ks * 32;
            uint32_t ah[4][4], al[4][4], bh[4][2], bl[4][2];
            #pragma unroll
            for (int mf = 0; mf < 4; mf++) {
                ldsm4(ah[mf][0], ah[mf][1], ah[mf][2], ah[mf][3],
                      uAh + aOff + mf * (16 * LDA * 2) + kb);
                ldsm4(al[mf][0], al[mf][1], al[mf][2], al[mf][3],
                      uAl + aOff + mf * (16 * LDA * 2) + kb);
            }
            #pragma unroll
            for (int nf = 0; nf < 4; nf++) {
                ldsm2(bh[nf][0], bh[nf][1], uBh + bOff + nf * (8 * LDA * 2) + kb);
                ldsm2(bl[nf][0], bl[nf][1], uBl + bOff + nf * (8 * LDA * 2) + kb);
            }
            #pragma unroll
            for (int mf = 0; mf < 4; mf++)
                #pragma unroll
                for (int nf = 0; nf < 4; nf++) {
                    mma16816(acc[mf][nf], ah[mf][0], ah[mf][1], ah[mf][2], ah[mf][3],
                             bh[nf][0], bh[nf][1]);
                    mma16816(acc[mf][nf], ah[mf][0], ah[mf][1], ah[mf][2], ah[mf][3],
                             bl[nf][0], bl[nf][1]);
                    mma16816(acc[mf][nf], al[mf][0], al[mf][1], al[mf][2], al[mf][3],
                             bh[nf][0], bh[nf][1]);
                }
        }
        __syncthreads();
    }

    const int group = lane >> 2, tig = lane & 3;

    __nv_bfloat16 *bph, *bpl; int head, roped, nh;
    if (n0 < CMODEL) {
        bph = g_qh; bpl = g_ql; head = n0 >> 7; roped = 1; nh = NHEAD;
    } else if (n0 < CMODEL + 1024) {
        bph = g_kh; bpl = g_kl; head = (n0 - CMODEL) >> 7; roped = 1; nh = NKV;
    } else {
        bph = g_vh; bpl = g_vl; head = (n0 - CMODEL - 1024) >> 7; roped = 0; nh = NKV;
    }
    #pragma unroll
    for (int mf = 0; mf < 4; mf++) {
        #pragma unroll
        for (int nf = 0; nf < 4; nf++) {
            const int d = wn * 32 + nf * 8 + tig * 2;
            #pragma unroll
            for (int half = 0; half < 2; half++) {
                const int row = m0 + wm * 64 + mf * 16 + group + half * 8;
                const int bb = row >> 11, tt = row & (SEQ - 1);
                float e = acc[mf][nf][half * 2], o = acc[mf][nf][half * 2 + 1];
                if (roped) {
                    const float ct = cosp[tt * DHEAD + d];
                    const float st = sinp[tt * DHEAD + d];
                    const float ne = e * ct - o * st;
                    o = e * st + o * ct;
                    e = ne;
                }
                __nv_bfloat162 hi, lo;
                split_pair(e, o, hi, lo);
                const size_t off = ((size_t)(bb * nh + head) * SEQ + tt) * DHEAD + d;
                *(__nv_bfloat162*)(bph + off) = hi;
                *(__nv_bfloat162*)(bpl + off) = lo;
            }
        }
    }
}

// ------------------------- 1-pass fp16 HMMA GEMM (output projection) --------
#define OP_TILE_SM (128 * LDA)                 // fp16 elems per tile (same stride)
#define OP_STAGE_SM (2 * OP_TILE_SM)           // 2 tiles (A, B)
#define OP_SMEM (2 * OP_STAGE_SM * 2)          // 73728 B

__device__ __forceinline__ void load_tile_async_h(const __half* __restrict__ g,
                                                  int row0, int col0, uint32_t sdst, int tid) {
    const char* gp = (const char*)(g + (size_t)row0 * CMODEL + col0);
    #pragma unroll
    for (int i = 0; i < 4; i++) {
        const int idx = i * 256 + tid;
        const int r = idx >> 3, cb = (idx & 7) << 4;
        cpa16(sdst + (uint32_t)(r * (LDA * 2) + cb), gp + (size_t)r * (CMODEL * 2) + cb);
    }
}

__global__ __launch_bounds__(256, 2)
void gemm_op(const __half* __restrict__ A, const __half* __restrict__ B,
             float* __restrict__ outp)
{
    extern __shared__ __half smh[];
    const uint32_t base = s2u(smh);

    const int tid  = threadIdx.x;
    const int wid  = tid >> 5, lane = tid & 31;
    const int wm   = wid >> 2;
    const int wn   = wid & 3;
    const int n0   = blockIdx.x * 128, m0 = blockIdx.y * 128;

    float acc[4][4][4];
    #pragma unroll
    for (int i = 0; i < 4; i++)
        #pragma unroll
        for (int j = 0; j < 4; j++)
            #pragma unroll
            for (int c = 0; c < 4; c++) acc[i][j][c] = 0.f;

    const uint32_t aOff = (uint32_t)((wm * 64 + (lane & 15)) * (LDA * 2) + (lane >> 4) * 16);
    const uint32_t bOff = (uint32_t)((wn * 32 + (lane & 7)) * (LDA * 2) + ((lane & 15) >> 3) * 16);

    {
        load_tile_async_h(A, m0, 0, base, tid);
        load_tile_async_h(B, n0, 0, base + OP_TILE_SM * 2, tid);
        cpa_commit();
    }

    const int NIT = CMODEL / BKH;
    for (int it = 0; it < NIT; it++) {
        if (it + 1 < NIT) {
            const uint32_t sn = base + ((it + 1) & 1) * OP_STAGE_SM * 2;
            const int kc = (it + 1) * BKH;
            load_tile_async_h(A, m0, kc, sn, tid);
            load_tile_async_h(B, n0, kc, sn + OP_TILE_SM * 2, tid);
        }
        cpa_commit();
        cpa_wait1();
        __syncthreads();

        const uint32_t sc = base + (it & 1) * OP_STAGE_SM * 2;
        const uint32_t uA = sc, uB = sc + OP_TILE_SM * 2;

        #pragma unroll
        for (int ks = 0; ks < 4; ks++) {
            const uint32_t kb = ks * 32;
            uint32_t a[4][4], b[4][2];
            #pragma unroll
            for (int mf = 0; mf < 4; mf++)
                ldsm4(a[mf][0], a[mf][1], a[mf][2], a[mf][3],
                      uA + aOff + mf * (16 * LDA * 2) + kb);
            #pragma unroll
            for (int nf = 0; nf < 4; nf++)
                ldsm2(b[nf][0], b[nf][1], uB + bOff + nf * (8 * LDA * 2) + kb);
            #pragma unroll
            for (int mf = 0; mf < 4; mf++)
                #pragma unroll
                for (int nf = 0; nf < 4; nf++)
                    mma16816h(acc[mf][nf], a[mf][0], a[mf][1], a[mf][2], a[mf][3],
                              b[nf][0], b[nf][1]);
        }
        __syncthreads();
    }

    const int group = lane >> 2, tig = lane & 3;
    #pragma unroll
    for (int mf = 0; mf < 4; mf++) {
        #pragma unroll
        for (int nf = 0; nf < 4; nf++) {
            const int d = wn * 32 + nf * 8 + tig * 2;
            #pragma unroll
            for (int half = 0; half < 2; half++) {
                const int row = m0 + wm * 64 + mf * 16 + group + half * 8;
                float* dst = outp + (size_t)row * CMODEL + n0 + d;
                *(float2*)dst = make_float2(acc[mf][nf][half * 2], acc[mf][nf][half * 2 + 1]);
            }
        }
    }
}

// ===========================================================================
// HMMA flash attention (round-6 proven; epilogue now emits fp16 O)
// ===========================================================================
#define FBQ 128
#define FBK 64
#define SQK 136
#define SP  72
#define FLASH_SMEM ((2 * FBQ * SQK + 4 * FBK * SQK + 2 * FBQ * SP) * 2)

__global__ __launch_bounds__(256, 1)
void flash_mma_kernel(const int* __restrict__ is_causal_p)
{
    extern __shared__ __nv_bfloat16 fsm[];
    __nv_bfloat16* Qh = fsm;
    __nv_bfloat16* Ql = Qh + FBQ * SQK;
    __nv_bfloat16* Kh = Ql + FBQ * SQK;
    __nv_bfloat16* Kl = Kh + FBK * SQK;
    __nv_bfloat16* Vh = Kl + FBK * SQK;
    __nv_bfloat16* Vl = Vh + FBK * SQK;
    __nv_bfloat16* Ph = Vl + FBK * SQK;
    __nv_bfloat16* Pl = Ph + FBQ * SP;

    const int tid  = threadIdx.x;
    const int wid  = tid >> 5, lane = tid & 31;
    const int g    = lane >> 2, tig = lane & 3;
    const int qi   = (gridDim.x - 1) - blockIdx.x;
    const int h    = blockIdx.y, b = blockIdx.z;
    const int kh   = h >> 2;
    const float scale = 0.08838834764831845f;

    const __nv_bfloat16* qgh = g_qh + ((size_t)(b * NHEAD + h) * SEQ + qi * FBQ) * DHEAD;
    const __nv_bfloat16* qgl = g_ql + ((size_t)(b * NHEAD + h) * SEQ + qi * FBQ) * DHEAD;
    const __nv_bfloat16* kgh = g_kh + (size_t)(b * NKV + kh) * SEQ * DHEAD;
    const __nv_bfloat16* kgl = g_kl + (size_t)(b * NKV + kh) * SEQ * DHEAD;
    const __nv_bfloat16* vgh = g_vh + (size_t)(b * NKV + kh) * SEQ * DHEAD;
    const __nv_bfloat16* vgl = g_vl + (size_t)(b * NKV + kh) * SEQ * DHEAD;

    const uint32_t uQh = s2u(Qh), uQl = s2u(Ql), uKh = s2u(Kh), uKl = s2u(Kl);
    const uint32_t uVh = s2u(Vh), uVl = s2u(Vl), uPh = s2u(Ph), uPl = s2u(Pl);

    #pragma unroll
    for (int i = 0; i < 8; i++) {
        const int idx = i * 256 + tid;
        const int r = idx >> 4, c = (idx & 15) << 3;
        cpa16(uQh + (uint32_t)(r * SQK + c) * 2, qgh + (size_t)r * DHEAD + c);
        cpa16(uQl + (uint32_t)(r * SQK + c) * 2, qgl + (size_t)r * DHEAD + c);
    }
    cpa_commit();

    const int causal = is_causal_p[0];
    const int nkt = causal ? (2 * qi + 2) : (SEQ / FBK);

    float oc[16][4];
    #pragma unroll
    for (int i = 0; i < 16; i++)
        #pragma unroll
        for (int c = 0; c < 4; c++) oc[i][c] = 0.f;
    float mrow[2] = {-1e30f, -1e30f}, lrow[2] = {0.f, 0.f};

    const uint32_t aQ = (uint32_t)((wid * 16 + (lane & 15)) * (SQK * 2) + ((lane >> 4) << 4));
    const uint32_t aP = (uint32_t)((wid * 16 + (lane & 15)) * (SP * 2) + ((lane >> 4) << 4));
    const int brow = (lane & 7) + ((lane >> 4) << 3);
    const uint32_t bcol = ((lane >> 3) & 1) << 4;
    const int vkrow = (lane & 7) + (((lane >> 3) & 1) << 3);
    const int vdcol = (lane >> 4) << 3;

    for (int kt = 0; kt < nkt; kt++) {
        __syncthreads();
        #pragma unroll
        for (int i = 0; i < 4; i++) {
            const int idx = i * 256 + tid;
            const int r = idx >> 4, c = (idx & 15) << 3;
            const size_t go = ((size_t)kt * FBK + r) * DHEAD + c;
            const uint32_t so = (uint32_t)(r * SQK + c) * 2;
            cpa16(uKh + so, kgh + go);
            cpa16(uKl + so, kgl + go);
            cpa16(uVh + so, vgh + go);
            cpa16(uVl + so, vgl + go);
        }
        cpa_commit();
        cpa_wait0();
        __syncthreads();

        float sc[8][4];
        #pragma unroll
        for (int i = 0; i < 8; i++)
            #pragma unroll
            for (int c = 0; c < 4; c++) sc[i][c] = 0.f;

        #pragma unroll
        for (int ks = 0; ks < 8; ks++) {
            const uint32_t kb = ks * 32;
            uint32_t ah0, ah1, ah2, ah3, al0, al1, al2, al3;
            ldsm4(ah0, ah1, ah2, ah3, uQh + aQ + kb);
            ldsm4(al0, al1, al2, al3, uQl + aQ + kb);
            #pragma unroll
            for (int j = 0; j < 4; j++) {
                const uint32_t ro = (uint32_t)((j * 16 + brow) * (SQK * 2)) + bcol + kb;
                uint32_t bh0, bh1, bh2, bh3, bl0, bl1, bl2, bl3;
                ldsm4(bh0, bh1, bh2, bh3, uKh + ro);
                ldsm4(bl0, bl1, bl2, bl3, uKl + ro);
                mma16816(sc[2 * j],     ah0, ah1, ah2, ah3, bh0, bh1);
                mma16816(sc[2 * j],     ah0, ah1, ah2, ah3, bl0, bl1);
                mma16816(sc[2 * j],     al0, al1, al2, al3, bh0, bh1);
                mma16816(sc[2 * j + 1], ah0, ah1, ah2, ah3, bh2, bh3);
                mma16816(sc[2 * j + 1], ah0, ah1, ah2, ah3, bl2, bl3);
                mma16816(sc[2 * j + 1], al0, al1, al2, al3, bh2, bh3);
            }
        }

        const int rowA = qi * FBQ + wid * 16 + g;
        const bool mb = causal && (kt >= 2 * qi);
        #pragma unroll
        for (int nf = 0; nf < 8; nf++)
            #pragma unroll
            for (int c = 0; c < 4; c++) {
                float v = sc[nf][c] * scale;
                if (mb) {
                    const int col = kt * FBK + nf * 8 + 2 * tig + (c & 1);
                    const int row = rowA + ((c >> 1) << 3);
                    if (col > row) v = -1e30f;
                }
                sc[nf][c] = v;
            }

        #pragma unroll
        for (int half = 0; half < 2; half++) {
            float mx = -1e30f;
            #pragma unroll
            for (int nf = 0; nf < 8; nf++)
                mx = fmaxf(mx, fmaxf(sc[nf][half * 2], sc[nf][half * 2 + 1]));
            mx = fmaxf(mx, __shfl_xor_sync(0xffffffffu, mx, 1));
            mx = fmaxf(mx, __shfl_xor_sync(0xffffffffu, mx, 2));
            const float mnew  = fmaxf(mrow[half], mx);
            const float alpha = __expf(mrow[half] - mnew);
            float ps = 0.f;
            #pragma unroll
            for (int nf = 0; nf < 8; nf++) {
                const float p0 = __expf(sc[nf][half * 2]     - mnew);
                const float p1 = __expf(sc[nf][half * 2 + 1] - mnew);
                sc[nf][half * 2] = p0; sc[nf][half * 2 + 1] = p1;
                ps += p0 + p1;
            }
            ps += __shfl_xor_sync(0xffffffffu, ps, 1);
            ps += __shfl_xor_sync(0xffffffffu, ps, 2);
            lrow[half] = lrow[half] * alpha + ps;
            mrow[half] = mnew;
            #pragma unroll
            for (int i = 0; i < 16; i++) {
                oc[i][half * 2]     *= alpha;
                oc[i][half * 2 + 1] *= alpha;
            }
        }

        #pragma unroll
        for (int nf = 0; nf < 8; nf++)
            #pragma unroll
            for (int half = 0; half < 2; half++) {
                __nv_bfloat162 hi, lo;
                split_pair(sc[nf][half * 2], sc[nf][half * 2 + 1], hi, lo);
                const int r = wid * 16 + g + half * 8;
                const int cc = nf * 8 + 2 * tig;
                *(__nv_bfloat162*)&Ph[r * SP + cc] = hi;
                *(__nv_bfloat162*)&Pl[r * SP + cc] = lo;
            }
        __syncwarp();

        #pragma unroll
        for (int ks = 0; ks < 4; ks++) {
            const uint32_t kb = ks * 32;
            uint32_t ph0, ph1, ph2, ph3, pl0, pl1, pl2, pl3;
            ldsm4(ph0, ph1, ph2, ph3, uPh + aP + kb);
            ldsm4(pl0, pl1, pl2, pl3, uPl + aP + kb);
            #pragma unroll
            for (int j = 0; j < 8; j++) {
                const uint32_t vo = (uint32_t)((ks * 16 + vkrow) * (SQK * 2) + (j * 16 + vdcol) * 2);
                uint32_t vh0, vh1, vh2, vh3, vl0, vl1, vl2, vl3;
                ldsm4t(vh0, vh1, vh2, vh3, uVh + vo);
                ldsm4t(vl0, vl1, vl2, vl3, uVl + vo);
                mma16816(oc[2 * j],     ph0, ph1, ph2, ph3, vh0, vh1);
                mma16816(oc[2 * j],     ph0, ph1, ph2, ph3, vl0, vl1);
                mma16816(oc[2 * j],     pl0, pl1, pl2, pl3, vh0, vh1);
                mma16816(oc[2 * j + 1], ph0, ph1, ph2, ph3, vh2, vh3);
                mma16816(oc[2 * j + 1], ph0, ph1, ph2, ph3, vl2, vl3);
                mma16816(oc[2 * j + 1], pl0, pl1, pl2, pl3, vh2, vh3);
            }
        }
    }

    // ---- epilogue: normalize and emit fp16 O directly ----------------------
    const float inv0 = 1.0f / lrow[0], inv1 = 1.0f / lrow[1];
    const int row0 = b * SEQ + qi * FBQ + wid * 16 + g;
    const int cb   = h * DHEAD + 2 * tig;
    #pragma unroll
    for (int nfo = 0; nfo < 16; nfo++) {
        const int col = cb + nfo * 8;
        *(__half2*)(g_aoF + (size_t)row0 * CMODEL + col) =
            __floats2half2_rn(oc[nfo][0] * inv0, oc[nfo][1] * inv0);
        *(__half2*)(g_aoF + (size_t)(row0 + 8) * CMODEL + col) =
            __floats2half2_rn(oc[nfo][2] * inv1, oc[nfo][3] * inv1);
    }
}

// ===========================================================================
// Launch
// ===========================================================================
extern "C" void kernel_launch(void* const* d_in, const int* in_sizes, int n_in,
                              void* d_out, int out_size)
{
    const float* x    = (const float*)d_in[0];
    const float* wq   = (const float*)d_in[1];
    const float* wk   = (const float*)d_in[2];
    const float* wv   = (const float*)d_in[3];
    const float* wo   = (const float*)d_in[4];
    const float* cosp = (const float*)d_in[5];
    const float* sinp = (const float*)d_in[6];
    const int*   isc  = (const int*)d_in[7];

    __nv_bfloat16 *xh, *xl, *wth, *wtl;
    __half *wotH, *aoF;
    cudaGetSymbolAddress((void**)&xh,  g_xh);   cudaGetSymbolAddress((void**)&xl,  g_xl);
    cudaGetSymbolAddress((void**)&wth, g_wth);  cudaGetSymbolAddress((void**)&wtl, g_wtl);
    cudaGetSymbolAddress((void**)&wotH, g_wotH);
    cudaGetSymbolAddress((void**)&aoF,  g_aoF);

    // 1) split x into bf16 hi/lo
    fsplit_kernel<<<(MROWS * CMODEL / 4 + 255) / 256, 256>>>(x, xh, xl, MROWS * CMODEL / 4);

    // 2) transpose+split qkv weights (bf16 hi/lo); transpose wo to fp16
    dim3 tb(32, 8);
    tsplit_kernel<<<dim3(CMODEL / 32, CMODEL / 32), tb>>>(wq, CMODEL, wth, wtl, 0);
    tsplit_kernel<<<dim3(1024 / 32,   CMODEL / 32), tb>>>(wk, 1024,   wth, wtl, CMODEL);
    tsplit_kernel<<<dim3(1024 / 32,   CMODEL / 32), tb>>>(wv, 1024,   wth, wtl, CMODEL + 1024);
    thalf_kernel<<<dim3(CMODEL / 32, CMODEL / 32), tb>>>(wo, wotH);

    // 3) QKV projection (3-pass bf16 HMMA) + RoPE + bf16 hi/lo emit
    cudaFuncSetAttribute(gemm_qkv, cudaFuncAttributeMaxDynamicSharedMemorySize, GEMM_SMEM);
    gemm_qkv<<<dim3(NQKV / 128, MROWS / 128), 256, GEMM_SMEM>>>(
        xh, xl, wth, wtl, cosp, sinp);

    // 4) HMMA flash attention -> fp16 O
    cudaFuncSetAttribute(flash_mma_kernel, cudaFuncAttributeMaxDynamicSharedMemorySize,
                         FLASH_SMEM);
    dim3 g2(SEQ / FBQ, NHEAD, BATCH);
    flash_mma_kernel<<<g2, 256, FLASH_SMEM>>>(isc);

    // 5) output projection (1-pass fp16 HMMA)
    cudaFuncSetAttribute(gemm_op, cudaFuncAttributeMaxDynamicSharedMemorySize, OP_SMEM);
    gemm_op<<<dim3(CMODEL / 128, MROWS / 128), 256, OP_SMEM>>>(
        aoF, wotH, (float*)d_out);
}

// round 9
// speedup vs baseline: 4.2644x; 1.1395x over previous
#include <cuda_runtime.h>
#include <cuda_bf16.h>
#include <cuda_fp16.h>
#include <cstdint>

#define BATCH   2
#define SEQ     2048
#define CMODEL  4096
#define NHEAD   32
#define DHEAD   128
#define NKV     8
#define GQA     4
#define MROWS   (BATCH * SEQ)
#define NQK     (CMODEL + NKV * DHEAD)        // 5120 (q+k projection cols)

// ------------------------- device scratch (no allocs) ----------------------
__device__ __nv_bfloat16 g_qh[BATCH * NHEAD * SEQ * DHEAD];
__device__ __nv_bfloat16 g_ql[BATCH * NHEAD * SEQ * DHEAD];
__device__ __nv_bfloat16 g_kh[BATCH * NKV * SEQ * DHEAD];
__device__ __nv_bfloat16 g_kl[BATCH * NKV * SEQ * DHEAD];
__device__ __half        g_vF[BATCH * NKV * SEQ * DHEAD];

__device__ __nv_bfloat16 g_xh [MROWS * CMODEL];
__device__ __nv_bfloat16 g_xl [MROWS * CMODEL];
__device__ __half        g_xF [MROWS * CMODEL];
__device__ __nv_bfloat16 g_wth[NQK * CMODEL];     // wq|wk transposed, bf16 hi
__device__ __nv_bfloat16 g_wtl[NQK * CMODEL];     // bf16 lo
__device__ __half        g_wvtF[(NKV * DHEAD) * CMODEL];  // wv transposed fp16
__device__ __half        g_wotH[CMODEL * CMODEL];         // wo transposed fp16
__device__ __half        g_aoF [MROWS * CMODEL];          // attention out fp16

// ------------------------- PTX helpers --------------------------------------
__device__ __forceinline__ uint32_t s2u(const void* p) {
    uint32_t a;
    asm("{ .reg .u64 t; cvta.to.shared.u64 t, %1; cvt.u32.u64 %0, t; }" : "=r"(a) : "l"(p));
    return a;
}
__device__ __forceinline__ void cpa16(uint32_t dst, const void* src) {
    asm volatile("cp.async.ca.shared.global [%0], [%1], 16;" :: "r"(dst), "l"(src));
}
__device__ __forceinline__ void cpa_commit() {
    asm volatile("cp.async.commit_group;" ::: "memory");
}
__device__ __forceinline__ void cpa_wait1() {
    asm volatile("cp.async.wait_group 1;" ::: "memory");
}
__device__ __forceinline__ void cpa_wait0() {
    asm volatile("cp.async.wait_group 0;" ::: "memory");
}
__device__ __forceinline__ void ldsm4(uint32_t& r0, uint32_t& r1, uint32_t& r2, uint32_t& r3,
                                      uint32_t addr) {
    asm volatile("ldmatrix.sync.aligned.m8n8.x4.shared.b16 {%0,%1,%2,%3}, [%4];"
                 : "=r"(r0), "=r"(r1), "=r"(r2), "=r"(r3) : "r"(addr));
}
__device__ __forceinline__ void ldsm4t(uint32_t& r0, uint32_t& r1, uint32_t& r2, uint32_t& r3,
                                       uint32_t addr) {
    asm volatile("ldmatrix.sync.aligned.m8n8.x4.trans.shared.b16 {%0,%1,%2,%3}, [%4];"
                 : "=r"(r0), "=r"(r1), "=r"(r2), "=r"(r3) : "r"(addr));
}
__device__ __forceinline__ void ldsm2(uint32_t& r0, uint32_t& r1, uint32_t addr) {
    asm volatile("ldmatrix.sync.aligned.m8n8.x2.shared.b16 {%0,%1}, [%2];"
                 : "=r"(r0), "=r"(r1) : "r"(addr));
}
__device__ __forceinline__ void mma16816(float* c, uint32_t a0, uint32_t a1, uint32_t a2,
                                         uint32_t a3, uint32_t b0, uint32_t b1) {
    asm volatile("mma.sync.aligned.m16n8k16.row.col.f32.bf16.bf16.f32 "
                 "{%0,%1,%2,%3}, {%4,%5,%6,%7}, {%8,%9}, {%0,%1,%2,%3};"
                 : "+f"(c[0]), "+f"(c[1]), "+f"(c[2]), "+f"(c[3])
                 : "r"(a0), "r"(a1), "r"(a2), "r"(a3), "r"(b0), "r"(b1));
}
__device__ __forceinline__ void mma16816h(float* c, uint32_t a0, uint32_t a1, uint32_t a2,
                                          uint32_t a3, uint32_t b0, uint32_t b1) {
    asm volatile("mma.sync.aligned.m16n8k16.row.col.f32.f16.f16.f32 "
                 "{%0,%1,%2,%3}, {%4,%5,%6,%7}, {%8,%9}, {%0,%1,%2,%3};"
                 : "+f"(c[0]), "+f"(c[1]), "+f"(c[2]), "+f"(c[3])
                 : "r"(a0), "r"(a1), "r"(a2), "r"(a3), "r"(b0), "r"(b1));
}
__device__ __forceinline__ void split_pair(float a, float b,
                                           __nv_bfloat162& hi, __nv_bfloat162& lo) {
    __nv_bfloat16 ha = __float2bfloat16(a), hb = __float2bfloat16(b);
    hi = __nv_bfloat162(ha, hb);
    lo = __nv_bfloat162(__float2bfloat16(a - __bfloat162float(ha)),
                        __float2bfloat16(b - __bfloat162float(hb)));
}

// ------------------------- conversion kernels -------------------------------
// fp32 -> bf16 hi/lo + fp16 copy
__global__ __launch_bounds__(256)
void fsplit_kernel(const float* __restrict__ s, __nv_bfloat16* __restrict__ dh,
                   __nv_bfloat16* __restrict__ dl, __half* __restrict__ dF, int n4) {
    int i = blockIdx.x * 256 + threadIdx.x;
    if (i >= n4) return;
    float4 v = ((const float4*)s)[i];
    __nv_bfloat162 h0, l0, h1, l1;
    split_pair(v.x, v.y, h0, l0);
    split_pair(v.z, v.w, h1, l1);
    ((__nv_bfloat162*)dh)[i * 2]     = h0;
    ((__nv_bfloat162*)dh)[i * 2 + 1] = h1;
    ((__nv_bfloat162*)dl)[i * 2]     = l0;
    ((__nv_bfloat162*)dl)[i * 2 + 1] = l1;
    ((__half2*)dF)[i * 2]     = __floats2half2_rn(v.x, v.y);
    ((__half2*)dF)[i * 2 + 1] = __floats2half2_rn(v.z, v.w);
}

__global__ __launch_bounds__(256)
void tsplit_kernel(const float* __restrict__ src, int N,
                   __nv_bfloat16* __restrict__ dh, __nv_bfloat16* __restrict__ dl,
                   int row_off) {
    __shared__ float t[32][33];
    const int k0 = blockIdx.y * 32, n0 = blockIdx.x * 32;
    const int tx = threadIdx.x, ty = threadIdx.y;
    #pragma unroll
    for (int i = 0; i < 32; i += 8)
        t[ty + i][tx] = src[(size_t)(k0 + ty + i) * N + n0 + tx];
    __syncthreads();
    #pragma unroll
    for (int i = 0; i < 32; i += 8) {
        const int n = n0 + ty + i, k = k0 + tx;
        const float v = t[tx][ty + i];
        const __nv_bfloat16 h = __float2bfloat16(v);
        dh[(size_t)(row_off + n) * CMODEL + k] = h;
        dl[(size_t)(row_off + n) * CMODEL + k] = __float2bfloat16(v - __bfloat162float(h));
    }
}

// transpose [K=4096][N] fp32 -> [N][4096] fp16
__global__ __launch_bounds__(256)
void thalf_kernel(const float* __restrict__ src, int N, __half* __restrict__ dst) {
    __shared__ float t[32][33];
    const int k0 = blockIdx.y * 32, n0 = blockIdx.x * 32;
    const int tx = threadIdx.x, ty = threadIdx.y;
    #pragma unroll
    for (int i = 0; i < 32; i += 8)
        t[ty + i][tx] = src[(size_t)(k0 + ty + i) * N + n0 + tx];
    __syncthreads();
    #pragma unroll
    for (int i = 0; i < 32; i += 8)
        dst[(size_t)(n0 + ty + i) * CMODEL + k0 + tx] = __float2half(t[tx][ty + i]);
}

// ------------------------- split-bf16 HMMA GEMM (Q+K projection) ------------
#define BKH 64
#define LDA 72
#define TILE_SM (128 * LDA)
#define STAGE_SM (4 * TILE_SM)
#define GEMM_SMEM (2 * STAGE_SM * 2)        // 147456 B

__device__ __forceinline__ void load_tile_async(const __nv_bfloat16* __restrict__ g,
                                                int row0, int col0, uint32_t sdst, int tid) {
    const char* gp = (const char*)(g + (size_t)row0 * CMODEL + col0);
    #pragma unroll
    for (int i = 0; i < 4; i++) {
        const int idx = i * 256 + tid;
        const int r = idx >> 3, cb = (idx & 7) << 4;
        cpa16(sdst + (uint32_t)(r * (LDA * 2) + cb), gp + (size_t)r * (CMODEL * 2) + cb);
    }
}

__global__ __launch_bounds__(256)
void gemm_qk(const __nv_bfloat16* __restrict__ Ah, const __nv_bfloat16* __restrict__ Al,
             const __nv_bfloat16* __restrict__ Bh, const __nv_bfloat16* __restrict__ Bl,
             const float* __restrict__ cosp, const float* __restrict__ sinp)
{
    extern __shared__ __nv_bfloat16 sm[];
    const uint32_t base = s2u(sm);

    const int tid  = threadIdx.x;
    const int wid  = tid >> 5, lane = tid & 31;
    const int wm   = wid >> 2;
    const int wn   = wid & 3;
    const int n0   = blockIdx.x * 128, m0 = blockIdx.y * 128;

    float acc[4][4][4];
    #pragma unroll
    for (int i = 0; i < 4; i++)
        #pragma unroll
        for (int j = 0; j < 4; j++)
            #pragma unroll
            for (int c = 0; c < 4; c++) acc[i][j][c] = 0.f;

    const uint32_t aOff = (uint32_t)((wm * 64 + (lane & 15)) * (LDA * 2) + (lane >> 4) * 16);
    const uint32_t bOff = (uint32_t)((wn * 32 + (lane & 7)) * (LDA * 2) + ((lane & 15) >> 3) * 16);

    {
        const uint32_t s0 = base;
        load_tile_async(Ah, m0, 0, s0 + 0 * TILE_SM * 2, tid);
        load_tile_async(Al, m0, 0, s0 + 1 * TILE_SM * 2, tid);
        load_tile_async(Bh, n0, 0, s0 + 2 * TILE_SM * 2, tid);
        load_tile_async(Bl, n0, 0, s0 + 3 * TILE_SM * 2, tid);
        cpa_commit();
    }

    const int NIT = CMODEL / BKH;
    for (int it = 0; it < NIT; it++) {
        if (it + 1 < NIT) {
            const uint32_t sn = base + ((it + 1) & 1) * STAGE_SM * 2;
            const int kc = (it + 1) * BKH;
            load_tile_async(Ah, m0, kc, sn + 0 * TILE_SM * 2, tid);
            load_tile_async(Al, m0, kc, sn + 1 * TILE_SM * 2, tid);
            load_tile_async(Bh, n0, kc, sn + 2 * TILE_SM * 2, tid);
            load_tile_async(Bl, n0, kc, sn + 3 * TILE_SM * 2, tid);
        }
        cpa_commit();
        cpa_wait1();
        __syncthreads();

        const uint32_t sc = base + (it & 1) * STAGE_SM * 2;
        const uint32_t uAh = sc, uAl = sc + TILE_SM * 2;
        const uint32_t uBh = sc + 2 * TILE_SM * 2, uBl = sc + 3 * TILE_SM * 2;

        #pragma unroll
        for (int ks = 0; ks < 4; ks++) {
            const uint32_t kb = ks * 32;
            uint32_t ah[4][4], al[4][4], bh[4][2], bl[4][2];
            #pragma unroll
            for (int mf = 0; mf < 4; mf++) {
                ldsm4(ah[mf][0], ah[mf][1], ah[mf][2], ah[mf][3],
                      uAh + aOff + mf * (16 * LDA * 2) + kb);
                ldsm4(al[mf][0], al[mf][1], al[mf][2], al[mf][3],
                      uAl + aOff + mf * (16 * LDA * 2) + kb);
            }
            #pragma unroll
            for (int nf = 0; nf < 4; nf++) {
                ldsm2(bh[nf][0], bh[nf][1], uBh + bOff + nf * (8 * LDA * 2) + kb);
                ldsm2(bl[nf][0], bl[nf][1], uBl + bOff + nf * (8 * LDA * 2) + kb);
            }
            #pragma unroll
            for (int mf = 0; mf < 4; mf++)
                #pragma unroll
                for (int nf = 0; nf < 4; nf++) {
                    mma16816(acc[mf][nf], ah[mf][0], ah[mf][1], ah[mf][2], ah[mf][3],
                             bh[nf][0], bh[nf][1]);
                    mma16816(acc[mf][nf], ah[mf][0], ah[mf][1], ah[mf][2], ah[mf][3],
                             bl[nf][0], bl[nf][1]);
                    mma16816(acc[mf][nf], al[mf][0], al[mf][1], al[mf][2], al[mf][3],
                             bh[nf][0], bh[nf][1]);
                }
        }
        __syncthreads();
    }

    const int group = lane >> 2, tig = lane & 3;

    __nv_bfloat16 *bph, *bpl; int head, nh;
    if (n0 < CMODEL) { bph = g_qh; bpl = g_ql; head = n0 >> 7;            nh = NHEAD; }
    else             { bph = g_kh; bpl = g_kl; head = (n0 - CMODEL) >> 7; nh = NKV;   }
    #pragma unroll
    for (int mf = 0; mf < 4; mf++) {
        #pragma unroll
        for (int nf = 0; nf < 4; nf++) {
            const int d = wn * 32 + nf * 8 + tig * 2;
            #pragma unroll
            for (int half = 0; half < 2; half++) {
                const int row = m0 + wm * 64 + mf * 16 + group + half * 8;
                const int bb = row >> 11, tt = row & (SEQ - 1);
                float e = acc[mf][nf][half * 2], o = acc[mf][nf][half * 2 + 1];
                const float ct = cosp[tt * DHEAD + d];
                const float st = sinp[tt * DHEAD + d];
                const float ne = e * ct - o * st;
                o = e * st + o * ct;
                e = ne;
                __nv_bfloat162 hi, lo;
                split_pair(e, o, hi, lo);
                const size_t off = ((size_t)(bb * nh + head) * SEQ + tt) * DHEAD + d;
                *(__nv_bfloat162*)(bph + off) = hi;
                *(__nv_bfloat162*)(bpl + off) = lo;
            }
        }
    }
}

// ------------------------- 1-pass fp16 HMMA GEMM ----------------------------
// MODE 0: V projection -> g_vF scatter ; MODE 1: out proj -> float out
#define OP_TILE_SM (128 * LDA)
#define OP_STAGE_SM (2 * OP_TILE_SM)
#define OP_SMEM (2 * OP_STAGE_SM * 2)          // 73728 B

__device__ __forceinline__ void load_tile_async_h(const __half* __restrict__ g,
                                                  int row0, int col0, uint32_t sdst, int tid) {
    const char* gp = (const char*)(g + (size_t)row0 * CMODEL + col0);
    #pragma unroll
    for (int i = 0; i < 4; i++) {
        const int idx = i * 256 + tid;
        const int r = idx >> 3, cb = (idx & 7) << 4;
        cpa16(sdst + (uint32_t)(r * (LDA * 2) + cb), gp + (size_t)r * (CMODEL * 2) + cb);
    }
}

template<int MODE>
__global__ __launch_bounds__(256, 2)
void gemm_h(const __half* __restrict__ A, const __half* __restrict__ B,
            float* __restrict__ outp)
{
    extern __shared__ __half smh[];
    const uint32_t base = s2u(smh);

    const int tid  = threadIdx.x;
    const int wid  = tid >> 5, lane = tid & 31;
    const int wm   = wid >> 2;
    const int wn   = wid & 3;
    const int n0   = blockIdx.x * 128, m0 = blockIdx.y * 128;

    float acc[4][4][4];
    #pragma unroll
    for (int i = 0; i < 4; i++)
        #pragma unroll
        for (int j = 0; j < 4; j++)
            #pragma unroll
            for (int c = 0; c < 4; c++) acc[i][j][c] = 0.f;

    const uint32_t aOff = (uint32_t)((wm * 64 + (lane & 15)) * (LDA * 2) + (lane >> 4) * 16);
    const uint32_t bOff = (uint32_t)((wn * 32 + (lane & 7)) * (LDA * 2) + ((lane & 15) >> 3) * 16);

    {
        load_tile_async_h(A, m0, 0, base, tid);
        load_tile_async_h(B, n0, 0, base + OP_TILE_SM * 2, tid);
        cpa_commit();
    }

    const int NIT = CMODEL / BKH;
    for (int it = 0; it < NIT; it++) {
        if (it + 1 < NIT) {
            const uint32_t sn = base + ((it + 1) & 1) * OP_STAGE_SM * 2;
            const int kc = (it + 1) * BKH;
            load_tile_async_h(A, m0, kc, sn, tid);
            load_tile_async_h(B, n0, kc, sn + OP_TILE_SM * 2, tid);
        }
        cpa_commit();
        cpa_wait1();
        __syncthreads();

        const uint32_t sc = base + (it & 1) * OP_STAGE_SM * 2;
        const uint32_t uA = sc, uB = sc + OP_TILE_SM * 2;

        #pragma unroll
        for (int ks = 0; ks < 4; ks++) {
            const uint32_t kb = ks * 32;
            uint32_t a[4][4], b[4][2];
            #pragma unroll
            for (int mf = 0; mf < 4; mf++)
                ldsm4(a[mf][0], a[mf][1], a[mf][2], a[mf][3],
                      uA + aOff + mf * (16 * LDA * 2) + kb);
            #pragma unroll
            for (int nf = 0; nf < 4; nf++)
                ldsm2(b[nf][0], b[nf][1], uB + bOff + nf * (8 * LDA * 2) + kb);
            #pragma unroll
            for (int mf = 0; mf < 4; mf++)
                #pragma unroll
                for (int nf = 0; nf < 4; nf++)
                    mma16816h(acc[mf][nf], a[mf][0], a[mf][1], a[mf][2], a[mf][3],
                              b[nf][0], b[nf][1]);
        }
        __syncthreads();
    }

    const int group = lane >> 2, tig = lane & 3;
    if (MODE == 0) {
        const int head = n0 >> 7;
        #pragma unroll
        for (int mf = 0; mf < 4; mf++) {
            #pragma unroll
            for (int nf = 0; nf < 4; nf++) {
                const int d = wn * 32 + nf * 8 + tig * 2;
                #pragma unroll
                for (int half = 0; half < 2; half++) {
                    const int row = m0 + wm * 64 + mf * 16 + group + half * 8;
                    const int bb = row >> 11, tt = row & (SEQ - 1);
                    const size_t off = ((size_t)(bb * NKV + head) * SEQ + tt) * DHEAD + d;
                    *(__half2*)(g_vF + off) =
                        __floats2half2_rn(acc[mf][nf][half * 2], acc[mf][nf][half * 2 + 1]);
                }
            }
        }
    } else {
        #pragma unroll
        for (int mf = 0; mf < 4; mf++) {
            #pragma unroll
            for (int nf = 0; nf < 4; nf++) {
                const int d = wn * 32 + nf * 8 + tig * 2;
                #pragma unroll
                for (int half = 0; half < 2; half++) {
                    const int row = m0 + wm * 64 + mf * 16 + group + half * 8;
                    float* dst = outp + (size_t)row * CMODEL + n0 + d;
                    *(float2*)dst = make_float2(acc[mf][nf][half * 2], acc[mf][nf][half * 2 + 1]);
                }
            }
        }
    }
}

// ===========================================================================
// HMMA flash attention: 3-pass bf16 QK, 1-pass fp16 PV
// ===========================================================================
#define FBQ 128
#define FBK 64
#define SQK 136
#define SP  72
#define FLASH_SMEM ((2 * FBQ * SQK + 3 * FBK * SQK + FBQ * SP) * 2)   // 140288 B

__global__ __launch_bounds__(256, 1)
void flash_mma_kernel(const int* __restrict__ is_causal_p)
{
    extern __shared__ char fsmc[];
    __nv_bfloat16* Qh = (__nv_bfloat16*)fsmc;
    __nv_bfloat16* Ql = Qh + FBQ * SQK;
    __nv_bfloat16* Kh = Ql + FBQ * SQK;
    __nv_bfloat16* Kl = Kh + FBK * SQK;
    __half*        Vf = (__half*)(Kl + FBK * SQK);
    __half*        Ph = Vf + FBK * SQK;

    const int tid  = threadIdx.x;
    const int wid  = tid >> 5, lane = tid & 31;
    const int g    = lane >> 2, tig = lane & 3;
    const int qi   = (gridDim.x - 1) - blockIdx.x;
    const int h    = blockIdx.y, b = blockIdx.z;
    const int kh   = h >> 2;
    const float scale = 0.08838834764831845f;

    const __nv_bfloat16* qgh = g_qh + ((size_t)(b * NHEAD + h) * SEQ + qi * FBQ) * DHEAD;
    const __nv_bfloat16* qgl = g_ql + ((size_t)(b * NHEAD + h) * SEQ + qi * FBQ) * DHEAD;
    const __nv_bfloat16* kgh = g_kh + (size_t)(b * NKV + kh) * SEQ * DHEAD;
    const __nv_bfloat16* kgl = g_kl + (size_t)(b * NKV + kh) * SEQ * DHEAD;
    const __half*        vgf = g_vF + (size_t)(b * NKV + kh) * SEQ * DHEAD;

    const uint32_t uQh = s2u(Qh), uQl = s2u(Ql), uKh = s2u(Kh), uKl = s2u(Kl);
    const uint32_t uVf = s2u(Vf), uPh = s2u(Ph);

    #pragma unroll
    for (int i = 0; i < 8; i++) {
        const int idx = i * 256 + tid;
        const int r = idx >> 4, c = (idx & 15) << 3;
        cpa16(uQh + (uint32_t)(r * SQK + c) * 2, qgh + (size_t)r * DHEAD + c);
        cpa16(uQl + (uint32_t)(r * SQK + c) * 2, qgl + (size_t)r * DHEAD + c);
    }
    cpa_commit();

    const int causal = is_causal_p[0];
    const int nkt = causal ? (2 * qi + 2) : (SEQ / FBK);

    float oc[16][4];
    #pragma unroll
    for (int i = 0; i < 16; i++)
        #pragma unroll
        for (int c = 0; c < 4; c++) oc[i][c] = 0.f;
    float mrow[2] = {-1e30f, -1e30f}, lrow[2] = {0.f, 0.f};

    const uint32_t aQ = (uint32_t)((wid * 16 + (lane & 15)) * (SQK * 2) + ((lane >> 4) << 4));
    const uint32_t aP = (uint32_t)((wid * 16 + (lane & 15)) * (SP * 2) + ((lane >> 4) << 4));
    const int brow = (lane & 7) + ((lane >> 4) << 3);
    const uint32_t bcol = ((lane >> 3) & 1) << 4;
    const int vkrow = (lane & 7) + (((lane >> 3) & 1) << 3);
    const int vdcol = (lane >> 4) << 3;

    for (int kt = 0; kt < nkt; kt++) {
        __syncthreads();
        #pragma unroll
        for (int i = 0; i < 4; i++) {
            const int idx = i * 256 + tid;
            const int r = idx >> 4, c = (idx & 15) << 3;
            const size_t go = ((size_t)kt * FBK + r) * DHEAD + c;
            const uint32_t so = (uint32_t)(r * SQK + c) * 2;
            cpa16(uKh + so, kgh + go);
            cpa16(uKl + so, kgl + go);
            cpa16(uVf + so, vgf + go);
        }
        cpa_commit();
        cpa_wait0();
        __syncthreads();

        // ---- S = Q K^T (3-pass split-bf16) --------------------------------
        float sc[8][4];
        #pragma unroll
        for (int i = 0; i < 8; i++)
            #pragma unroll
            for (int c = 0; c < 4; c++) sc[i][c] = 0.f;

        #pragma unroll
        for (int ks = 0; ks < 8; ks++) {
            const uint32_t kb = ks * 32;
            uint32_t ah0, ah1, ah2, ah3, al0, al1, al2, al3;
            ldsm4(ah0, ah1, ah2, ah3, uQh + aQ + kb);
            ldsm4(al0, al1, al2, al3, uQl + aQ + kb);
            #pragma unroll
            for (int j = 0; j < 4; j++) {
                const uint32_t ro = (uint32_t)((j * 16 + brow) * (SQK * 2)) + bcol + kb;
                uint32_t bh0, bh1, bh2, bh3, bl0, bl1, bl2, bl3;
                ldsm4(bh0, bh1, bh2, bh3, uKh + ro);
                ldsm4(bl0, bl1, bl2, bl3, uKl + ro);
                mma16816(sc[2 * j],     ah0, ah1, ah2, ah3, bh0, bh1);
                mma16816(sc[2 * j],     ah0, ah1, ah2, ah3, bl0, bl1);
                mma16816(sc[2 * j],     al0, al1, al2, al3, bh0, bh1);
                mma16816(sc[2 * j + 1], ah0, ah1, ah2, ah3, bh2, bh3);
                mma16816(sc[2 * j + 1], ah0, ah1, ah2, ah3, bl2, bl3);
                mma16816(sc[2 * j + 1], al0, al1, al2, al3, bh2, bh3);
            }
        }

        const int rowA = qi * FBQ + wid * 16 + g;
        const bool mb = causal && (kt >= 2 * qi);
        #pragma unroll
        for (int nf = 0; nf < 8; nf++)
            #pragma unroll
            for (int c = 0; c < 4; c++) {
                float v = sc[nf][c] * scale;
                if (mb) {
                    const int col = kt * FBK + nf * 8 + 2 * tig + (c & 1);
                    const int row = rowA + ((c >> 1) << 3);
                    if (col > row) v = -1e30f;
                }
                sc[nf][c] = v;
            }

        #pragma unroll
        for (int half = 0; half < 2; half++) {
            float mx = -1e30f;
            #pragma unroll
            for (int nf = 0; nf < 8; nf++)
                mx = fmaxf(mx, fmaxf(sc[nf][half * 2], sc[nf][half * 2 + 1]));
            mx = fmaxf(mx, __shfl_xor_sync(0xffffffffu, mx, 1));
            mx = fmaxf(mx, __shfl_xor_sync(0xffffffffu, mx, 2));
            const float mnew  = fmaxf(mrow[half], mx);
            const float alpha = __expf(mrow[half] - mnew);
            float ps = 0.f;
            #pragma unroll
            for (int nf = 0; nf < 8; nf++) {
                const float p0 = __expf(sc[nf][half * 2]     - mnew);
                const float p1 = __expf(sc[nf][half * 2 + 1] - mnew);
                sc[nf][half * 2] = p0; sc[nf][half * 2 + 1] = p1;
                ps += p0 + p1;
            }
            ps += __shfl_xor_sync(0xffffffffu, ps, 1);
            ps += __shfl_xor_sync(0xffffffffu, ps, 2);
            lrow[half] = lrow[half] * alpha + ps;
            mrow[half] = mnew;
            #pragma unroll
            for (int i = 0; i < 16; i++) {
                oc[i][half * 2]     *= alpha;
                oc[i][half * 2 + 1] *= alpha;
            }
        }

        // ---- publish P as fp16 --------------------------------------------
        #pragma unroll
        for (int nf = 0; nf < 8; nf++)
            #pragma unroll
            for (int half = 0; half < 2; half++) {
                const int r = wid * 16 + g + half * 8;
                const int cc = nf * 8 + 2 * tig;
                *(__half2*)&Ph[r * SP + cc] =
                    __floats2half2_rn(sc[nf][half * 2], sc[nf][half * 2 + 1]);
            }
        __syncwarp();

        // ---- O += P V (1-pass fp16) ---------------------------------------
        #pragma unroll
        for (int ks = 0; ks < 4; ks++) {
            const uint32_t kb = ks * 32;
            uint32_t ph0, ph1, ph2, ph3;
            ldsm4(ph0, ph1, ph2, ph3, uPh + aP + kb);
            #pragma unroll
            for (int j = 0; j < 8; j++) {
                const uint32_t vo = (uint32_t)((ks * 16 + vkrow) * (SQK * 2) + (j * 16 + vdcol) * 2);
                uint32_t vf0, vf1, vf2, vf3;
                ldsm4t(vf0, vf1, vf2, vf3, uVf + vo);
                mma16816h(oc[2 * j],     ph0, ph1, ph2, ph3, vf0, vf1);
                mma16816h(oc[2 * j + 1], ph0, ph1, ph2, ph3, vf2, vf3);
            }
        }
    }

    // ---- epilogue: normalize and emit fp16 O -------------------------------
    const float inv0 = 1.0f / lrow[0], inv1 = 1.0f / lrow[1];
    const int row0 = b * SEQ + qi * FBQ + wid * 16 + g;
    const int cb   = h * DHEAD + 2 * tig;
    #pragma unroll
    for (int nfo = 0; nfo < 16; nfo++) {
        const int col = cb + nfo * 8;
        *(__half2*)(g_aoF + (size_t)row0 * CMODEL + col) =
            __floats2half2_rn(oc[nfo][0] * inv0, oc[nfo][1] * inv0);
        *(__half2*)(g_aoF + (size_t)(row0 + 8) * CMODEL + col) =
            __floats2half2_rn(oc[nfo][2] * inv1, oc[nfo][3] * inv1);
    }
}

// ===========================================================================
// Launch
// ===========================================================================
extern "C" void kernel_launch(void* const* d_in, const int* in_sizes, int n_in,
                              void* d_out, int out_size)
{
    const float* x    = (const float*)d_in[0];
    const float* wq   = (const float*)d_in[1];
    const float* wk   = (const float*)d_in[2];
    const float* wv   = (const float*)d_in[3];
    const float* wo   = (const float*)d_in[4];
    const float* cosp = (const float*)d_in[5];
    const float* sinp = (const float*)d_in[6];
    const int*   isc  = (const int*)d_in[7];

    __nv_bfloat16 *xh, *xl, *wth, *wtl;
    __half *xF, *wvtF, *wotH, *aoF;
    cudaGetSymbolAddress((void**)&xh,   g_xh);   cudaGetSymbolAddress((void**)&xl,  g_xl);
    cudaGetSymbolAddress((void**)&xF,   g_xF);
    cudaGetSymbolAddress((void**)&wth,  g_wth);  cudaGetSymbolAddress((void**)&wtl, g_wtl);
    cudaGetSymbolAddress((void**)&wvtF, g_wvtF);
    cudaGetSymbolAddress((void**)&wotH, g_wotH);
    cudaGetSymbolAddress((void**)&aoF,  g_aoF);

    // 1) split x into bf16 hi/lo + fp16
    fsplit_kernel<<<(MROWS * CMODEL / 4 + 255) / 256, 256>>>(x, xh, xl, xF, MROWS * CMODEL / 4);

    // 2) transpose weights: wq/wk bf16 hi/lo ; wv/wo fp16
    dim3 tb(32, 8);
    tsplit_kernel<<<dim3(CMODEL / 32, CMODEL / 32), tb>>>(wq, CMODEL, wth, wtl, 0);
    tsplit_kernel<<<dim3(1024 / 32,   CMODEL / 32), tb>>>(wk, 1024,   wth, wtl, CMODEL);
    thalf_kernel<<<dim3(1024 / 32,   CMODEL / 32), tb>>>(wv, 1024,   wvtF);
    thalf_kernel<<<dim3(CMODEL / 32, CMODEL / 32), tb>>>(wo, CMODEL, wotH);

    // 3) Q+K projection (3-pass bf16 HMMA) + RoPE
    cudaFuncSetAttribute(gemm_qk, cudaFuncAttributeMaxDynamicSharedMemorySize, GEMM_SMEM);
    gemm_qk<<<dim3(NQK / 128, MROWS / 128), 256, GEMM_SMEM>>>(
        xh, xl, wth, wtl, cosp, sinp);

    // 4) V projection (1-pass fp16 HMMA)
    cudaFuncSetAttribute(gemm_h<0>, cudaFuncAttributeMaxDynamicSharedMemorySize, OP_SMEM);
    gemm_h<0><<<dim3(1024 / 128, MROWS / 128), 256, OP_SMEM>>>(xF, wvtF, nullptr);

    // 5) HMMA flash attention (bf16 QK 3-pass, fp16 PV 1-pass) -> fp16 O
    cudaFuncSetAttribute(flash_mma_kernel, cudaFuncAttributeMaxDynamicSharedMemorySize,
                         FLASH_SMEM);
    dim3 g2(SEQ / FBQ, NHEAD, BATCH);
    flash_mma_kernel<<<g2, 256, FLASH_SMEM>>>(isc);

    // 6) output projection (1-pass fp16 HMMA)
    cudaFuncSetAttribute(gemm_h<1>, cudaFuncAttributeMaxDynamicSharedMemorySize, OP_SMEM);
    gemm_h<1><<<dim3(CMODEL / 128, MROWS / 128), 256, OP_SMEM>>>(
        aoF, wotH, (float*)d_out);
}

// round 11
// speedup vs baseline: 4.9129x; 1.1521x over previous
#include <cuda_runtime.h>
#include <cuda_bf16.h>
#include <cuda_fp16.h>
#include <cstdint>

#define BATCH   2
#define SEQ     2048
#define CMODEL  4096
#define NHEAD   32
#define DHEAD   128
#define NKV     8
#define GQA     4
#define MROWS   (BATCH * SEQ)
#define NQK     (CMODEL + NKV * DHEAD)        // 5120 (q+k projection cols)

// ------------------------- device scratch (no allocs) ----------------------
__device__ __half g_qh[BATCH * NHEAD * SEQ * DHEAD];   // q fp16 hi
__device__ __half g_ql[BATCH * NHEAD * SEQ * DHEAD];   // q fp16 lo
__device__ __half g_kh[BATCH * NKV * SEQ * DHEAD];     // k fp16 hi
__device__ __half g_kl[BATCH * NKV * SEQ * DHEAD];     // k fp16 lo
__device__ __half g_vF[BATCH * NKV * SEQ * DHEAD];

__device__ __half g_xh [MROWS * CMODEL];               // fp16 hi of x (also V input)
__device__ __half g_xl [MROWS * CMODEL];               // fp16 lo of x
__device__ __half g_wqkF[NQK * CMODEL];                // wq|wk transposed fp16
__device__ __half g_wvtF[(NKV * DHEAD) * CMODEL];      // wv transposed fp16
__device__ __half g_wotH[CMODEL * CMODEL];             // wo transposed fp16
__device__ __half g_aoF [MROWS * CMODEL];              // attention out fp16

// ------------------------- PTX helpers --------------------------------------
__device__ __forceinline__ uint32_t s2u(const void* p) {
    uint32_t a;
    asm("{ .reg .u64 t; cvta.to.shared.u64 t, %1; cvt.u32.u64 %0, t; }" : "=r"(a) : "l"(p));
    return a;
}
__device__ __forceinline__ void cpa16(uint32_t dst, const void* src) {
    asm volatile("cp.async.ca.shared.global [%0], [%1], 16;" :: "r"(dst), "l"(src));
}
__device__ __forceinline__ void cpa_commit() {
    asm volatile("cp.async.commit_group;" ::: "memory");
}
__device__ __forceinline__ void cpa_wait1() {
    asm volatile("cp.async.wait_group 1;" ::: "memory");
}
__device__ __forceinline__ void cpa_wait0() {
    asm volatile("cp.async.wait_group 0;" ::: "memory");
}
__device__ __forceinline__ void ldsm4(uint32_t& r0, uint32_t& r1, uint32_t& r2, uint32_t& r3,
                                      uint32_t addr) {
    asm volatile("ldmatrix.sync.aligned.m8n8.x4.shared.b16 {%0,%1,%2,%3}, [%4];"
                 : "=r"(r0), "=r"(r1), "=r"(r2), "=r"(r3) : "r"(addr));
}
__device__ __forceinline__ void ldsm4t(uint32_t& r0, uint32_t& r1, uint32_t& r2, uint32_t& r3,
                                       uint32_t addr) {
    asm volatile("ldmatrix.sync.aligned.m8n8.x4.trans.shared.b16 {%0,%1,%2,%3}, [%4];"
                 : "=r"(r0), "=r"(r1), "=r"(r2), "=r"(r3) : "r"(addr));
}
__device__ __forceinline__ void ldsm2(uint32_t& r0, uint32_t& r1, uint32_t addr) {
    asm volatile("ldmatrix.sync.aligned.m8n8.x2.shared.b16 {%0,%1}, [%2];"
                 : "=r"(r0), "=r"(r1) : "r"(addr));
}
__device__ __forceinline__ void mma16816h(float* c, uint32_t a0, uint32_t a1, uint32_t a2,
                                          uint32_t a3, uint32_t b0, uint32_t b1) {
    asm volatile("mma.sync.aligned.m16n8k16.row.col.f32.f16.f16.f32 "
                 "{%0,%1,%2,%3}, {%4,%5,%6,%7}, {%8,%9}, {%0,%1,%2,%3};"
                 : "+f"(c[0]), "+f"(c[1]), "+f"(c[2]), "+f"(c[3])
                 : "r"(a0), "r"(a1), "r"(a2), "r"(a3), "r"(b0), "r"(b1));
}
__device__ __forceinline__ void split_pair_h(float a, float b,
                                             __half2& hi, __half2& lo) {
    const __half ha = __float2half(a), hb = __float2half(b);
    hi = __halves2half2(ha, hb);
    lo = __halves2half2(__float2half(a - __half2float(ha)),
                        __float2half(b - __half2float(hb)));
}

// ------------------------- conversion kernels -------------------------------
// fp32 -> fp16 hi/lo
__global__ __launch_bounds__(256)
void fsplit_kernel(const float* __restrict__ s, __half* __restrict__ dh,
                   __half* __restrict__ dl, int n4) {
    int i = blockIdx.x * 256 + threadIdx.x;
    if (i >= n4) return;
    float4 v = ((const float4*)s)[i];
    __half2 h0, l0, h1, l1;
    split_pair_h(v.x, v.y, h0, l0);
    split_pair_h(v.z, v.w, h1, l1);
    ((__half2*)dh)[i * 2]     = h0;
    ((__half2*)dh)[i * 2 + 1] = h1;
    ((__half2*)dl)[i * 2]     = l0;
    ((__half2*)dl)[i * 2 + 1] = l1;
}

// transpose [K=4096][N] fp32 -> [row_off + N][4096] fp16
__global__ __launch_bounds__(256)
void thalf_kernel(const float* __restrict__ src, int N, __half* __restrict__ dst,
                  int row_off) {
    __shared__ float t[32][33];
    const int k0 = blockIdx.y * 32, n0 = blockIdx.x * 32;
    const int tx = threadIdx.x, ty = threadIdx.y;
    #pragma unroll
    for (int i = 0; i < 32; i += 8)
        t[ty + i][tx] = src[(size_t)(k0 + ty + i) * N + n0 + tx];
    __syncthreads();
    #pragma unroll
    for (int i = 0; i < 32; i += 8)
        dst[(size_t)(row_off + n0 + ty + i) * CMODEL + k0 + tx] = __float2half(t[tx][ty + i]);
}

// ------------------------- 2-pass fp16 HMMA GEMM (Q+K projection) -----------
#define BKH 64
#define LDA 72
#define TILE_SM (128 * LDA)                 // 16-bit elems per tile
#define QK_STAGE_SM (3 * TILE_SM)           // xhi, xlo, w
#define QK_SMEM (2 * QK_STAGE_SM * 2)       // 110592 B

__device__ __forceinline__ void load_tile_async_h(const __half* __restrict__ g,
                                                  int row0, int col0, uint32_t sdst, int tid) {
    const char* gp = (const char*)(g + (size_t)row0 * CMODEL + col0);
    #pragma unroll
    for (int i = 0; i < 4; i++) {
        const int idx = i * 256 + tid;
        const int r = idx >> 3, cb = (idx & 7) << 4;
        cpa16(sdst + (uint32_t)(r * (LDA * 2) + cb), gp + (size_t)r * (CMODEL * 2) + cb);
    }
}

__global__ __launch_bounds__(256)
void gemm_qk(const __half* __restrict__ Ah, const __half* __restrict__ Al,
             const __half* __restrict__ B,
             const float* __restrict__ cosp, const float* __restrict__ sinp)
{
    extern __shared__ __half sm[];
    const uint32_t base = s2u(sm);

    const int tid  = threadIdx.x;
    const int wid  = tid >> 5, lane = tid & 31;
    const int wm   = wid >> 2;
    const int wn   = wid & 3;
    const int n0   = blockIdx.x * 128, m0 = blockIdx.y * 128;

    float acc[4][4][4];
    #pragma unroll
    for (int i = 0; i < 4; i++)
        #pragma unroll
        for (int j = 0; j < 4; j++)
            #pragma unroll
            for (int c = 0; c < 4; c++) acc[i][j][c] = 0.f;

    const uint32_t aOff = (uint32_t)((wm * 64 + (lane & 15)) * (LDA * 2) + (lane >> 4) * 16);
    const uint32_t bOff = (uint32_t)((wn * 32 + (lane & 7)) * (LDA * 2) + ((lane & 15) >> 3) * 16);

    {
        load_tile_async_h(Ah, m0, 0, base + 0 * TILE_SM * 2, tid);
        load_tile_async_h(Al, m0, 0, base + 1 * TILE_SM * 2, tid);
        load_tile_async_h(B,  n0, 0, base + 2 * TILE_SM * 2, tid);
        cpa_commit();
    }

    const int NIT = CMODEL / BKH;
    for (int it = 0; it < NIT; it++) {
        if (it + 1 < NIT) {
            const uint32_t sn = base + ((it + 1) & 1) * QK_STAGE_SM * 2;
            const int kc = (it + 1) * BKH;
            load_tile_async_h(Ah, m0, kc, sn + 0 * TILE_SM * 2, tid);
            load_tile_async_h(Al, m0, kc, sn + 1 * TILE_SM * 2, tid);
            load_tile_async_h(B,  n0, kc, sn + 2 * TILE_SM * 2, tid);
        }
        cpa_commit();
        cpa_wait1();
        __syncthreads();

        const uint32_t sc = base + (it & 1) * QK_STAGE_SM * 2;
        const uint32_t uAh = sc, uAl = sc + TILE_SM * 2, uB = sc + 2 * TILE_SM * 2;

        #pragma unroll
        for (int ks = 0; ks < 4; ks++) {
            const uint32_t kb = ks * 32;
            uint32_t ah[4][4], al[4][4], b[4][2];
            #pragma unroll
            for (int mf = 0; mf < 4; mf++) {
                ldsm4(ah[mf][0], ah[mf][1], ah[mf][2], ah[mf][3],
                      uAh + aOff + mf * (16 * LDA * 2) + kb);
                ldsm4(al[mf][0], al[mf][1], al[mf][2], al[mf][3],
                      uAl + aOff + mf * (16 * LDA * 2) + kb);
            }
            #pragma unroll
            for (int nf = 0; nf < 4; nf++)
                ldsm2(b[nf][0], b[nf][1], uB + bOff + nf * (8 * LDA * 2) + kb);
            #pragma unroll
            for (int mf = 0; mf < 4; mf++)
                #pragma unroll
                for (int nf = 0; nf < 4; nf++) {
                    mma16816h(acc[mf][nf], ah[mf][0], ah[mf][1], ah[mf][2], ah[mf][3],
                              b[nf][0], b[nf][1]);
                    mma16816h(acc[mf][nf], al[mf][0], al[mf][1], al[mf][2], al[mf][3],
                              b[nf][0], b[nf][1]);
                }
        }
        __syncthreads();
    }

    const int group = lane >> 2, tig = lane & 3;

    __half *bph, *bpl; int head, nh;
    if (n0 < CMODEL) { bph = g_qh; bpl = g_ql; head = n0 >> 7;            nh = NHEAD; }
    else             { bph = g_kh; bpl = g_kl; head = (n0 - CMODEL) >> 7; nh = NKV;   }
    #pragma unroll
    for (int mf = 0; mf < 4; mf++) {
        #pragma unroll
        for (int nf = 0; nf < 4; nf++) {
            const int d = wn * 32 + nf * 8 + tig * 2;
            #pragma unroll
            for (int half = 0; half < 2; half++) {
                const int row = m0 + wm * 64 + mf * 16 + group + half * 8;
                const int bb = row >> 11, tt = row & (SEQ - 1);
                float e = acc[mf][nf][half * 2], o = acc[mf][nf][half * 2 + 1];
                const float ct = cosp[tt * DHEAD + d];
                const float st = sinp[tt * DHEAD + d];
                const float ne = e * ct - o * st;
                o = e * st + o * ct;
                e = ne;
                __half2 hi, lo;
                split_pair_h(e, o, hi, lo);
                const size_t off = ((size_t)(bb * nh + head) * SEQ + tt) * DHEAD + d;
                *(__half2*)(bph + off) = hi;
                *(__half2*)(bpl + off) = lo;
            }
        }
    }
}

// ------------------------- 1-pass fp16 HMMA GEMM ----------------------------
// MODE 0: V projection -> g_vF scatter ; MODE 1: out proj -> float out
#define OP_STAGE_SM (2 * TILE_SM)
#define OP_SMEM (2 * OP_STAGE_SM * 2)          // 73728 B

template<int MODE>
__global__ __launch_bounds__(256, 2)
void gemm_h(const __half* __restrict__ A, const __half* __restrict__ B,
            float* __restrict__ outp)
{
    extern __shared__ __half smh[];
    const uint32_t base = s2u(smh);

    const int tid  = threadIdx.x;
    const int wid  = tid >> 5, lane = tid & 31;
    const int wm   = wid >> 2;
    const int wn   = wid & 3;
    const int n0   = blockIdx.x * 128, m0 = blockIdx.y * 128;

    float acc[4][4][4];
    #pragma unroll
    for (int i = 0; i < 4; i++)
        #pragma unroll
        for (int j = 0; j < 4; j++)
            #pragma unroll
            for (int c = 0; c < 4; c++) acc[i][j][c] = 0.f;

    const uint32_t aOff = (uint32_t)((wm * 64 + (lane & 15)) * (LDA * 2) + (lane >> 4) * 16);
    const uint32_t bOff = (uint32_t)((wn * 32 + (lane & 7)) * (LDA * 2) + ((lane & 15) >> 3) * 16);

    {
        load_tile_async_h(A, m0, 0, base, tid);
        load_tile_async_h(B, n0, 0, base + TILE_SM * 2, tid);
        cpa_commit();
    }

    const int NIT = CMODEL / BKH;
    for (int it = 0; it < NIT; it++) {
        if (it + 1 < NIT) {
            const uint32_t sn = base + ((it + 1) & 1) * OP_STAGE_SM * 2;
            const int kc = (it + 1) * BKH;
            load_tile_async_h(A, m0, kc, sn, tid);
            load_tile_async_h(B, n0, kc, sn + TILE_SM * 2, tid);
        }
        cpa_commit();
        cpa_wait1();
        __syncthreads();

        const uint32_t sc = base + (it & 1) * OP_STAGE_SM * 2;
        const uint32_t uA = sc, uB = sc + TILE_SM * 2;

        #pragma unroll
        for (int ks = 0; ks < 4; ks++) {
            const uint32_t kb = ks * 32;
            uint32_t a[4][4], b[4][2];
            #pragma unroll
            for (int mf = 0; mf < 4; mf++)
                ldsm4(a[mf][0], a[mf][1], a[mf][2], a[mf][3],
                      uA + aOff + mf * (16 * LDA * 2) + kb);
            #pragma unroll
            for (int nf = 0; nf < 4; nf++)
                ldsm2(b[nf][0], b[nf][1], uB + bOff + nf * (8 * LDA * 2) + kb);
            #pragma unroll
            for (int mf = 0; mf < 4; mf++)
                #pragma unroll
                for (int nf = 0; nf < 4; nf++)
                    mma16816h(acc[mf][nf], a[mf][0], a[mf][1], a[mf][2], a[mf][3],
                              b[nf][0], b[nf][1]);
        }
        __syncthreads();
    }

    const int group = lane >> 2, tig = lane & 3;
    if (MODE == 0) {
        const int head = n0 >> 7;
        #pragma unroll
        for (int mf = 0; mf < 4; mf++) {
            #pragma unroll
            for (int nf = 0; nf < 4; nf++) {
                const int d = wn * 32 + nf * 8 + tig * 2;
                #pragma unroll
                for (int half = 0; half < 2; half++) {
                    const int row = m0 + wm * 64 + mf * 16 + group + half * 8;
                    const int bb = row >> 11, tt = row & (SEQ - 1);
                    const size_t off = ((size_t)(bb * NKV + head) * SEQ + tt) * DHEAD + d;
                    *(__half2*)(g_vF + off) =
                        __floats2half2_rn(acc[mf][nf][half * 2], acc[mf][nf][half * 2 + 1]);
                }
            }
        }
    } else {
        #pragma unroll
        for (int mf = 0; mf < 4; mf++) {
            #pragma unroll
            for (int nf = 0; nf < 4; nf++) {
                const int d = wn * 32 + nf * 8 + tig * 2;
                #pragma unroll
                for (int half = 0; half < 2; half++) {
                    const int row = m0 + wm * 64 + mf * 16 + group + half * 8;
                    float* dst = outp + (size_t)row * CMODEL + n0 + d;
                    *(float2*)dst = make_float2(acc[mf][nf][half * 2], acc[mf][nf][half * 2 + 1]);
                }
            }
        }
    }
}

// ===========================================================================
// HMMA flash attention: 3-pass fp16 QK (q/k split), 1-pass fp16 PV
// ===========================================================================
#define FBQ 128
#define FBK 64
#define SQK 136
#define SP  72
#define FLASH_SMEM ((2 * FBQ * SQK + 3 * FBK * SQK + FBQ * SP) * 2)   // 140288 B

__global__ __launch_bounds__(256, 1)
void flash_mma_kernel(const int* __restrict__ is_causal_p)
{
    extern __shared__ char fsmc[];
    __half* Qh = (__half*)fsmc;
    __half* Ql = Qh + FBQ * SQK;
    __half* Kh = Ql + FBQ * SQK;
    __half* Kl = Kh + FBK * SQK;
    __half* Vf = Kl + FBK * SQK;
    __half* Ph = Vf + FBK * SQK;

    const int tid  = threadIdx.x;
    const int wid  = tid >> 5, lane = tid & 31;
    const int g    = lane >> 2, tig = lane & 3;
    const int qi   = (gridDim.x - 1) - blockIdx.x;
    const int h    = blockIdx.y, b = blockIdx.z;
    const int kh   = h >> 2;
    const float scale = 0.08838834764831845f;

    const __half* qgh = g_qh + ((size_t)(b * NHEAD + h) * SEQ + qi * FBQ) * DHEAD;
    const __half* qgl = g_ql + ((size_t)(b * NHEAD + h) * SEQ + qi * FBQ) * DHEAD;
    const __half* kgh = g_kh + (size_t)(b * NKV + kh) * SEQ * DHEAD;
    const __half* kgl = g_kl + (size_t)(b * NKV + kh) * SEQ * DHEAD;
    const __half* vgf = g_vF + (size_t)(b * NKV + kh) * SEQ * DHEAD;

    const uint32_t uQh = s2u(Qh), uQl = s2u(Ql), uKh = s2u(Kh), uKl = s2u(Kl);
    const uint32_t uVf = s2u(Vf), uPh = s2u(Ph);

    #pragma unroll
    for (int i = 0; i < 8; i++) {
        const int idx = i * 256 + tid;
        const int r = idx >> 4, c = (idx & 15) << 3;
        cpa16(uQh + (uint32_t)(r * SQK + c) * 2, qgh + (size_t)r * DHEAD + c);
        cpa16(uQl + (uint32_t)(r * SQK + c) * 2, qgl + (size_t)r * DHEAD + c);
    }
    cpa_commit();

    const int causal = is_causal_p[0];
    const int nkt = causal ? (2 * qi + 2) : (SEQ / FBK);

    float oc[16][4];
    #pragma unroll
    for (int i = 0; i < 16; i++)
        #pragma unroll
        for (int c = 0; c < 4; c++) oc[i][c] = 0.f;
    float mrow[2] = {-1e30f, -1e30f}, lrow[2] = {0.f, 0.f};

    const uint32_t aQ = (uint32_t)((wid * 16 + (lane & 15)) * (SQK * 2) + ((lane >> 4) << 4));
    const uint32_t aP = (uint32_t)((wid * 16 + (lane & 15)) * (SP * 2) + ((lane >> 4) << 4));
    const int brow = (lane & 7) + ((lane >> 4) << 3);
    const uint32_t bcol = ((lane >> 3) & 1) << 4;
    const int vkrow = (lane & 7) + (((lane >> 3) & 1) << 3);
    const int vdcol = (lane >> 4) << 3;

    for (int kt = 0; kt < nkt; kt++) {
        __syncthreads();
        #pragma unroll
        for (int i = 0; i < 4; i++) {
            const int idx = i * 256 + tid;
            const int r = idx >> 4, c = (idx & 15) << 3;
            const size_t go = ((size_t)kt * FBK + r) * DHEAD + c;
            const uint32_t so = (uint32_t)(r * SQK + c) * 2;
            cpa16(uKh + so, kgh + go);
            cpa16(uKl + so, kgl + go);
            cpa16(uVf + so, vgf + go);
        }
        cpa_commit();
        cpa_wait0();
        __syncthreads();

        // ---- S = Q K^T (3-pass split-fp16: qh*kh + ql*kh + qh*kl) ---------
        float sc[8][4];
        #pragma unroll
        for (int i = 0; i < 8; i++)
            #pragma unroll
            for (int c = 0; c < 4; c++) sc[i][c] = 0.f;

        #pragma unroll
        for (int ks = 0; ks < 8; ks++) {
            const uint32_t kb = ks * 32;
            uint32_t ah0, ah1, ah2, ah3, al0, al1, al2, al3;
            ldsm4(ah0, ah1, ah2, ah3, uQh + aQ + kb);
            ldsm4(al0, al1, al2, al3, uQl + aQ + kb);
            #pragma unroll
            for (int j = 0; j < 4; j++) {
                const uint32_t ro = (uint32_t)((j * 16 + brow) * (SQK * 2)) + bcol + kb;
                uint32_t bh0, bh1, bh2, bh3, bl0, bl1, bl2, bl3;
                ldsm4(bh0, bh1, bh2, bh3, uKh + ro);
                ldsm4(bl0, bl1, bl2, bl3, uKl + ro);
                mma16816h(sc[2 * j],     ah0, ah1, ah2, ah3, bh0, bh1);
                mma16816h(sc[2 * j],     al0, al1, al2, al3, bh0, bh1);
                mma16816h(sc[2 * j],     ah0, ah1, ah2, ah3, bl0, bl1);
                mma16816h(sc[2 * j + 1], ah0, ah1, ah2, ah3, bh2, bh3);
                mma16816h(sc[2 * j + 1], al0, al1, al2, al3, bh2, bh3);
                mma16816h(sc[2 * j + 1], ah0, ah1, ah2, ah3, bl2, bl3);
            }
        }

        const int rowA = qi * FBQ + wid * 16 + g;
        const bool mb = causal && (kt >= 2 * qi);
        #pragma unroll
        for (int nf = 0; nf < 8; nf++)
            #pragma unroll
            for (int c = 0; c < 4; c++) {
                float v = sc[nf][c] * scale;
                if (mb) {
                    const int col = kt * FBK + nf * 8 + 2 * tig + (c & 1);
                    const int row = rowA + ((c >> 1) << 3);
                    if (col > row) v = -1e30f;
                }
                sc[nf][c] = v;
            }

        #pragma unroll
        for (int half = 0; half < 2; half++) {
            float mx = -1e30f;
            #pragma unroll
            for (int nf = 0; nf < 8; nf++)
                mx = fmaxf(mx, fmaxf(sc[nf][half * 2], sc[nf][half * 2 + 1]));
            mx = fmaxf(mx, __shfl_xor_sync(0xffffffffu, mx, 1));
            mx = fmaxf(mx, __shfl_xor_sync(0xffffffffu, mx, 2));
            const float mnew  = fmaxf(mrow[half], mx);
            const float alpha = __expf(mrow[half] - mnew);
            float ps = 0.f;
            #pragma unroll
            for (int nf = 0; nf < 8; nf++) {
                const float p0 = __expf(sc[nf][half * 2]     - mnew);
                const float p1 = __expf(sc[nf][half * 2 + 1] - mnew);
                sc[nf][half * 2] = p0; sc[nf][half * 2 + 1] = p1;
                ps += p0 + p1;
            }
            ps += __shfl_xor_sync(0xffffffffu, ps, 1);
            ps += __shfl_xor_sync(0xffffffffu, ps, 2);
            lrow[half] = lrow[half] * alpha + ps;
            mrow[half] = mnew;
            #pragma unroll
            for (int i = 0; i < 16; i++) {
                oc[i][half * 2]     *= alpha;
                oc[i][half * 2 + 1] *= alpha;
            }
        }

        // ---- publish P as fp16 --------------------------------------------
        #pragma unroll
        for (int nf = 0; nf < 8; nf++)
            #pragma unroll
            for (int half = 0; half < 2; half++) {
                const int r = wid * 16 + g + half * 8;
                const int cc = nf * 8 + 2 * tig;
                *(__half2*)&Ph[r * SP + cc] =
                    __floats2half2_rn(sc[nf][half * 2], sc[nf][half * 2 + 1]);
            }
        __syncwarp();

        // ---- O += P V (1-pass fp16) ---------------------------------------
        #pragma unroll
        for (int ks = 0; ks < 4; ks++) {
            const uint32_t kb = ks * 32;
            uint32_t ph0, ph1, ph2, ph3;
            ldsm4(ph0, ph1, ph2, ph3, uPh + aP + kb);
            #pragma unroll
            for (int j = 0; j < 8; j++) {
                const uint32_t vo = (uint32_t)((ks * 16 + vkrow) * (SQK * 2) + (j * 16 + vdcol) * 2);
                uint32_t vf0, vf1, vf2, vf3;
                ldsm4t(vf0, vf1, vf2, vf3, uVf + vo);
                mma16816h(oc[2 * j],     ph0, ph1, ph2, ph3, vf0, vf1);
                mma16816h(oc[2 * j + 1], ph0, ph1, ph2, ph3, vf2, vf3);
            }
        }
    }

    // ---- epilogue: normalize and emit fp16 O -------------------------------
    const float inv0 = 1.0f / lrow[0], inv1 = 1.0f / lrow[1];
    const int row0 = b * SEQ + qi * FBQ + wid * 16 + g;
    const int cb   = h * DHEAD + 2 * tig;
    #pragma unroll
    for (int nfo = 0; nfo < 16; nfo++) {
        const int col = cb + nfo * 8;
        *(__half2*)(g_aoF + (size_t)row0 * CMODEL + col) =
            __floats2half2_rn(oc[nfo][0] * inv0, oc[nfo][1] * inv0);
        *(__half2*)(g_aoF + (size_t)(row0 + 8) * CMODEL + col) =
            __floats2half2_rn(oc[nfo][2] * inv1, oc[nfo][3] * inv1);
    }
}

// ===========================================================================
// Launch
// ===========================================================================
extern "C" void kernel_launch(void* const* d_in, const int* in_sizes, int n_in,
                              void* d_out, int out_size)
{
    const float* x    = (const float*)d_in[0];
    const float* wq   = (const float*)d_in[1];
    const float* wk   = (const float*)d_in[2];
    const float* wv   = (const float*)d_in[3];
    const float* wo   = (const float*)d_in[4];
    const float* cosp = (const float*)d_in[5];
    const float* sinp = (const float*)d_in[6];
    const int*   isc  = (const int*)d_in[7];

    __half *xh, *xl, *wqkF, *wvtF, *wotH, *aoF;
    cudaGetSymbolAddress((void**)&xh,   g_xh);
    cudaGetSymbolAddress((void**)&xl,   g_xl);
    cudaGetSymbolAddress((void**)&wqkF, g_wqkF);
    cudaGetSymbolAddress((void**)&wvtF, g_wvtF);
    cudaGetSymbolAddress((void**)&wotH, g_wotH);
    cudaGetSymbolAddress((void**)&aoF,  g_aoF);

    // 1) split x into fp16 hi/lo (hi also feeds V projection)
    fsplit_kernel<<<(MROWS * CMODEL / 4 + 255) / 256, 256>>>(x, xh, xl, MROWS * CMODEL / 4);

    // 2) transpose weights to fp16: wq|wk concat, wv, wo
    dim3 tb(32, 8);
    thalf_kernel<<<dim3(CMODEL / 32, CMODEL / 32), tb>>>(wq, CMODEL, wqkF, 0);
    thalf_kernel<<<dim3(1024 / 32,   CMODEL / 32), tb>>>(wk, 1024,   wqkF, CMODEL);
    thalf_kernel<<<dim3(1024 / 32,   CMODEL / 32), tb>>>(wv, 1024,   wvtF, 0);
    thalf_kernel<<<dim3(CMODEL / 32, CMODEL / 32), tb>>>(wo, CMODEL, wotH, 0);

    // 3) Q+K projection (2-pass fp16 HMMA) + RoPE -> fp16 hi/lo q,k
    cudaFuncSetAttribute(gemm_qk, cudaFuncAttributeMaxDynamicSharedMemorySize, QK_SMEM);
    gemm_qk<<<dim3(NQK / 128, MROWS / 128), 256, QK_SMEM>>>(
        xh, xl, wqkF, cosp, sinp);

    // 4) V projection (1-pass fp16 HMMA)
    cudaFuncSetAttribute(gemm_h<0>, cudaFuncAttributeMaxDynamicSharedMemorySize, OP_SMEM);
    gemm_h<0><<<dim3(1024 / 128, MROWS / 128), 256, OP_SMEM>>>(xh, wvtF, nullptr);

    // 5) HMMA flash attention (fp16 QK 3-pass split, fp16 PV 1-pass) -> fp16 O
    cudaFuncSetAttribute(flash_mma_kernel, cudaFuncAttributeMaxDynamicSharedMemorySize,
                         FLASH_SMEM);
    dim3 g2(SEQ / FBQ, NHEAD, BATCH);
    flash_mma_kernel<<<g2, 256, FLASH_SMEM>>>(isc);

    // 6) output projection (1-pass fp16 HMMA)
    cudaFuncSetAttribute(gemm_h<1>, cudaFuncAttributeMaxDynamicSharedMemorySize, OP_SMEM);
    gemm_h<1><<<dim3(CMODEL / 128, MROWS / 128), 256, OP_SMEM>>>(
        aoF, wotH, (float*)d_out);
}

// round 12
// speedup vs baseline: 5.1401x; 1.0462x over previous
#include <cuda_runtime.h>
#include <cuda_bf16.h>
#include <cuda_fp16.h>
#include <cstdint>

#define BATCH   2
#define SEQ     2048
#define CMODEL  4096
#define NHEAD   32
#define DHEAD   128
#define NKV     8
#define GQA     4
#define MROWS   (BATCH * SEQ)
#define NQK     (CMODEL + NKV * DHEAD)        // 5120 (q+k projection cols)

// ------------------------- device scratch (no allocs) ----------------------
__device__ __half g_qh[BATCH * NHEAD * SEQ * DHEAD];   // q fp16 hi
__device__ __half g_ql[BATCH * NHEAD * SEQ * DHEAD];   // q fp16 lo
__device__ __half g_kF[BATCH * NKV * SEQ * DHEAD];     // k fp16 (single)
__device__ __half g_vF[BATCH * NKV * SEQ * DHEAD];

__device__ __half g_xh [MROWS * CMODEL];               // fp16 hi of x (also V input)
__device__ __half g_xl [MROWS * CMODEL];               // fp16 lo of x
__device__ __half g_wqkF[NQK * CMODEL];                // wq|wk transposed fp16
__device__ __half g_wvtF[(NKV * DHEAD) * CMODEL];      // wv transposed fp16
__device__ __half g_wotH[CMODEL * CMODEL];             // wo transposed fp16
__device__ __half g_aoF [MROWS * CMODEL];              // attention out fp16

// ------------------------- PTX helpers --------------------------------------
__device__ __forceinline__ uint32_t s2u(const void* p) {
    uint32_t a;
    asm("{ .reg .u64 t; cvta.to.shared.u64 t, %1; cvt.u32.u64 %0, t; }" : "=r"(a) : "l"(p));
    return a;
}
__device__ __forceinline__ void cpa16(uint32_t dst, const void* src) {
    asm volatile("cp.async.ca.shared.global [%0], [%1], 16;" :: "r"(dst), "l"(src));
}
__device__ __forceinline__ void cpa_commit() {
    asm volatile("cp.async.commit_group;" ::: "memory");
}
__device__ __forceinline__ void cpa_wait1() {
    asm volatile("cp.async.wait_group 1;" ::: "memory");
}
__device__ __forceinline__ void cpa_wait0() {
    asm volatile("cp.async.wait_group 0;" ::: "memory");
}
__device__ __forceinline__ void ldsm4(uint32_t& r0, uint32_t& r1, uint32_t& r2, uint32_t& r3,
                                      uint32_t addr) {
    asm volatile("ldmatrix.sync.aligned.m8n8.x4.shared.b16 {%0,%1,%2,%3}, [%4];"
                 : "=r"(r0), "=r"(r1), "=r"(r2), "=r"(r3) : "r"(addr));
}
__device__ __forceinline__ void ldsm4t(uint32_t& r0, uint32_t& r1, uint32_t& r2, uint32_t& r3,
                                       uint32_t addr) {
    asm volatile("ldmatrix.sync.aligned.m8n8.x4.trans.shared.b16 {%0,%1,%2,%3}, [%4];"
                 : "=r"(r0), "=r"(r1), "=r"(r2), "=r"(r3) : "r"(addr));
}
__device__ __forceinline__ void ldsm2(uint32_t& r0, uint32_t& r1, uint32_t addr) {
    asm volatile("ldmatrix.sync.aligned.m8n8.x2.shared.b16 {%0,%1}, [%2];"
                 : "=r"(r0), "=r"(r1) : "r"(addr));
}
__device__ __forceinline__ void mma16816h(float* c, uint32_t a0, uint32_t a1, uint32_t a2,
                                          uint32_t a3, uint32_t b0, uint32_t b1) {
    asm volatile("mma.sync.aligned.m16n8k16.row.col.f32.f16.f16.f32 "
                 "{%0,%1,%2,%3}, {%4,%5,%6,%7}, {%8,%9}, {%0,%1,%2,%3};"
                 : "+f"(c[0]), "+f"(c[1]), "+f"(c[2]), "+f"(c[3])
                 : "r"(a0), "r"(a1), "r"(a2), "r"(a3), "r"(b0), "r"(b1));
}
__device__ __forceinline__ void split_pair_h(float a, float b,
                                             __half2& hi, __half2& lo) {
    const __half ha = __float2half(a), hb = __float2half(b);
    hi = __halves2half2(ha, hb);
    lo = __halves2half2(__float2half(a - __half2float(ha)),
                        __float2half(b - __half2float(hb)));
}

// ------------------------- conversion kernels -------------------------------
// fp32 -> fp16 hi/lo
__global__ __launch_bounds__(256)
void fsplit_kernel(const float* __restrict__ s, __half* __restrict__ dh,
                   __half* __restrict__ dl, int n4) {
    int i = blockIdx.x * 256 + threadIdx.x;
    if (i >= n4) return;
    float4 v = ((const float4*)s)[i];
    __half2 h0, l0, h1, l1;
    split_pair_h(v.x, v.y, h0, l0);
    split_pair_h(v.z, v.w, h1, l1);
    ((__half2*)dh)[i * 2]     = h0;
    ((__half2*)dh)[i * 2 + 1] = h1;
    ((__half2*)dl)[i * 2]     = l0;
    ((__half2*)dl)[i * 2 + 1] = l1;
}

// transpose [K=4096][N] fp32 -> [row_off + N][4096] fp16
__global__ __launch_bounds__(256)
void thalf_kernel(const float* __restrict__ src, int N, __half* __restrict__ dst,
                  int row_off) {
    __shared__ float t[32][33];
    const int k0 = blockIdx.y * 32, n0 = blockIdx.x * 32;
    const int tx = threadIdx.x, ty = threadIdx.y;
    #pragma unroll
    for (int i = 0; i < 32; i += 8)
        t[ty + i][tx] = src[(size_t)(k0 + ty + i) * N + n0 + tx];
    __syncthreads();
    #pragma unroll
    for (int i = 0; i < 32; i += 8)
        dst[(size_t)(row_off + n0 + ty + i) * CMODEL + k0 + tx] = __float2half(t[tx][ty + i]);
}

// ------------------------- 2-pass fp16 HMMA GEMM (Q+K projection) -----------
#define BKH 64
#define LDA 72
#define TILE_SM (128 * LDA)                 // 16-bit elems per tile
#define QK_STAGE_SM (3 * TILE_SM)           // xhi, xlo, w
#define QK_SMEM (2 * QK_STAGE_SM * 2)       // 110592 B

__device__ __forceinline__ void load_tile_async_h(const __half* __restrict__ g,
                                                  int row0, int col0, uint32_t sdst, int tid) {
    const char* gp = (const char*)(g + (size_t)row0 * CMODEL + col0);
    #pragma unroll
    for (int i = 0; i < 4; i++) {
        const int idx = i * 256 + tid;
        const int r = idx >> 3, cb = (idx & 7) << 4;
        cpa16(sdst + (uint32_t)(r * (LDA * 2) + cb), gp + (size_t)r * (CMODEL * 2) + cb);
    }
}

__global__ __launch_bounds__(256)
void gemm_qk(const __half* __restrict__ Ah, const __half* __restrict__ Al,
             const __half* __restrict__ B,
             const float* __restrict__ cosp, const float* __restrict__ sinp)
{
    extern __shared__ __half sm[];
    const uint32_t base = s2u(sm);

    const int tid  = threadIdx.x;
    const int wid  = tid >> 5, lane = tid & 31;
    const int wm   = wid >> 2;
    const int wn   = wid & 3;
    const int n0   = blockIdx.x * 128, m0 = blockIdx.y * 128;

    float acc[4][4][4];
    #pragma unroll
    for (int i = 0; i < 4; i++)
        #pragma unroll
        for (int j = 0; j < 4; j++)
            #pragma unroll
            for (int c = 0; c < 4; c++) acc[i][j][c] = 0.f;

    const uint32_t aOff = (uint32_t)((wm * 64 + (lane & 15)) * (LDA * 2) + (lane >> 4) * 16);
    const uint32_t bOff = (uint32_t)((wn * 32 + (lane & 7)) * (LDA * 2) + ((lane & 15) >> 3) * 16);

    {
        load_tile_async_h(Ah, m0, 0, base + 0 * TILE_SM * 2, tid);
        load_tile_async_h(Al, m0, 0, base + 1 * TILE_SM * 2, tid);
        load_tile_async_h(B,  n0, 0, base + 2 * TILE_SM * 2, tid);
        cpa_commit();
    }

    const int NIT = CMODEL / BKH;
    for (int it = 0; it < NIT; it++) {
        if (it + 1 < NIT) {
            const uint32_t sn = base + ((it + 1) & 1) * QK_STAGE_SM * 2;
            const int kc = (it + 1) * BKH;
            load_tile_async_h(Ah, m0, kc, sn + 0 * TILE_SM * 2, tid);
            load_tile_async_h(Al, m0, kc, sn + 1 * TILE_SM * 2, tid);
            load_tile_async_h(B,  n0, kc, sn + 2 * TILE_SM * 2, tid);
        }
        cpa_commit();
        cpa_wait1();
        __syncthreads();

        const uint32_t sc = base + (it & 1) * QK_STAGE_SM * 2;
        const uint32_t uAh = sc, uAl = sc + TILE_SM * 2, uB = sc + 2 * TILE_SM * 2;

        #pragma unroll
        for (int ks = 0; ks < 4; ks++) {
            const uint32_t kb = ks * 32;
            uint32_t ah[4][4], al[4][4], b[4][2];
            #pragma unroll
            for (int mf = 0; mf < 4; mf++) {
                ldsm4(ah[mf][0], ah[mf][1], ah[mf][2], ah[mf][3],
                      uAh + aOff + mf * (16 * LDA * 2) + kb);
                ldsm4(al[mf][0], al[mf][1], al[mf][2], al[mf][3],
                      uAl + aOff + mf * (16 * LDA * 2) + kb);
            }
            #pragma unroll
            for (int nf = 0; nf < 4; nf++)
                ldsm2(b[nf][0], b[nf][1], uB + bOff + nf * (8 * LDA * 2) + kb);
            #pragma unroll
            for (int mf = 0; mf < 4; mf++)
                #pragma unroll
                for (int nf = 0; nf < 4; nf++) {
                    mma16816h(acc[mf][nf], ah[mf][0], ah[mf][1], ah[mf][2], ah[mf][3],
                              b[nf][0], b[nf][1]);
                    mma16816h(acc[mf][nf], al[mf][0], al[mf][1], al[mf][2], al[mf][3],
                              b[nf][0], b[nf][1]);
                }
        }
        __syncthreads();
    }

    const int group = lane >> 2, tig = lane & 3;
    const int isQ = (n0 < CMODEL);
    const int head = isQ ? (n0 >> 7) : ((n0 - CMODEL) >> 7);
    const int nh   = isQ ? NHEAD : NKV;

    #pragma unroll
    for (int mf = 0; mf < 4; mf++) {
        #pragma unroll
        for (int nf = 0; nf < 4; nf++) {
            const int d = wn * 32 + nf * 8 + tig * 2;
            #pragma unroll
            for (int half = 0; half < 2; half++) {
                const int row = m0 + wm * 64 + mf * 16 + group + half * 8;
                const int bb = row >> 11, tt = row & (SEQ - 1);
                float e = acc[mf][nf][half * 2], o = acc[mf][nf][half * 2 + 1];
                const float ct = cosp[tt * DHEAD + d];
                const float st = sinp[tt * DHEAD + d];
                const float ne = e * ct - o * st;
                o = e * st + o * ct;
                e = ne;
                const size_t off = ((size_t)(bb * nh + head) * SEQ + tt) * DHEAD + d;
                if (isQ) {
                    __half2 hi, lo;
                    split_pair_h(e, o, hi, lo);
                    *(__half2*)(g_qh + off) = hi;
                    *(__half2*)(g_ql + off) = lo;
                } else {
                    *(__half2*)(g_kF + off) = __floats2half2_rn(e, o);
                }
            }
        }
    }
}

// ------------------------- 1-pass fp16 HMMA GEMM ----------------------------
// MODE 0: V projection -> g_vF scatter ; MODE 1: out proj -> float out
#define OP_STAGE_SM (2 * TILE_SM)
#define OP_SMEM (2 * OP_STAGE_SM * 2)          // 73728 B

template<int MODE>
__global__ __launch_bounds__(256, 2)
void gemm_h(const __half* __restrict__ A, const __half* __restrict__ B,
            float* __restrict__ outp)
{
    extern __shared__ __half smh[];
    const uint32_t base = s2u(smh);

    const int tid  = threadIdx.x;
    const int wid  = tid >> 5, lane = tid & 31;
    const int wm   = wid >> 2;
    const int wn   = wid & 3;
    const int n0   = blockIdx.x * 128, m0 = blockIdx.y * 128;

    float acc[4][4][4];
    #pragma unroll
    for (int i = 0; i < 4; i++)
        #pragma unroll
        for (int j = 0; j < 4; j++)
            #pragma unroll
            for (int c = 0; c < 4; c++) acc[i][j][c] = 0.f;

    const uint32_t aOff = (uint32_t)((wm * 64 + (lane & 15)) * (LDA * 2) + (lane >> 4) * 16);
    const uint32_t bOff = (uint32_t)((wn * 32 + (lane & 7)) * (LDA * 2) + ((lane & 15) >> 3) * 16);

    {
        load_tile_async_h(A, m0, 0, base, tid);
        load_tile_async_h(B, n0, 0, base + TILE_SM * 2, tid);
        cpa_commit();
    }

    const int NIT = CMODEL / BKH;
    for (int it = 0; it < NIT; it++) {
        if (it + 1 < NIT) {
            const uint32_t sn = base + ((it + 1) & 1) * OP_STAGE_SM * 2;
            const int kc = (it + 1) * BKH;
            load_tile_async_h(A, m0, kc, sn, tid);
            load_tile_async_h(B, n0, kc, sn + TILE_SM * 2, tid);
        }
        cpa_commit();
        cpa_wait1();
        __syncthreads();

        const uint32_t sc = base + (it & 1) * OP_STAGE_SM * 2;
        const uint32_t uA = sc, uB = sc + TILE_SM * 2;

        #pragma unroll
        for (int ks = 0; ks < 4; ks++) {
            const uint32_t kb = ks * 32;
            uint32_t a[4][4], b[4][2];
            #pragma unroll
            for (int mf = 0; mf < 4; mf++)
                ldsm4(a[mf][0], a[mf][1], a[mf][2], a[mf][3],
                      uA + aOff + mf * (16 * LDA * 2) + kb);
            #pragma unroll
            for (int nf = 0; nf < 4; nf++)
                ldsm2(b[nf][0], b[nf][1], uB + bOff + nf * (8 * LDA * 2) + kb);
            #pragma unroll
            for (int mf = 0; mf < 4; mf++)
                #pragma unroll
                for (int nf = 0; nf < 4; nf++)
                    mma16816h(acc[mf][nf], a[mf][0], a[mf][1], a[mf][2], a[mf][3],
                              b[nf][0], b[nf][1]);
        }
        __syncthreads();
    }

    const int group = lane >> 2, tig = lane & 3;
    if (MODE == 0) {
        const int head = n0 >> 7;
        #pragma unroll
        for (int mf = 0; mf < 4; mf++) {
            #pragma unroll
            for (int nf = 0; nf < 4; nf++) {
                const int d = wn * 32 + nf * 8 + tig * 2;
                #pragma unroll
                for (int half = 0; half < 2; half++) {
                    const int row = m0 + wm * 64 + mf * 16 + group + half * 8;
                    const int bb = row >> 11, tt = row & (SEQ - 1);
                    const size_t off = ((size_t)(bb * NKV + head) * SEQ + tt) * DHEAD + d;
                    *(__half2*)(g_vF + off) =
                        __floats2half2_rn(acc[mf][nf][half * 2], acc[mf][nf][half * 2 + 1]);
                }
            }
        }
    } else {
        #pragma unroll
        for (int mf = 0; mf < 4; mf++) {
            #pragma unroll
            for (int nf = 0; nf < 4; nf++) {
                const int d = wn * 32 + nf * 8 + tig * 2;
                #pragma unroll
                for (int half = 0; half < 2; half++) {
                    const int row = m0 + wm * 64 + mf * 16 + group + half * 8;
                    float* dst = outp + (size_t)row * CMODEL + n0 + d;
                    *(float2*)dst = make_float2(acc[mf][nf][half * 2], acc[mf][nf][half * 2 + 1]);
                }
            }
        }
    }
}

// ===========================================================================
// HMMA flash attention: 2-pass fp16 QK (qh*k + ql*k), 1-pass fp16 PV
// ===========================================================================
#define FBQ 128
#define FBK 64
#define SQK 136
#define SP  72
#define FLASH_SMEM ((2 * FBQ * SQK + 2 * FBK * SQK + FBQ * SP) * 2)   // 122880 B

__global__ __launch_bounds__(256, 1)
void flash_mma_kernel(const int* __restrict__ is_causal_p)
{
    extern __shared__ char fsmc[];
    __half* Qh = (__half*)fsmc;
    __half* Ql = Qh + FBQ * SQK;
    __half* Kf = Ql + FBQ * SQK;
    __half* Vf = Kf + FBK * SQK;
    __half* Ph = Vf + FBK * SQK;

    const int tid  = threadIdx.x;
    const int wid  = tid >> 5, lane = tid & 31;
    const int g    = lane >> 2, tig = lane & 3;
    const int qi   = (gridDim.x - 1) - blockIdx.x;
    const int h    = blockIdx.y, b = blockIdx.z;
    const int kh   = h >> 2;
    const float scale = 0.08838834764831845f;

    const __half* qgh = g_qh + ((size_t)(b * NHEAD + h) * SEQ + qi * FBQ) * DHEAD;
    const __half* qgl = g_ql + ((size_t)(b * NHEAD + h) * SEQ + qi * FBQ) * DHEAD;
    const __half* kgf = g_kF + (size_t)(b * NKV + kh) * SEQ * DHEAD;
    const __half* vgf = g_vF + (size_t)(b * NKV + kh) * SEQ * DHEAD;

    const uint32_t uQh = s2u(Qh), uQl = s2u(Ql), uKf = s2u(Kf);
    const uint32_t uVf = s2u(Vf), uPh = s2u(Ph);

    #pragma unroll
    for (int i = 0; i < 8; i++) {
        const int idx = i * 256 + tid;
        const int r = idx >> 4, c = (idx & 15) << 3;
        cpa16(uQh + (uint32_t)(r * SQK + c) * 2, qgh + (size_t)r * DHEAD + c);
        cpa16(uQl + (uint32_t)(r * SQK + c) * 2, qgl + (size_t)r * DHEAD + c);
    }
    cpa_commit();

    const int causal = is_causal_p[0];
    const int nkt = causal ? (2 * qi + 2) : (SEQ / FBK);

    float oc[16][4];
    #pragma unroll
    for (int i = 0; i < 16; i++)
        #pragma unroll
        for (int c = 0; c < 4; c++) oc[i][c] = 0.f;
    float mrow[2] = {-1e30f, -1e30f}, lrow[2] = {0.f, 0.f};

    const uint32_t aQ = (uint32_t)((wid * 16 + (lane & 15)) * (SQK * 2) + ((lane >> 4) << 4));
    const uint32_t aP = (uint32_t)((wid * 16 + (lane & 15)) * (SP * 2) + ((lane >> 4) << 4));
    const int brow = (lane & 7) + ((lane >> 4) << 3);
    const uint32_t bcol = ((lane >> 3) & 1) << 4;
    const int vkrow = (lane & 7) + (((lane >> 3) & 1) << 3);
    const int vdcol = (lane >> 4) << 3;

    for (int kt = 0; kt < nkt; kt++) {
        __syncthreads();
        #pragma unroll
        for (int i = 0; i < 4; i++) {
            const int idx = i * 256 + tid;
            const int r = idx >> 4, c = (idx & 15) << 3;
            const size_t go = ((size_t)kt * FBK + r) * DHEAD + c;
            const uint32_t so = (uint32_t)(r * SQK + c) * 2;
            cpa16(uKf + so, kgf + go);
            cpa16(uVf + so, vgf + go);
        }
        cpa_commit();
        cpa_wait0();
        __syncthreads();

        // ---- S = Q K^T (2-pass: qh*k + ql*k) ------------------------------
        float sc[8][4];
        #pragma unroll
        for (int i = 0; i < 8; i++)
            #pragma unroll
            for (int c = 0; c < 4; c++) sc[i][c] = 0.f;

        #pragma unroll
        for (int ks = 0; ks < 8; ks++) {
            const uint32_t kb = ks * 32;
            uint32_t ah0, ah1, ah2, ah3, al0, al1, al2, al3;
            ldsm4(ah0, ah1, ah2, ah3, uQh + aQ + kb);
            ldsm4(al0, al1, al2, al3, uQl + aQ + kb);
            #pragma unroll
            for (int j = 0; j < 4; j++) {
                const uint32_t ro = (uint32_t)((j * 16 + brow) * (SQK * 2)) + bcol + kb;
                uint32_t bf0, bf1, bf2, bf3;
                ldsm4(bf0, bf1, bf2, bf3, uKf + ro);
                mma16816h(sc[2 * j],     ah0, ah1, ah2, ah3, bf0, bf1);
                mma16816h(sc[2 * j],     al0, al1, al2, al3, bf0, bf1);
                mma16816h(sc[2 * j + 1], ah0, ah1, ah2, ah3, bf2, bf3);
                mma16816h(sc[2 * j + 1], al0, al1, al2, al3, bf2, bf3);
            }
        }

        const int rowA = qi * FBQ + wid * 16 + g;
        const bool mb = causal && (kt >= 2 * qi);
        #pragma unroll
        for (int nf = 0; nf < 8; nf++)
            #pragma unroll
            for (int c = 0; c < 4; c++) {
                float v = sc[nf][c] * scale;
                if (mb) {
                    const int col = kt * FBK + nf * 8 + 2 * tig + (c & 1);
                    const int row = rowA + ((c >> 1) << 3);
                    if (col > row) v = -1e30f;
                }
                sc[nf][c] = v;
            }

        #pragma unroll
        for (int half = 0; half < 2; half++) {
            float mx = -1e30f;
            #pragma unroll
            for (int nf = 0; nf < 8; nf++)
                mx = fmaxf(mx, fmaxf(sc[nf][half * 2], sc[nf][half * 2 + 1]));
            mx = fmaxf(mx, __shfl_xor_sync(0xffffffffu, mx, 1));
            mx = fmaxf(mx, __shfl_xor_sync(0xffffffffu, mx, 2));
            const float mnew  = fmaxf(mrow[half], mx);
            const float alpha = __expf(mrow[half] - mnew);
            float ps = 0.f;
            #pragma unroll
            for (int nf = 0; nf < 8; nf++) {
                const float p0 = __expf(sc[nf][half * 2]     - mnew);
                const float p1 = __expf(sc[nf][half * 2 + 1] - mnew);
                sc[nf][half * 2] = p0; sc[nf][half * 2 + 1] = p1;
                ps += p0 + p1;
            }
            ps += __shfl_xor_sync(0xffffffffu, ps, 1);
            ps += __shfl_xor_sync(0xffffffffu, ps, 2);
            lrow[half] = lrow[half] * alpha + ps;
            mrow[half] = mnew;
            #pragma unroll
            for (int i = 0; i < 16; i++) {
                oc[i][half * 2]     *= alpha;
                oc[i][half * 2 + 1] *= alpha;
            }
        }

        // ---- publish P as fp16 --------------------------------------------
        #pragma unroll
        for (int nf = 0; nf < 8; nf++)
            #pragma unroll
            for (int half = 0; half < 2; half++) {
                const int r = wid * 16 + g + half * 8;
                const int cc = nf * 8 + 2 * tig;
                *(__half2*)&Ph[r * SP + cc] =
                    __floats2half2_rn(sc[nf][half * 2], sc[nf][half * 2 + 1]);
            }
        __syncwarp();

        // ---- O += P V (1-pass fp16) ---------------------------------------
        #pragma unroll
        for (int ks = 0; ks < 4; ks++) {
            const uint32_t kb = ks * 32;
            uint32_t ph0, ph1, ph2, ph3;
            ldsm4(ph0, ph1, ph2, ph3, uPh + aP + kb);
            #pragma unroll
            for (int j = 0; j < 8; j++) {
                const uint32_t vo = (uint32_t)((ks * 16 + vkrow) * (SQK * 2) + (j * 16 + vdcol) * 2);
                uint32_t vf0, vf1, vf2, vf3;
                ldsm4t(vf0, vf1, vf2, vf3, uVf + vo);
                mma16816h(oc[2 * j],     ph0, ph1, ph2, ph3, vf0, vf1);
                mma16816h(oc[2 * j + 1], ph0, ph1, ph2, ph3, vf2, vf3);
            }
        }
    }

    // ---- epilogue: normalize and emit fp16 O -------------------------------
    const float inv0 = 1.0f / lrow[0], inv1 = 1.0f / lrow[1];
    const int row0 = b * SEQ + qi * FBQ + wid * 16 + g;
    const int cb   = h * DHEAD + 2 * tig;
    #pragma unroll
    for (int nfo = 0; nfo < 16; nfo++) {
        const int col = cb + nfo * 8;
        *(__half2*)(g_aoF + (size_t)row0 * CMODEL + col) =
            __floats2half2_rn(oc[nfo][0] * inv0, oc[nfo][1] * inv0);
        *(__half2*)(g_aoF + (size_t)(row0 + 8) * CMODEL + col) =
            __floats2half2_rn(oc[nfo][2] * inv1, oc[nfo][3] * inv1);
    }
}

// ===========================================================================
// Launch
// ===========================================================================
extern "C" void kernel_launch(void* const* d_in, const int* in_sizes, int n_in,
                              void* d_out, int out_size)
{
    const float* x    = (const float*)d_in[0];
    const float* wq   = (const float*)d_in[1];
    const float* wk   = (const float*)d_in[2];
    const float* wv   = (const float*)d_in[3];
    const float* wo   = (const float*)d_in[4];
    const float* cosp = (const float*)d_in[5];
    const float* sinp = (const float*)d_in[6];
    const int*   isc  = (const int*)d_in[7];

    __half *xh, *xl, *wqkF, *wvtF, *wotH, *aoF;
    cudaGetSymbolAddress((void**)&xh,   g_xh);
    cudaGetSymbolAddress((void**)&xl,   g_xl);
    cudaGetSymbolAddress((void**)&wqkF, g_wqkF);
    cudaGetSymbolAddress((void**)&wvtF, g_wvtF);
    cudaGetSymbolAddress((void**)&wotH, g_wotH);
    cudaGetSymbolAddress((void**)&aoF,  g_aoF);

    // 1) split x into fp16 hi/lo (hi also feeds V projection)
    fsplit_kernel<<<(MROWS * CMODEL / 4 + 255) / 256, 256>>>(x, xh, xl, MROWS * CMODEL / 4);

    // 2) transpose weights to fp16: wq|wk concat, wv, wo
    dim3 tb(32, 8);
    thalf_kernel<<<dim3(CMODEL / 32, CMODEL / 32), tb>>>(wq, CMODEL, wqkF, 0);
    thalf_kernel<<<dim3(1024 / 32,   CMODEL / 32), tb>>>(wk, 1024,   wqkF, CMODEL);
    thalf_kernel<<<dim3(1024 / 32,   CMODEL / 32), tb>>>(wv, 1024,   wvtF, 0);
    thalf_kernel<<<dim3(CMODEL / 32, CMODEL / 32), tb>>>(wo, CMODEL, wotH, 0);

    // 3) Q+K projection (2-pass fp16 HMMA) + RoPE -> q hi/lo, k single fp16
    cudaFuncSetAttribute(gemm_qk, cudaFuncAttributeMaxDynamicSharedMemorySize, QK_SMEM);
    gemm_qk<<<dim3(NQK / 128, MROWS / 128), 256, QK_SMEM>>>(
        xh, xl, wqkF, cosp, sinp);

    // 4) V projection (1-pass fp16 HMMA)
    cudaFuncSetAttribute(gemm_h<0>, cudaFuncAttributeMaxDynamicSharedMemorySize, OP_SMEM);
    gemm_h<0><<<dim3(1024 / 128, MROWS / 128), 256, OP_SMEM>>>(xh, wvtF, nullptr);

    // 5) HMMA flash attention (fp16 QK 2-pass, fp16 PV 1-pass) -> fp16 O
    cudaFuncSetAttribute(flash_mma_kernel, cudaFuncAttributeMaxDynamicSharedMemorySize,
                         FLASH_SMEM);
    dim3 g2(SEQ / FBQ, NHEAD, BATCH);
    flash_mma_kernel<<<g2, 256, FLASH_SMEM>>>(isc);

    // 6) output projection (1-pass fp16 HMMA)
    cudaFuncSetAttribute(gemm_h<1>, cudaFuncAttributeMaxDynamicSharedMemorySize, OP_SMEM);
    gemm_h<1><<<dim3(CMODEL / 128, MROWS / 128), 256, OP_SMEM>>>(
        aoF, wotH, (float*)d_out);
}

// round 13
// speedup vs baseline: 5.2758x; 1.0264x over previous
#include <cuda_runtime.h>
#include <cuda_bf16.h>
#include <cuda_fp16.h>
#include <cstdint>

#define BATCH   2
#define SEQ     2048
#define CMODEL  4096
#define NHEAD   32
#define DHEAD   128
#define NKV     8
#define GQA     4
#define MROWS   (BATCH * SEQ)
#define NQK     (CMODEL + NKV * DHEAD)        // 5120 (q+k projection cols)

// ------------------------- device scratch (no allocs) ----------------------
__device__ __half g_qh[BATCH * NHEAD * SEQ * DHEAD];   // q fp16 hi
__device__ __half g_ql[BATCH * NHEAD * SEQ * DHEAD];   // q fp16 lo
__device__ __half g_kF[BATCH * NKV * SEQ * DHEAD];     // k fp16 (single)
__device__ __half g_vF[BATCH * NKV * SEQ * DHEAD];

__device__ __half g_xh [MROWS * CMODEL];               // fp16 hi of x (also V input)
__device__ __half g_xl [MROWS * CMODEL];               // fp16 lo of x
__device__ __half g_wqkF[NQK * CMODEL];                // wq|wk transposed fp16
__device__ __half g_wvtF[(NKV * DHEAD) * CMODEL];      // wv transposed fp16
__device__ __half g_wotH[CMODEL * CMODEL];             // wo transposed fp16
__device__ __half g_aoF [MROWS * CMODEL];              // attention out fp16

// ------------------------- PTX helpers --------------------------------------
__device__ __forceinline__ uint32_t s2u(const void* p) {
    uint32_t a;
    asm("{ .reg .u64 t; cvta.to.shared.u64 t, %1; cvt.u32.u64 %0, t; }" : "=r"(a) : "l"(p));
    return a;
}
__device__ __forceinline__ void cpa16(uint32_t dst, const void* src) {
    asm volatile("cp.async.ca.shared.global [%0], [%1], 16;" :: "r"(dst), "l"(src));
}
__device__ __forceinline__ void cpa_commit() {
    asm volatile("cp.async.commit_group;" ::: "memory");
}
__device__ __forceinline__ void cpa_wait1() {
    asm volatile("cp.async.wait_group 1;" ::: "memory");
}
__device__ __forceinline__ void cpa_wait0() {
    asm volatile("cp.async.wait_group 0;" ::: "memory");
}
__device__ __forceinline__ void ldsm4(uint32_t& r0, uint32_t& r1, uint32_t& r2, uint32_t& r3,
                                      uint32_t addr) {
    asm volatile("ldmatrix.sync.aligned.m8n8.x4.shared.b16 {%0,%1,%2,%3}, [%4];"
                 : "=r"(r0), "=r"(r1), "=r"(r2), "=r"(r3) : "r"(addr));
}
__device__ __forceinline__ void ldsm4t(uint32_t& r0, uint32_t& r1, uint32_t& r2, uint32_t& r3,
                                       uint32_t addr) {
    asm volatile("ldmatrix.sync.aligned.m8n8.x4.trans.shared.b16 {%0,%1,%2,%3}, [%4];"
                 : "=r"(r0), "=r"(r1), "=r"(r2), "=r"(r3) : "r"(addr));
}
__device__ __forceinline__ void ldsm2(uint32_t& r0, uint32_t& r1, uint32_t addr) {
    asm volatile("ldmatrix.sync.aligned.m8n8.x2.shared.b16 {%0,%1}, [%2];"
                 : "=r"(r0), "=r"(r1) : "r"(addr));
}
__device__ __forceinline__ void mma16816h(float* c, uint32_t a0, uint32_t a1, uint32_t a2,
                                          uint32_t a3, uint32_t b0, uint32_t b1) {
    asm volatile("mma.sync.aligned.m16n8k16.row.col.f32.f16.f16.f32 "
                 "{%0,%1,%2,%3}, {%4,%5,%6,%7}, {%8,%9}, {%0,%1,%2,%3};"
                 : "+f"(c[0]), "+f"(c[1]), "+f"(c[2]), "+f"(c[3])
                 : "r"(a0), "r"(a1), "r"(a2), "r"(a3), "r"(b0), "r"(b1));
}
__device__ __forceinline__ uint32_t packh2(float a, float b) {
    const __half2 h = __floats2half2_rn(a, b);
    return *(const uint32_t*)&h;
}
__device__ __forceinline__ void split_pair_h(float a, float b,
                                             __half2& hi, __half2& lo) {
    const __half ha = __float2half(a), hb = __float2half(b);
    hi = __halves2half2(ha, hb);
    lo = __halves2half2(__float2half(a - __half2float(ha)),
                        __float2half(b - __half2float(hb)));
}

// ------------------------- conversion kernels -------------------------------
// fp32 -> fp16 hi/lo
__global__ __launch_bounds__(256)
void fsplit_kernel(const float* __restrict__ s, __half* __restrict__ dh,
                   __half* __restrict__ dl, int n4) {
    int i = blockIdx.x * 256 + threadIdx.x;
    if (i >= n4) return;
    float4 v = ((const float4*)s)[i];
    __half2 h0, l0, h1, l1;
    split_pair_h(v.x, v.y, h0, l0);
    split_pair_h(v.z, v.w, h1, l1);
    ((__half2*)dh)[i * 2]     = h0;
    ((__half2*)dh)[i * 2 + 1] = h1;
    ((__half2*)dl)[i * 2]     = l0;
    ((__half2*)dl)[i * 2 + 1] = l1;
}

// transpose [K=4096][N] fp32 -> [row_off + N][4096] fp16
__global__ __launch_bounds__(256)
void thalf_kernel(const float* __restrict__ src, int N, __half* __restrict__ dst,
                  int row_off) {
    __shared__ float t[32][33];
    const int k0 = blockIdx.y * 32, n0 = blockIdx.x * 32;
    const int tx = threadIdx.x, ty = threadIdx.y;
    #pragma unroll
    for (int i = 0; i < 32; i += 8)
        t[ty + i][tx] = src[(size_t)(k0 + ty + i) * N + n0 + tx];
    __syncthreads();
    #pragma unroll
    for (int i = 0; i < 32; i += 8)
        dst[(size_t)(row_off + n0 + ty + i) * CMODEL + k0 + tx] = __float2half(t[tx][ty + i]);
}

// ------------------------- 2-pass fp16 HMMA GEMM (Q+K projection) -----------
#define BKH 64
#define LDA 72
#define TILE_SM (128 * LDA)                 // 16-bit elems per tile
#define QK_STAGE_SM (3 * TILE_SM)           // xhi, xlo, w
#define QK_SMEM (2 * QK_STAGE_SM * 2)       // 110592 B

__device__ __forceinline__ void load_tile_async_h(const __half* __restrict__ g,
                                                  int row0, int col0, uint32_t sdst, int tid) {
    const char* gp = (const char*)(g + (size_t)row0 * CMODEL + col0);
    #pragma unroll
    for (int i = 0; i < 4; i++) {
        const int idx = i * 256 + tid;
        const int r = idx >> 3, cb = (idx & 7) << 4;
        cpa16(sdst + (uint32_t)(r * (LDA * 2) + cb), gp + (size_t)r * (CMODEL * 2) + cb);
    }
}

__global__ __launch_bounds__(256)
void gemm_qk(const __half* __restrict__ Ah, const __half* __restrict__ Al,
             const __half* __restrict__ B,
             const float* __restrict__ cosp, const float* __restrict__ sinp)
{
    extern __shared__ __half sm[];
    const uint32_t base = s2u(sm);

    const int tid  = threadIdx.x;
    const int wid  = tid >> 5, lane = tid & 31;
    const int wm   = wid >> 2;
    const int wn   = wid & 3;
    const int n0   = blockIdx.x * 128, m0 = blockIdx.y * 128;

    float acc[4][4][4];
    #pragma unroll
    for (int i = 0; i < 4; i++)
        #pragma unroll
        for (int j = 0; j < 4; j++)
            #pragma unroll
            for (int c = 0; c < 4; c++) acc[i][j][c] = 0.f;

    const uint32_t aOff = (uint32_t)((wm * 64 + (lane & 15)) * (LDA * 2) + (lane >> 4) * 16);
    const uint32_t bOff = (uint32_t)((wn * 32 + (lane & 7)) * (LDA * 2) + ((lane & 15) >> 3) * 16);

    {
        load_tile_async_h(Ah, m0, 0, base + 0 * TILE_SM * 2, tid);
        load_tile_async_h(Al, m0, 0, base + 1 * TILE_SM * 2, tid);
        load_tile_async_h(B,  n0, 0, base + 2 * TILE_SM * 2, tid);
        cpa_commit();
    }

    const int NIT = CMODEL / BKH;
    for (int it = 0; it < NIT; it++) {
        if (it + 1 < NIT) {
            const uint32_t sn = base + ((it + 1) & 1) * QK_STAGE_SM * 2;
            const int kc = (it + 1) * BKH;
            load_tile_async_h(Ah, m0, kc, sn + 0 * TILE_SM * 2, tid);
            load_tile_async_h(Al, m0, kc, sn + 1 * TILE_SM * 2, tid);
            load_tile_async_h(B,  n0, kc, sn + 2 * TILE_SM * 2, tid);
        }
        cpa_commit();
        cpa_wait1();
        __syncthreads();

        const uint32_t sc = base + (it & 1) * QK_STAGE_SM * 2;
        const uint32_t uAh = sc, uAl = sc + TILE_SM * 2, uB = sc + 2 * TILE_SM * 2;

        #pragma unroll
        for (int ks = 0; ks < 4; ks++) {
            const uint32_t kb = ks * 32;
            uint32_t ah[4][4], al[4][4], b[4][2];
            #pragma unroll
            for (int mf = 0; mf < 4; mf++) {
                ldsm4(ah[mf][0], ah[mf][1], ah[mf][2], ah[mf][3],
                      uAh + aOff + mf * (16 * LDA * 2) + kb);
                ldsm4(al[mf][0], al[mf][1], al[mf][2], al[mf][3],
                      uAl + aOff + mf * (16 * LDA * 2) + kb);
            }
            #pragma unroll
            for (int nf = 0; nf < 4; nf++)
                ldsm2(b[nf][0], b[nf][1], uB + bOff + nf * (8 * LDA * 2) + kb);
            #pragma unroll
            for (int mf = 0; mf < 4; mf++)
                #pragma unroll
                for (int nf = 0; nf < 4; nf++) {
                    mma16816h(acc[mf][nf], ah[mf][0], ah[mf][1], ah[mf][2], ah[mf][3],
                              b[nf][0], b[nf][1]);
                    mma16816h(acc[mf][nf], al[mf][0], al[mf][1], al[mf][2], al[mf][3],
                              b[nf][0], b[nf][1]);
                }
        }
        __syncthreads();
    }

    const int group = lane >> 2, tig = lane & 3;
    const int isQ = (n0 < CMODEL);
    const int head = isQ ? (n0 >> 7) : ((n0 - CMODEL) >> 7);
    const int nh   = isQ ? NHEAD : NKV;

    #pragma unroll
    for (int mf = 0; mf < 4; mf++) {
        #pragma unroll
        for (int nf = 0; nf < 4; nf++) {
            const int d = wn * 32 + nf * 8 + tig * 2;
            #pragma unroll
            for (int half = 0; half < 2; half++) {
                const int row = m0 + wm * 64 + mf * 16 + group + half * 8;
                const int bb = row >> 11, tt = row & (SEQ - 1);
                float e = acc[mf][nf][half * 2], o = acc[mf][nf][half * 2 + 1];
                const float ct = cosp[tt * DHEAD + d];
                const float st = sinp[tt * DHEAD + d];
                const float ne = e * ct - o * st;
                o = e * st + o * ct;
                e = ne;
                const size_t off = ((size_t)(bb * nh + head) * SEQ + tt) * DHEAD + d;
                if (isQ) {
                    __half2 hi, lo;
                    split_pair_h(e, o, hi, lo);
                    *(__half2*)(g_qh + off) = hi;
                    *(__half2*)(g_ql + off) = lo;
                } else {
                    *(__half2*)(g_kF + off) = __floats2half2_rn(e, o);
                }
            }
        }
    }
}

// ------------------------- 1-pass fp16 HMMA GEMM ----------------------------
// MODE 0: V projection -> g_vF scatter ; MODE 1: out proj -> float out
#define OP_STAGE_SM (2 * TILE_SM)
#define OP_SMEM (2 * OP_STAGE_SM * 2)          // 73728 B

template<int MODE>
__global__ __launch_bounds__(256, 2)
void gemm_h(const __half* __restrict__ A, const __half* __restrict__ B,
            float* __restrict__ outp)
{
    extern __shared__ __half smh[];
    const uint32_t base = s2u(smh);

    const int tid  = threadIdx.x;
    const int wid  = tid >> 5, lane = tid & 31;
    const int wm   = wid >> 2;
    const int wn   = wid & 3;
    const int n0   = blockIdx.x * 128, m0 = blockIdx.y * 128;

    float acc[4][4][4];
    #pragma unroll
    for (int i = 0; i < 4; i++)
        #pragma unroll
        for (int j = 0; j < 4; j++)
            #pragma unroll
            for (int c = 0; c < 4; c++) acc[i][j][c] = 0.f;

    const uint32_t aOff = (uint32_t)((wm * 64 + (lane & 15)) * (LDA * 2) + (lane >> 4) * 16);
    const uint32_t bOff = (uint32_t)((wn * 32 + (lane & 7)) * (LDA * 2) + ((lane & 15) >> 3) * 16);

    {
        load_tile_async_h(A, m0, 0, base, tid);
        load_tile_async_h(B, n0, 0, base + TILE_SM * 2, tid);
        cpa_commit();
    }

    const int NIT = CMODEL / BKH;
    for (int it = 0; it < NIT; it++) {
        if (it + 1 < NIT) {
            const uint32_t sn = base + ((it + 1) & 1) * OP_STAGE_SM * 2;
            const int kc = (it + 1) * BKH;
            load_tile_async_h(A, m0, kc, sn, tid);
            load_tile_async_h(B, n0, kc, sn + TILE_SM * 2, tid);
        }
        cpa_commit();
        cpa_wait1();
        __syncthreads();

        const uint32_t sc = base + (it & 1) * OP_STAGE_SM * 2;
        const uint32_t uA = sc, uB = sc + TILE_SM * 2;

        #pragma unroll
        for (int ks = 0; ks < 4; ks++) {
            const uint32_t kb = ks * 32;
            uint32_t a[4][4], b[4][2];
            #pragma unroll
            for (int mf = 0; mf < 4; mf++)
                ldsm4(a[mf][0], a[mf][1], a[mf][2], a[mf][3],
                      uA + aOff + mf * (16 * LDA * 2) + kb);
            #pragma unroll
            for (int nf = 0; nf < 4; nf++)
                ldsm2(b[nf][0], b[nf][1], uB + bOff + nf * (8 * LDA * 2) + kb);
            #pragma unroll
            for (int mf = 0; mf < 4; mf++)
                #pragma unroll
                for (int nf = 0; nf < 4; nf++)
                    mma16816h(acc[mf][nf], a[mf][0], a[mf][1], a[mf][2], a[mf][3],
                              b[nf][0], b[nf][1]);
        }
        __syncthreads();
    }

    const int group = lane >> 2, tig = lane & 3;
    if (MODE == 0) {
        const int head = n0 >> 7;
        #pragma unroll
        for (int mf = 0; mf < 4; mf++) {
            #pragma unroll
            for (int nf = 0; nf < 4; nf++) {
                const int d = wn * 32 + nf * 8 + tig * 2;
                #pragma unroll
                for (int half = 0; half < 2; half++) {
                    const int row = m0 + wm * 64 + mf * 16 + group + half * 8;
                    const int bb = row >> 11, tt = row & (SEQ - 1);
                    const size_t off = ((size_t)(bb * NKV + head) * SEQ + tt) * DHEAD + d;
                    *(__half2*)(g_vF + off) =
                        __floats2half2_rn(acc[mf][nf][half * 2], acc[mf][nf][half * 2 + 1]);
                }
            }
        }
    } else {
        #pragma unroll
        for (int mf = 0; mf < 4; mf++) {
            #pragma unroll
            for (int nf = 0; nf < 4; nf++) {
                const int d = wn * 32 + nf * 8 + tig * 2;
                #pragma unroll
                for (int half = 0; half < 2; half++) {
                    const int row = m0 + wm * 64 + mf * 16 + group + half * 8;
                    float* dst = outp + (size_t)row * CMODEL + n0 + d;
                    *(float2*)dst = make_float2(acc[mf][nf][half * 2], acc[mf][nf][half * 2 + 1]);
                }
            }
        }
    }
}

// ===========================================================================
// HMMA flash attention: 2-pass fp16 QK, 1-pass fp16 PV.
// P stays in registers (C-fragment of S == A-fragment for PV).
// K/V double-buffered via cp.async; fully-masked diagonal warp-tiles skipped.
// ===========================================================================
#define FBQ 128
#define FBK 64
#define SQK 136
#define KVT (FBK * SQK)                         // halfs per K or V tile
#define FLASH_SMEM ((2 * FBQ * SQK + 4 * KVT) * 2)   // 139264 B

__global__ __launch_bounds__(256, 1)
void flash_mma_kernel(const int* __restrict__ is_causal_p)
{
    extern __shared__ char fsmc[];
    __half* Qh = (__half*)fsmc;
    __half* Ql = Qh + FBQ * SQK;
    __half* KV = Ql + FBQ * SQK;   // [stage][K tile | V tile]

    const int tid  = threadIdx.x;
    const int wid  = tid >> 5, lane = tid & 31;
    const int g    = lane >> 2, tig = lane & 3;
    const int qi   = (gridDim.x - 1) - blockIdx.x;
    const int h    = blockIdx.y, b = blockIdx.z;
    const int kh   = h >> 2;
    const float scale = 0.08838834764831845f;

    const __half* qgh = g_qh + ((size_t)(b * NHEAD + h) * SEQ + qi * FBQ) * DHEAD;
    const __half* qgl = g_ql + ((size_t)(b * NHEAD + h) * SEQ + qi * FBQ) * DHEAD;
    const __half* kgf = g_kF + (size_t)(b * NKV + kh) * SEQ * DHEAD;
    const __half* vgf = g_vF + (size_t)(b * NKV + kh) * SEQ * DHEAD;

    const uint32_t uQh = s2u(Qh), uQl = s2u(Ql), uKV = s2u(KV);

    // Q load (group 0)
    #pragma unroll
    for (int i = 0; i < 8; i++) {
        const int idx = i * 256 + tid;
        const int r = idx >> 4, c = (idx & 15) << 3;
        cpa16(uQh + (uint32_t)(r * SQK + c) * 2, qgh + (size_t)r * DHEAD + c);
        cpa16(uQl + (uint32_t)(r * SQK + c) * 2, qgl + (size_t)r * DHEAD + c);
    }
    cpa_commit();

    const int causal = is_causal_p[0];
    const int nkt = causal ? (2 * qi + 2) : (SEQ / FBK);

    // K/V tile 0 into stage 0 (group 1)
    #pragma unroll
    for (int i = 0; i < 4; i++) {
        const int idx = i * 256 + tid;
        const int r = idx >> 4, c = (idx & 15) << 3;
        const uint32_t so = (uint32_t)(r * SQK + c) * 2;
        cpa16(uKV + so,              kgf + (size_t)r * DHEAD + c);
        cpa16(uKV + KVT * 2 + so,    vgf + (size_t)r * DHEAD + c);
    }
    cpa_commit();

    float oc[16][4];
    #pragma unroll
    for (int i = 0; i < 16; i++)
        #pragma unroll
        for (int c = 0; c < 4; c++) oc[i][c] = 0.f;
    float mrow[2] = {-1e30f, -1e30f}, lrow[2] = {0.f, 0.f};

    const uint32_t aQ = (uint32_t)((wid * 16 + (lane & 15)) * (SQK * 2) + ((lane >> 4) << 4));
    const int brow = (lane & 7) + ((lane >> 4) << 3);
    const uint32_t bcol = ((lane >> 3) & 1) << 4;
    const int vkrow = (lane & 7) + (((lane >> 3) & 1) << 3);
    const int vdcol = (lane >> 4) << 3;
    const int warpRow0 = qi * FBQ + wid * 16;     // first row this warp owns

    for (int kt = 0; kt < nkt; kt++) {
        // prefetch next K/V tile into the other stage
        if (kt + 1 < nkt) {
            const uint32_t sn = uKV + ((kt + 1) & 1) * (2 * KVT * 2);
            #pragma unroll
            for (int i = 0; i < 4; i++) {
                const int idx = i * 256 + tid;
                const int r = idx >> 4, c = (idx & 15) << 3;
                const size_t go = ((size_t)(kt + 1) * FBK + r) * DHEAD + c;
                const uint32_t so = (uint32_t)(r * SQK + c) * 2;
                cpa16(sn + so,           kgf + go);
                cpa16(sn + KVT * 2 + so, vgf + go);
            }
        }
        cpa_commit();
        cpa_wait1();          // current stage (and Q on iter 0) complete
        __syncthreads();

        const uint32_t uKf = uKV + (kt & 1) * (2 * KVT * 2);
        const uint32_t uVf = uKf + KVT * 2;

        // Fully-masked diagonal warp-tile? (smallest col > largest row)
        const bool dead = causal && (kt * FBK > warpRow0 + 15);

        if (!dead) {
            // ---- S = Q K^T (2-pass: qh*k + ql*k) --------------------------
            float sc[8][4];
            #pragma unroll
            for (int i = 0; i < 8; i++)
                #pragma unroll
                for (int c = 0; c < 4; c++) sc[i][c] = 0.f;

            #pragma unroll
            for (int ks = 0; ks < 8; ks++) {
                const uint32_t kb = ks * 32;
                uint32_t ah0, ah1, ah2, ah3, al0, al1, al2, al3;
                ldsm4(ah0, ah1, ah2, ah3, uQh + aQ + kb);
                ldsm4(al0, al1, al2, al3, uQl + aQ + kb);
                #pragma unroll
                for (int j = 0; j < 4; j++) {
                    const uint32_t ro = (uint32_t)((j * 16 + brow) * (SQK * 2)) + bcol + kb;
                    uint32_t bf0, bf1, bf2, bf3;
                    ldsm4(bf0, bf1, bf2, bf3, uKf + ro);
                    mma16816h(sc[2 * j],     ah0, ah1, ah2, ah3, bf0, bf1);
                    mma16816h(sc[2 * j],     al0, al1, al2, al3, bf0, bf1);
                    mma16816h(sc[2 * j + 1], ah0, ah1, ah2, ah3, bf2, bf3);
                    mma16816h(sc[2 * j + 1], al0, al1, al2, al3, bf2, bf3);
                }
            }

            const int rowA = warpRow0 + g;
            const bool mb = causal && (kt >= 2 * qi);
            #pragma unroll
            for (int nf = 0; nf < 8; nf++)
                #pragma unroll
                for (int c = 0; c < 4; c++) {
                    float v = sc[nf][c] * scale;
                    if (mb) {
                        const int col = kt * FBK + nf * 8 + 2 * tig + (c & 1);
                        const int row = rowA + ((c >> 1) << 3);
                        if (col > row) v = -1e30f;
                    }
                    sc[nf][c] = v;
                }

            // ---- online softmax -------------------------------------------
            #pragma unroll
            for (int half = 0; half < 2; half++) {
                float mx = -1e30f;
                #pragma unroll
                for (int nf = 0; nf < 8; nf++)
                    mx = fmaxf(mx, fmaxf(sc[nf][half * 2], sc[nf][half * 2 + 1]));
                mx = fmaxf(mx, __shfl_xor_sync(0xffffffffu, mx, 1));
                mx = fmaxf(mx, __shfl_xor_sync(0xffffffffu, mx, 2));
                const float mnew  = fmaxf(mrow[half], mx);
                const float alpha = __expf(mrow[half] - mnew);
                float ps = 0.f;
                #pragma unroll
                for (int nf = 0; nf < 8; nf++) {
                    const float p0 = __expf(sc[nf][half * 2]     - mnew);
                    const float p1 = __expf(sc[nf][half * 2 + 1] - mnew);
                    sc[nf][half * 2] = p0; sc[nf][half * 2 + 1] = p1;
                    ps += p0 + p1;
                }
                ps += __shfl_xor_sync(0xffffffffu, ps, 1);
                ps += __shfl_xor_sync(0xffffffffu, ps, 2);
                lrow[half] = lrow[half] * alpha + ps;
                mrow[half] = mnew;
                #pragma unroll
                for (int i = 0; i < 16; i++) {
                    oc[i][half * 2]     *= alpha;
                    oc[i][half * 2 + 1] *= alpha;
                }
            }

            // ---- O += P V : P fed directly from registers -----------------
            #pragma unroll
            for (int ks = 0; ks < 4; ks++) {
                const uint32_t p0 = packh2(sc[2 * ks][0],     sc[2 * ks][1]);
                const uint32_t p1 = packh2(sc[2 * ks][2],     sc[2 * ks][3]);
                const uint32_t p2 = packh2(sc[2 * ks + 1][0], sc[2 * ks + 1][1]);
                const uint32_t p3 = packh2(sc[2 * ks + 1][2], sc[2 * ks + 1][3]);
                #pragma unroll
                for (int j = 0; j < 8; j++) {
                    const uint32_t vo = (uint32_t)((ks * 16 + vkrow) * (SQK * 2)
                                                   + (j * 16 + vdcol) * 2);
                    uint32_t vf0, vf1, vf2, vf3;
                    ldsm4t(vf0, vf1, vf2, vf3, uVf + vo);
                    mma16816h(oc[2 * j],     p0, p1, p2, p3, vf0, vf1);
                    mma16816h(oc[2 * j + 1], p0, p1, p2, p3, vf2, vf3);
                }
            }
        }
        __syncthreads();    // all warps done reading this stage before refill
    }

    // ---- epilogue: normalize and emit fp16 O -------------------------------
    const float inv0 = 1.0f / lrow[0], inv1 = 1.0f / lrow[1];
    const int row0 = b * SEQ + qi * FBQ + wid * 16 + g;
    const int cb   = h * DHEAD + 2 * tig;
    #pragma unroll
    for (int nfo = 0; nfo < 16; nfo++) {
        const int col = cb + nfo * 8;
        *(__half2*)(g_aoF + (size_t)row0 * CMODEL + col) =
            __floats2half2_rn(oc[nfo][0] * inv0, oc[nfo][1] * inv0);
        *(__half2*)(g_aoF + (size_t)(row0 + 8) * CMODEL + col) =
            __floats2half2_rn(oc[nfo][2] * inv1, oc[nfo][3] * inv1);
    }
}

// ===========================================================================
// Launch
// ===========================================================================
extern "C" void kernel_launch(void* const* d_in, const int* in_sizes, int n_in,
                              void* d_out, int out_size)
{
    const float* x    = (const float*)d_in[0];
    const float* wq   = (const float*)d_in[1];
    const float* wk   = (const float*)d_in[2];
    const float* wv   = (const float*)d_in[3];
    const float* wo   = (const float*)d_in[4];
    const float* cosp = (const float*)d_in[5];
    const float* sinp = (const float*)d_in[6];
    const int*   isc  = (const int*)d_in[7];

    __half *xh, *xl, *wqkF, *wvtF, *wotH, *aoF;
    cudaGetSymbolAddress((void**)&xh,   g_xh);
    cudaGetSymbolAddress((void**)&xl,   g_xl);
    cudaGetSymbolAddress((void**)&wqkF, g_wqkF);
    cudaGetSymbolAddress((void**)&wvtF, g_wvtF);
    cudaGetSymbolAddress((void**)&wotH, g_wotH);
    cudaGetSymbolAddress((void**)&aoF,  g_aoF);

    // 1) split x into fp16 hi/lo (hi also feeds V projection)
    fsplit_kernel<<<(MROWS * CMODEL / 4 + 255) / 256, 256>>>(x, xh, xl, MROWS * CMODEL / 4);

    // 2) transpose weights to fp16: wq|wk concat, wv, wo
    dim3 tb(32, 8);
    thalf_kernel<<<dim3(CMODEL / 32, CMODEL / 32), tb>>>(wq, CMODEL, wqkF, 0);
    thalf_kernel<<<dim3(1024 / 32,   CMODEL / 32), tb>>>(wk, 1024,   wqkF, CMODEL);
    thalf_kernel<<<dim3(1024 / 32,   CMODEL / 32), tb>>>(wv, 1024,   wvtF, 0);
    thalf_kernel<<<dim3(CMODEL / 32, CMODEL / 32), tb>>>(wo, CMODEL, wotH, 0);

    // 3) Q+K projection (2-pass fp16 HMMA) + RoPE -> q hi/lo, k single fp16
    cudaFuncSetAttribute(gemm_qk, cudaFuncAttributeMaxDynamicSharedMemorySize, QK_SMEM);
    gemm_qk<<<dim3(NQK / 128, MROWS / 128), 256, QK_SMEM>>>(
        xh, xl, wqkF, cosp, sinp);

    // 4) V projection (1-pass fp16 HMMA)
    cudaFuncSetAttribute(gemm_h<0>, cudaFuncAttributeMaxDynamicSharedMemorySize, OP_SMEM);
    gemm_h<0><<<dim3(1024 / 128, MROWS / 128), 256, OP_SMEM>>>(xh, wvtF, nullptr);

    // 5) HMMA flash attention (2-pass QK, register-P 1-pass PV, K/V pipelined)
    cudaFuncSetAttribute(flash_mma_kernel, cudaFuncAttributeMaxDynamicSharedMemorySize,
                         FLASH_SMEM);
    dim3 g2(SEQ / FBQ, NHEAD, BATCH);
    flash_mma_kernel<<<g2, 256, FLASH_SMEM>>>(isc);

    // 6) output projection (1-pass fp16 HMMA)
    cudaFuncSetAttribute(gemm_h<1>, cudaFuncAttributeMaxDynamicSharedMemorySize, OP_SMEM);
    gemm_h<1><<<dim3(CMODEL / 128, MROWS / 128), 256, OP_SMEM>>>(
        aoF, wotH, (float*)d_out);
}